// round 9
// baseline (speedup 1.0000x reference)
#include <cuda_runtime.h>
#include <cuda_bf16.h>
#include <math.h>
#include <stdint.h>

#define Bv   2048
#define Lv   75
#define Ev   300
#define Hv   300
#define G3   900
#define OUTv 5
#define KP   320                 // K padded to 10 x 32
#define VROWS 50048              // vocab rows padded to 391*128
#define NROWS 960                // gate rows padded to 10*96
#define VOCAB 50000
#define NTILE 10                 // n-blocks per step
#define MT2   8                  // m-blocks (256 rows each)

// ---------------- scratch (device globals; zero-initialized) ---------------
__device__ __nv_bfloat16 d_emb_hi[(size_t)VROWS * KP];
__device__ __nv_bfloat16 d_emb_lo[(size_t)VROWS * KP];
__device__ __nv_bfloat16 d_Wih_hi[NROWS * KP];
__device__ __nv_bfloat16 d_Wih_lo[NROWS * KP];
__device__ __nv_bfloat16 d_Whh_hi[NROWS * KP];
__device__ __nv_bfloat16 d_Whh_lo[NROWS * KP];
__device__ float d_bp_ih[G3];
__device__ float d_bp_hh[G3];
__device__ float d_VG[(size_t)VROWS * G3];                   // vocab gates (b_ih + rz(b_hh) folded)
__device__ __nv_bfloat16 d_Hhi[(size_t)(Lv + 1) * Bv * KP];  // slice 0 = zeros
__device__ __nv_bfloat16 d_Hlo[(size_t)(Lv + 1) * Bv * KP];
__device__ unsigned int d_flagf[Lv + 1][MT2][16];            // [slice][m-chain][producer n]
__device__ unsigned int d_done2[MT2];

// ---------------------------- helpers ---------------------------------------
__device__ __forceinline__ uint32_t smem_u32(const void* p) {
    uint32_t a;
    asm("{ .reg .u64 t; cvta.to.shared.u64 t, %1; cvt.u32.u64 %0, t; }" : "=r"(a) : "l"(p));
    return a;
}
__device__ __forceinline__ void ldsm_x4(uint32_t* r, uint32_t addr) {
    asm volatile("ldmatrix.sync.aligned.m8n8.x4.shared.b16 {%0,%1,%2,%3}, [%4];"
                 : "=r"(r[0]), "=r"(r[1]), "=r"(r[2]), "=r"(r[3]) : "r"(addr));
}
__device__ __forceinline__ void ldsm_x2(uint32_t* r, uint32_t addr) {
    asm volatile("ldmatrix.sync.aligned.m8n8.x2.shared.b16 {%0,%1}, [%2];"
                 : "=r"(r[0]), "=r"(r[1]) : "r"(addr));
}
__device__ __forceinline__ void mma_bf16(float* c, const uint32_t* a, const uint32_t* b) {
    asm volatile(
        "mma.sync.aligned.m16n8k16.row.col.f32.bf16.bf16.f32 "
        "{%0,%1,%2,%3}, {%4,%5,%6,%7}, {%8,%9}, {%0,%1,%2,%3};"
        : "+f"(c[0]), "+f"(c[1]), "+f"(c[2]), "+f"(c[3])
        : "r"(a[0]), "r"(a[1]), "r"(a[2]), "r"(a[3]), "r"(b[0]), "r"(b[1]));
}
__device__ __forceinline__ void cp16(uint32_t dst, const void* src) {
    asm volatile("cp.async.cg.shared.global [%0], [%1], 16;" :: "r"(dst), "l"(src));
}
#define CP_COMMIT() asm volatile("cp.async.commit_group;" ::: "memory")
#define CP_WAIT0()  asm volatile("cp.async.wait_group 0;" ::: "memory")
#define CP_WAIT1()  asm volatile("cp.async.wait_group 1;" ::: "memory")

__device__ __forceinline__ unsigned int ld_acq(const unsigned int* p) {
    unsigned int v;
    asm volatile("ld.global.acquire.gpu.u32 %0, [%1];" : "=r"(v) : "l"(p) : "memory");
    return v;
}
__device__ __forceinline__ void red_rel_add1(unsigned int* p) {
    asm volatile("red.release.gpu.global.add.u32 [%0], 1;" :: "l"(p) : "memory");
}

// ---------------------------- conversion kernels ---------------------------
__global__ void conv_emb(const float* __restrict__ emb,
                         __nv_bfloat16* __restrict__ hi, __nv_bfloat16* __restrict__ lo)
{
    long i = (long)blockIdx.x * blockDim.x + threadIdx.x;
    if (i >= (long)VOCAB * Ev) return;
    int row = (int)(i / Ev), col = (int)(i - (long)row * Ev);
    float x = emb[i];
    __nv_bfloat16 h = __float2bfloat16(x);
    hi[(size_t)row * KP + col] = h;
    lo[(size_t)row * KP + col] = __float2bfloat16(x - __bfloat162float(h));
}

__global__ void conv_w(const float* __restrict__ W, const float* __restrict__ b,
                       __nv_bfloat16* __restrict__ hi, __nv_bfloat16* __restrict__ lo,
                       float* __restrict__ bp)
{
    int n = blockIdx.x;            // 0..899, target row = 3j+g
    int j = n / 3, g = n % 3;
    const float* src = W + (size_t)(g * Hv + j) * 300;
    for (int k = threadIdx.x; k < 300; k += blockDim.x) {
        float x = src[k];
        __nv_bfloat16 h = __float2bfloat16(x);
        hi[(size_t)n * KP + k] = h;
        lo[(size_t)n * KP + k] = __float2bfloat16(x - __bfloat162float(h));
    }
    if (threadIdx.x == 0) bp[n] = b[g * Hv + j];
}

// ---------------------------------------------------------------------------
// VG GEMM: VG = emb @ W_ih^T + b_ih + rz(b_hh). Superchunk 4-plane pipeline.
// Block 128x96, 8 warps (2m x 4n), warp tile 64x24. cp.async, 2 stages.
// ---------------------------------------------------------------------------
#define V_A_HI(s) ((s) * 17920 + 0)
#define V_A_LO(s) ((s) * 17920 + 5120)
#define V_B_HI(s) ((s) * 17920 + 10240)
#define V_B_LO(s) ((s) * 17920 + 14080)
#define GH_STRIDE 100
#define SMEM_VG (2 * 17920 * 2)

__global__ void __launch_bounds__(256)
vg_gemm(const __nv_bfloat16* __restrict__ Ahi, const __nv_bfloat16* __restrict__ Alo,
        const __nv_bfloat16* __restrict__ Bhi, const __nv_bfloat16* __restrict__ Blo,
        const float* __restrict__ bias1, const float* __restrict__ bias2,
        float* __restrict__ VGout)
{
    extern __shared__ __align__(16) char smem[];
    float* ghs = (float*)smem;
    const uint32_t sbase = smem_u32(smem);

    int tid = threadIdx.x;
    int lane = tid & 31, wid = tid >> 5;
    int wm = wid >> 2, wn = wid & 3;
    int m0 = blockIdx.y * 128;
    int n0 = blockIdx.x * 96;

    int a_row = lane & 15, a_k = (lane >> 4) << 3;
    int b_row = lane & 7,  b_k = ((lane >> 3) & 1) << 3;

    auto load_chunk = [&](int cc, int s) {
        int kb = cc * 32;
        int r1 = tid >> 2, co = (tid & 3) * 8;
        int r2 = 64 + r1;
        cp16(sbase + (uint32_t)(V_A_HI(s) + r1 * 40 + co) * 2, Ahi + (size_t)(m0 + r1) * KP + kb + co);
        cp16(sbase + (uint32_t)(V_A_HI(s) + r2 * 40 + co) * 2, Ahi + (size_t)(m0 + r2) * KP + kb + co);
        cp16(sbase + (uint32_t)(V_A_LO(s) + r1 * 40 + co) * 2, Alo + (size_t)(m0 + r1) * KP + kb + co);
        cp16(sbase + (uint32_t)(V_A_LO(s) + r2 * 40 + co) * 2, Alo + (size_t)(m0 + r2) * KP + kb + co);
        cp16(sbase + (uint32_t)(V_B_HI(s) + r1 * 40 + co) * 2, Bhi + (size_t)(n0 + r1) * KP + kb + co);
        cp16(sbase + (uint32_t)(V_B_LO(s) + r1 * 40 + co) * 2, Blo + (size_t)(n0 + r1) * KP + kb + co);
        if (tid < 128) {
            int r3 = 64 + r1;
            cp16(sbase + (uint32_t)(V_B_HI(s) + r3 * 40 + co) * 2, Bhi + (size_t)(n0 + r3) * KP + kb + co);
            cp16(sbase + (uint32_t)(V_B_LO(s) + r3 * 40 + co) * 2, Blo + (size_t)(n0 + r3) * KP + kb + co);
        }
        CP_COMMIT();
    };

    float acc[4][3][4];
#pragma unroll
    for (int mi = 0; mi < 4; mi++)
#pragma unroll
        for (int ni = 0; ni < 3; ni++)
#pragma unroll
            for (int q = 0; q < 4; q++) acc[mi][ni][q] = 0.f;

    load_chunk(0, 0);
    load_chunk(1, 1);

    for (int c = 0; c < 10; c++) {
        if (c < 9) { CP_WAIT1(); } else { CP_WAIT0(); }
        __syncthreads();
        int s = c & 1;
        uint32_t ah = sbase + (uint32_t)V_A_HI(s) * 2;
        uint32_t al = sbase + (uint32_t)V_A_LO(s) * 2;
        uint32_t bh = sbase + (uint32_t)V_B_HI(s) * 2;
        uint32_t bl = sbase + (uint32_t)V_B_LO(s) * 2;
#pragma unroll
        for (int kk = 0; kk < 2; kk++) {
            uint32_t fah[4][4], fal[4][4], fbh[3][2], fbl[3][2];
#pragma unroll
            for (int mi = 0; mi < 4; mi++) {
                uint32_t ro = (uint32_t)((wm * 64 + mi * 16 + a_row) * 40 + kk * 16 + a_k) * 2;
                ldsm_x4(fah[mi], ah + ro);
                ldsm_x4(fal[mi], al + ro);
            }
#pragma unroll
            for (int ni = 0; ni < 3; ni++) {
                uint32_t ro = (uint32_t)((wn * 24 + ni * 8 + b_row) * 40 + kk * 16 + b_k) * 2;
                ldsm_x2(fbh[ni], bh + ro);
                ldsm_x2(fbl[ni], bl + ro);
            }
#pragma unroll
            for (int mi = 0; mi < 4; mi++)
#pragma unroll
                for (int ni = 0; ni < 3; ni++) {
                    mma_bf16(acc[mi][ni], fah[mi], fbh[ni]);
                    mma_bf16(acc[mi][ni], fal[mi], fbh[ni]);
                    mma_bf16(acc[mi][ni], fah[mi], fbl[ni]);
                }
        }
        __syncthreads();
        if (c + 2 < 10) load_chunk(c + 2, s);
    }

#pragma unroll
    for (int mi = 0; mi < 4; mi++) {
        int mr = wm * 64 + mi * 16 + (lane >> 2);
#pragma unroll
        for (int ni = 0; ni < 3; ni++) {
            int nn = wn * 24 + ni * 8 + (lane & 3) * 2;
            ghs[mr * GH_STRIDE + nn]           = acc[mi][ni][0];
            ghs[mr * GH_STRIDE + nn + 1]       = acc[mi][ni][1];
            ghs[(mr + 8) * GH_STRIDE + nn]     = acc[mi][ni][2];
            ghs[(mr + 8) * GH_STRIDE + nn + 1] = acc[mi][ni][3];
        }
    }
    __syncthreads();

    for (int i = tid; i < 128 * 96; i += 256) {
        int m = i / 96, n = i - m * 96;
        int gn = n0 + n;
        if (gn < G3) {
            float b2 = (gn % 3 != 2) ? bias2[gn] : 0.f;   // fold b_hh for r,z only
            VGout[(size_t)(m0 + m) * G3 + gn] = ghs[m * GH_STRIDE + n] + bias1[gn] + b2;
        }
    }
}

// ---------------------------------------------------------------------------
// GRU recurrence, persistent: 80 blocks (8 m-chains x 10 n), block tile
// M=256 x N=96, 8 warps (4m x 2n), warp tile 64x48. One block per SM,
// all resident. Fine-grained dependency: consumer's k-chunk c (= j range of
// producer bn=c) waits on flag[s][bm][c] right before loading it.
// smem (bytes): stages [0,112640): per stage A_hi(20480)+A_lo(20480)+
//   B_hi(7680)+B_lo(7680); gx [112640,210944); bhn [210944,211072).
// ---------------------------------------------------------------------------
#define ST_SZ 56320
#define ST_A_HI(s) ((s) * ST_SZ + 0)
#define ST_A_LO(s) ((s) * ST_SZ + 20480)
#define ST_B_HI(s) ((s) * ST_SZ + 40960)
#define ST_B_LO(s) ((s) * ST_SZ + 48640)
#define GX2_B 112640
#define BHN2_B 210944
#define SMEM_STEP2 211072

__global__ void __launch_bounds__(256)
gru_persist(const __nv_bfloat16* __restrict__ Hhi_all, const __nv_bfloat16* __restrict__ Hlo_all,
            const __nv_bfloat16* __restrict__ Bhi, const __nv_bfloat16* __restrict__ Blo,
            const int* __restrict__ seq, const float* __restrict__ VGin,
            const float* __restrict__ bph,
            int s_begin, int s_end, int use_flags)
{
    extern __shared__ __align__(16) char smem[];
    float* cs  = (float*)smem;                    // epilogue C (aliases stages)
    float* gxs = (float*)(smem + GX2_B);
    float* bhn = (float*)(smem + BHN2_B);
    const uint32_t sbase = smem_u32(smem);

    int tid = threadIdx.x;
    int lane = tid & 31, wid = tid >> 5;
    int wm = wid >> 1, wn = wid & 1;              // 4m x 2n warps
    int bn = blockIdx.x;                          // 0..9
    int bm = blockIdx.y;                          // 0..7
    int m0 = bm * 256;
    int n0 = bn * 96;
    int j0 = bn * 32;

    if (tid < 32 && (n0 + 3 * tid + 2) < G3) bhn[tid] = bph[n0 + 3 * tid + 2];

    int a_row = lane & 15, a_k = (lane >> 4) << 3;
    int b_row = lane & 7,  b_k = ((lane >> 3) & 1) << 3;
    const size_t slice = (size_t)Bv * KP;

    for (int s = s_begin; s < s_end; s++) {
        const __nv_bfloat16* Hp_hi = Hhi_all + (size_t)s * slice;
        const __nv_bfloat16* Hp_lo = Hlo_all + (size_t)s * slice;
        __nv_bfloat16* Ho_hi = (__nv_bfloat16*)(Hhi_all + (size_t)(s + 1) * slice);
        __nv_bfloat16* Ho_lo = (__nv_bfloat16*)(Hlo_all + (size_t)(s + 1) * slice);
        bool needw = use_flags && (s > 0);

        // ---- gx gather for this step (flag-independent; issue first) ----
#pragma unroll
        for (int it = 0; it < 24; it++) {
            int idx = tid + it * 256;             // 0..6143
            int row = idx / 24, off = (idx % 24) * 4;
            int t = seq[(m0 + row) * Lv + s];
            cp16(sbase + GX2_B + (uint32_t)(row * 96 + off) * 4,
                 VGin + (size_t)t * G3 + n0 + off);
        }
        CP_COMMIT();

        auto wait_flag = [&](int c) {
            if (needw) {
                if (tid == 0) {
                    while (ld_acq(&d_flagf[s][bm][c]) == 0u) __nanosleep(64);
                }
                __syncthreads();
            }
        };

        auto load_chunk = [&](int cc, int st) {
            int kb = cc * 32;
#pragma unroll
            for (int i = 0; i < 4; i++) {
                int idx = tid + i * 256;          // 0..1023
                int row = idx >> 2, co = (idx & 3) * 8;
                cp16(sbase + (uint32_t)(ST_A_HI(st) + (row * 40 + co) * 2),
                     Hp_hi + (size_t)(m0 + row) * KP + kb + co);
                cp16(sbase + (uint32_t)(ST_A_LO(st) + (row * 40 + co) * 2),
                     Hp_lo + (size_t)(m0 + row) * KP + kb + co);
            }
#pragma unroll
            for (int i = 0; i < 2; i++) {
                int idx = tid + i * 256;
                if (idx < 384) {
                    int row = idx >> 2, co = (idx & 3) * 8;
                    cp16(sbase + (uint32_t)(ST_B_HI(st) + (row * 40 + co) * 2),
                         Bhi + (size_t)(n0 + row) * KP + kb + co);
                    cp16(sbase + (uint32_t)(ST_B_LO(st) + (row * 40 + co) * 2),
                         Blo + (size_t)(n0 + row) * KP + kb + co);
                }
            }
            CP_COMMIT();
        };

        float acc[4][6][4];
#pragma unroll
        for (int mi = 0; mi < 4; mi++)
#pragma unroll
            for (int ni = 0; ni < 6; ni++)
#pragma unroll
                for (int q = 0; q < 4; q++) acc[mi][ni][q] = 0.f;

        wait_flag(0);
        load_chunk(0, 0);
        wait_flag(1);
        load_chunk(1, 1);

        for (int c = 0; c < 10; c++) {
            if (c < 9) { CP_WAIT1(); } else { CP_WAIT0(); }
            __syncthreads();
            int st = c & 1;
            uint32_t ah = sbase + (uint32_t)ST_A_HI(st);
            uint32_t al = sbase + (uint32_t)ST_A_LO(st);
            uint32_t bh = sbase + (uint32_t)ST_B_HI(st);
            uint32_t bl = sbase + (uint32_t)ST_B_LO(st);
#pragma unroll
            for (int kk = 0; kk < 2; kk++) {
                uint32_t fah[4][4], fal[4][4], fbh[6][2], fbl[6][2];
#pragma unroll
                for (int mi = 0; mi < 4; mi++) {
                    uint32_t ro = (uint32_t)((wm * 64 + mi * 16 + a_row) * 40 + kk * 16 + a_k) * 2;
                    ldsm_x4(fah[mi], ah + ro);
                    ldsm_x4(fal[mi], al + ro);
                }
#pragma unroll
                for (int ni = 0; ni < 6; ni++) {
                    uint32_t ro = (uint32_t)((wn * 48 + ni * 8 + b_row) * 40 + kk * 16 + b_k) * 2;
                    ldsm_x2(fbh[ni], bh + ro);
                    ldsm_x2(fbl[ni], bl + ro);
                }
#pragma unroll
                for (int mi = 0; mi < 4; mi++)
#pragma unroll
                    for (int ni = 0; ni < 6; ni++) {
                        mma_bf16(acc[mi][ni], fah[mi], fbh[ni]);
                        mma_bf16(acc[mi][ni], fal[mi], fbh[ni]);
                        mma_bf16(acc[mi][ni], fah[mi], fbl[ni]);
                    }
            }
            __syncthreads();
            if (c + 2 < 10) {
                wait_flag(c + 2);
                load_chunk(c + 2, st);
            }
        }

        // ---- dump C to smem (stage region; all compute synced) ----
#pragma unroll
        for (int mi = 0; mi < 4; mi++) {
            int mr = wm * 64 + mi * 16 + (lane >> 2);
#pragma unroll
            for (int ni = 0; ni < 6; ni++) {
                int nn = wn * 48 + ni * 8 + (lane & 3) * 2;
                cs[mr * GH_STRIDE + nn]           = acc[mi][ni][0];
                cs[mr * GH_STRIDE + nn + 1]       = acc[mi][ni][1];
                cs[(mr + 8) * GH_STRIDE + nn]     = acc[mi][ni][2];
                cs[(mr + 8) * GH_STRIDE + nn + 1] = acc[mi][ni][3];
            }
        }
        __syncthreads();

        // ---- gate epilogue (gx in smem; h_prev blend via coalesced LDG) ----
#pragma unroll 4
        for (int it = 0; it < 32; it++) {
            int i = tid + it * 256;               // 0..8191
            int ml = i >> 5, p = i & 31;
            int j = j0 + p;
            if (j < Hv) {
                int m = m0 + ml;
                float gh_r = cs[ml * GH_STRIDE + 3 * p + 0];
                float gh_z = cs[ml * GH_STRIDE + 3 * p + 1];
                float gh_n = cs[ml * GH_STRIDE + 3 * p + 2] + bhn[p];  // b_hh_n inside r*(.)
                float gx_r = gxs[ml * 96 + 3 * p + 0];
                float gx_z = gxs[ml * 96 + 3 * p + 1];
                float gx_n = gxs[ml * 96 + 3 * p + 2];
                float r = 1.f / (1.f + expf(-(gx_r + gh_r)));
                float z = 1.f / (1.f + expf(-(gx_z + gh_z)));
                float ng = tanhf(gx_n + r * gh_n);
                size_t hidx = (size_t)m * KP + j;
                float hp = __bfloat162float(Hp_hi[hidx]) + __bfloat162float(Hp_lo[hidx]);
                float h = (1.f - z) * ng + z * hp;
                __nv_bfloat16 hh = __float2bfloat16(h);
                Ho_hi[hidx] = hh;
                Ho_lo[hidx] = __float2bfloat16(h - __bfloat162float(hh));
            }
        }

        if (use_flags) {
            __threadfence();
            __syncthreads();
            if (tid == 0) red_rel_add1(&d_flagf[s + 1][bm][bn]);
        } else {
            __syncthreads();
        }
    }

    // ---- reset phase (persistent mode): make flags replay-safe ----
    if (use_flags) {
        if (tid == 0) red_rel_add1(&d_done2[bm]);
        if (bn == 0) {
            if (tid == 0) {
                while (ld_acq(&d_done2[bm]) < (unsigned)NTILE) __nanosleep(64);
            }
            __syncthreads();
            for (int i = tid; i < (Lv + 1) * 16; i += 256) {
                int s = i >> 4, c = i & 15;
                d_flagf[s][bm][c] = 0u;
            }
            if (tid == 0) d_done2[bm] = 0u;
            __threadfence();
        }
    }
}

// ---------------------------------------------------------------------------
// Post: collapsed co-attention + softmax + pooling + logits.
// ---------------------------------------------------------------------------
__device__ __forceinline__ float blockReduceSum(float v, volatile float* red)
{
    __syncthreads();
#pragma unroll
    for (int o = 16; o > 0; o >>= 1) v += __shfl_xor_sync(0xffffffffu, v, o);
    int w = threadIdx.x >> 5, ln = threadIdx.x & 31;
    if (ln == 0) red[w] = v;
    __syncthreads();
    if (threadIdx.x < 32) {
        float x = (threadIdx.x < 8) ? red[threadIdx.x] : 0.f;
#pragma unroll
        for (int o = 4; o > 0; o >>= 1) x += __shfl_xor_sync(0xffffffffu, x, o);
        if (threadIdx.x == 0) red[0] = x;
    }
    __syncthreads();
    return red[0];
}
__device__ __forceinline__ float blockReduceMax(float v, volatile float* red)
{
    __syncthreads();
#pragma unroll
    for (int o = 16; o > 0; o >>= 1) v = fmaxf(v, __shfl_xor_sync(0xffffffffu, v, o));
    int w = threadIdx.x >> 5, ln = threadIdx.x & 31;
    if (ln == 0) red[w] = v;
    __syncthreads();
    if (threadIdx.x < 32) {
        float x = (threadIdx.x < 8) ? red[threadIdx.x] : -3.4e38f;
#pragma unroll
        for (int o = 4; o > 0; o >>= 1) x = fmaxf(x, __shfl_xor_sync(0xffffffffu, x, o));
        if (threadIdx.x == 0) red[0] = x;
    }
    __syncthreads();
    return red[0];
}

__global__ void post_kernel(const __nv_bfloat16* __restrict__ Hhi,
                            const __nv_bfloat16* __restrict__ Hlo,
                            const float* __restrict__ wCo_w, const float* __restrict__ wCo_b,
                            const float* __restrict__ Wmy_w, const float* __restrict__ Wmy_b,
                            const float* __restrict__ logits_w, const float* __restrict__ logits_b,
                            float* __restrict__ out)
{
    extern __shared__ float fs[];
    float* h_s    = fs;
    float* wa     = h_s + Lv * Hv;
    float* wb_    = wa + Hv;
    float* wc     = wb_ + Hv;
    float* wmy    = wc + Hv;
    float* aa     = wmy + 80;
    float* bb     = aa + 80;
    float* qq     = bb + 80;
    float* pp     = qq + 80;
    float* smarr  = pp + 80;
    float* attn   = smarr + 80;
    float* u      = attn + 80;
    float* pooled = u + Hv;
    __shared__ float red[32];

    int b = blockIdx.x;
    int tid = threadIdx.x;
    int w = tid >> 5, ln = tid & 31;

    for (int t = tid; t < Lv * Hv; t += 256) {
        int i = t / Hv, d = t - i * Hv;
        size_t idx = (size_t)(i + 1) * Bv * KP + (size_t)b * KP + d;
        h_s[t] = __bfloat162float(Hhi[idx]) + __bfloat162float(Hlo[idx]);
    }
    for (int t = tid; t < Hv; t += 256) {
        wa[t]  = wCo_w[t];
        wb_[t] = wCo_w[Hv + t];
        wc[t]  = wCo_w[2 * Hv + t];
    }
    if (tid < Lv) wmy[tid] = Wmy_w[tid];
    __syncthreads();

    for (int i = w; i < Lv; i += 8) {
        float sa = 0.f, sb2 = 0.f, sq = 0.f;
        for (int d = ln; d < Hv; d += 32) {
            float hv = h_s[i * Hv + d];
            sa += hv * wa[d];
            sb2 += hv * wb_[d];
            sq += hv * hv * wc[d];
        }
#pragma unroll
        for (int o = 16; o > 0; o >>= 1) {
            sa += __shfl_xor_sync(0xffffffffu, sa, o);
            sb2 += __shfl_xor_sync(0xffffffffu, sb2, o);
            sq += __shfl_xor_sync(0xffffffffu, sq, o);
        }
        if (ln == 0) { aa[i] = sa; bb[i] = sb2; qq[i] = sq; }
    }
    __syncthreads();

    for (int d = tid; d < Hv; d += 256) {
        float s = 0.f;
#pragma unroll 5
        for (int i = 0; i < Lv; i++) s += wmy[i] * h_s[i * Hv + d];
        u[d] = s;
    }

    float swv = (tid < Lv) ? wmy[tid] : 0.f;
    float Sw = blockReduceSum(swv, red);
    float tv = (tid < Lv) ? wmy[tid] * bb[tid] : 0.f;
    float T = blockReduceSum(tv, red);
    __syncthreads();

    for (int i = w; i < Lv; i += 8) {
        float sp = 0.f;
        for (int d = ln; d < Hv; d += 32) sp += h_s[i * Hv + d] * wc[d] * u[d];
#pragma unroll
        for (int o = 16; o > 0; o >>= 1) sp += __shfl_xor_sync(0xffffffffu, sp, o);
        if (ln == 0) pp[i] = sp;
    }
    __syncthreads();

    float beta = wCo_b[0];
    if (tid < Lv) {
        smarr[tid] = (aa[tid] + beta) * Sw + T + pp[tid]
                   - wmy[tid] * (aa[tid] + bb[tid] + beta + qq[tid]) + Wmy_b[0];
    }
    __syncthreads();

    float mv = (tid < Lv) ? smarr[tid] : -3.4e38f;
    float mx = blockReduceMax(mv, red);
    float ev = (tid < Lv) ? expf(smarr[tid] - mx) : 0.f;
    if (tid < Lv) attn[tid] = ev;
    float se = blockReduceSum(ev, red);
    if (tid < Lv) attn[tid] = attn[tid] / se;
    __syncthreads();

    for (int d = tid; d < Hv; d += 256) {
        float s = 0.f;
#pragma unroll 5
        for (int i = 0; i < Lv; i++) s += attn[i] * h_s[i * Hv + d];
        pooled[d] = s;
    }
    __syncthreads();

    if (w < OUTv) {
        float s = 0.f;
        for (int d = ln; d < Hv; d += 32) s += pooled[d] * logits_w[w * Hv + d];
#pragma unroll
        for (int o = 16; o > 0; o >>= 1) s += __shfl_xor_sync(0xffffffffu, s, o);
        if (ln == 0) out[(size_t)b * OUTv + w] = s + logits_b[w];
    }
}

// ---------------------------------------------------------------------------
extern "C" void kernel_launch(void* const* d_in, const int* in_sizes, int n_in,
                              void* d_out, int out_size)
{
    const int*   seq      = (const int*)  d_in[0];
    const float* emb      = (const float*)d_in[1];
    const float* W_ih     = (const float*)d_in[2];
    const float* W_hh     = (const float*)d_in[3];
    const float* b_ih     = (const float*)d_in[4];
    const float* b_hh     = (const float*)d_in[5];
    const float* wCo_w    = (const float*)d_in[6];
    const float* wCo_b    = (const float*)d_in[7];
    const float* Wmy_w    = (const float*)d_in[8];
    const float* Wmy_b    = (const float*)d_in[9];
    const float* logits_w = (const float*)d_in[10];
    const float* logits_b = (const float*)d_in[11];
    float* out = (float*)d_out;

    __nv_bfloat16 *ehi, *elo, *wih_hi, *wih_lo, *whh_hi, *whh_lo, *Hhi, *Hlo;
    float *bpih, *bphh, *VG;
    cudaGetSymbolAddress((void**)&ehi,    d_emb_hi);
    cudaGetSymbolAddress((void**)&elo,    d_emb_lo);
    cudaGetSymbolAddress((void**)&wih_hi, d_Wih_hi);
    cudaGetSymbolAddress((void**)&wih_lo, d_Wih_lo);
    cudaGetSymbolAddress((void**)&whh_hi, d_Whh_hi);
    cudaGetSymbolAddress((void**)&whh_lo, d_Whh_lo);
    cudaGetSymbolAddress((void**)&bpih,   d_bp_ih);
    cudaGetSymbolAddress((void**)&bphh,   d_bp_hh);
    cudaGetSymbolAddress((void**)&VG,     d_VG);
    cudaGetSymbolAddress((void**)&Hhi,    d_Hhi);
    cudaGetSymbolAddress((void**)&Hlo,    d_Hlo);

    cudaFuncSetAttribute(vg_gemm, cudaFuncAttributeMaxDynamicSharedMemorySize, SMEM_VG);
    cudaFuncSetAttribute(gru_persist, cudaFuncAttributeMaxDynamicSharedMemorySize, SMEM_STEP2);
    const int POST_SMEM = (Lv * Hv + 3 * Hv + 7 * 80 + 2 * Hv) * (int)sizeof(float);
    cudaFuncSetAttribute(post_kernel, cudaFuncAttributeMaxDynamicSharedMemorySize, POST_SMEM);

    // Persistent only if all 80 blocks provably co-resident.
    int occ = 0, sms = 0;
    cudaOccupancyMaxActiveBlocksPerMultiprocessor(&occ, gru_persist, 256, SMEM_STEP2);
    cudaDeviceGetAttribute(&sms, cudaDevAttrMultiProcessorCount, 0);
    bool persistent = ((long)occ * sms >= NTILE * MT2);

    // 0) conversions
    {
        long n = (long)VOCAB * Ev;
        conv_emb<<<(unsigned)((n + 255) / 256), 256>>>(emb, ehi, elo);
    }
    conv_w<<<G3, 128>>>(W_ih, b_ih, wih_hi, wih_lo, bpih);
    conv_w<<<G3, 128>>>(W_hh, b_hh, whh_hi, whh_lo, bphh);

    // 1) VG = emb @ W_ih^T + b_ih + rz(b_hh) over full vocab
    {
        dim3 grid(10, VROWS / 128);
        vg_gemm<<<grid, 256, SMEM_VG>>>(ehi, elo, wih_hi, wih_lo, bpih, bphh, VG);
    }

    // 2) GRU recurrence: 80 fat blocks, fine-grained dataflow sync
    dim3 grid(NTILE, MT2);
    if (persistent) {
        gru_persist<<<grid, 256, SMEM_STEP2>>>(Hhi, Hlo, whh_hi, whh_lo,
                                               seq, VG, bphh, 0, Lv, 1);
    } else {
        for (int l = 0; l < Lv; l++)
            gru_persist<<<grid, 256, SMEM_STEP2>>>(Hhi, Hlo, whh_hi, whh_lo,
                                                   seq, VG, bphh, l, l + 1, 0);
    }

    // 3) collapsed co-attention + softmax + pooling + logits
    post_kernel<<<Bv, 256, POST_SMEM>>>(Hhi, Hlo, wCo_w, wCo_b, Wmy_w, Wmy_b,
                                        logits_w, logits_b, out);
}

// round 11
// speedup vs baseline: 1.4462x; 1.4462x over previous
#include <cuda_runtime.h>
#include <cuda_bf16.h>
#include <math.h>
#include <stdint.h>

#define Bv   2048
#define Lv   75
#define Ev   300
#define Hv   300
#define G3   900
#define OUTv 5
#define KP   320                 // K padded to 10 x 32
#define VROWS 50048              // vocab rows padded to 391*128
#define NROWS 960                // gate rows padded to 10*96
#define VOCAB 50000
#define NTILE 10                 // n-blocks per step
#define MTILE 32                 // m-blocks per step

// ---------------- scratch (device globals; zero-initialized) ---------------
__device__ __nv_bfloat16 d_emb_hi[(size_t)VROWS * KP];
__device__ __nv_bfloat16 d_emb_lo[(size_t)VROWS * KP];
__device__ __nv_bfloat16 d_Wih_hi[NROWS * KP];
__device__ __nv_bfloat16 d_Wih_lo[NROWS * KP];
__device__ __nv_bfloat16 d_Whh_hi[NROWS * KP];
__device__ __nv_bfloat16 d_Whh_lo[NROWS * KP];
__device__ float d_bp_ih[G3];
__device__ float d_bp_hh[G3];
__device__ float d_VG[(size_t)VROWS * G3];                   // vocab gates (b_ih + rz(b_hh) folded)
__device__ __nv_bfloat16 d_Hhi[(size_t)(Lv + 1) * Bv * KP];  // slice 0 = zeros
__device__ __nv_bfloat16 d_Hlo[(size_t)(Lv + 1) * Bv * KP];
__device__ unsigned int d_flagc[Lv][MTILE][16];              // [step][m-chain][producer bn]
__device__ unsigned int d_done[MTILE];

// ---------------------------- helpers ---------------------------------------
__device__ __forceinline__ uint32_t smem_u32(const void* p) {
    uint32_t a;
    asm("{ .reg .u64 t; cvta.to.shared.u64 t, %1; cvt.u32.u64 %0, t; }" : "=r"(a) : "l"(p));
    return a;
}
__device__ __forceinline__ void ldsm_x4(uint32_t* r, uint32_t addr) {
    asm volatile("ldmatrix.sync.aligned.m8n8.x4.shared.b16 {%0,%1,%2,%3}, [%4];"
                 : "=r"(r[0]), "=r"(r[1]), "=r"(r[2]), "=r"(r[3]) : "r"(addr));
}
__device__ __forceinline__ void ldsm_x2(uint32_t* r, uint32_t addr) {
    asm volatile("ldmatrix.sync.aligned.m8n8.x2.shared.b16 {%0,%1}, [%2];"
                 : "=r"(r[0]), "=r"(r[1]) : "r"(addr));
}
__device__ __forceinline__ void mma_bf16(float* c, const uint32_t* a, const uint32_t* b) {
    asm volatile(
        "mma.sync.aligned.m16n8k16.row.col.f32.bf16.bf16.f32 "
        "{%0,%1,%2,%3}, {%4,%5,%6,%7}, {%8,%9}, {%0,%1,%2,%3};"
        : "+f"(c[0]), "+f"(c[1]), "+f"(c[2]), "+f"(c[3])
        : "r"(a[0]), "r"(a[1]), "r"(a[2]), "r"(a[3]), "r"(b[0]), "r"(b[1]));
}
__device__ __forceinline__ void cp16(uint32_t dst, const void* src) {
    asm volatile("cp.async.cg.shared.global [%0], [%1], 16;" :: "r"(dst), "l"(src));
}
#define CP_COMMIT() asm volatile("cp.async.commit_group;" ::: "memory")
#define CP_WAIT0()  asm volatile("cp.async.wait_group 0;" ::: "memory")
#define CP_WAIT1()  asm volatile("cp.async.wait_group 1;" ::: "memory")

__device__ __forceinline__ unsigned int ld_acq(const unsigned int* p) {
    unsigned int v;
    asm volatile("ld.global.acquire.gpu.u32 %0, [%1];" : "=r"(v) : "l"(p) : "memory");
    return v;
}
__device__ __forceinline__ void red_rel_add1(unsigned int* p) {
    asm volatile("red.release.gpu.global.add.u32 [%0], 1;" :: "l"(p) : "memory");
}

// ---------------------------- conversion kernels ---------------------------
__global__ void conv_emb(const float* __restrict__ emb,
                         __nv_bfloat16* __restrict__ hi, __nv_bfloat16* __restrict__ lo)
{
    long i = (long)blockIdx.x * blockDim.x + threadIdx.x;
    if (i >= (long)VOCAB * Ev) return;
    int row = (int)(i / Ev), col = (int)(i - (long)row * Ev);
    float x = emb[i];
    __nv_bfloat16 h = __float2bfloat16(x);
    hi[(size_t)row * KP + col] = h;
    lo[(size_t)row * KP + col] = __float2bfloat16(x - __bfloat162float(h));
}

__global__ void conv_w(const float* __restrict__ W, const float* __restrict__ b,
                       __nv_bfloat16* __restrict__ hi, __nv_bfloat16* __restrict__ lo,
                       float* __restrict__ bp)
{
    int n = blockIdx.x;            // 0..899, target row = 3j+g
    int j = n / 3, g = n % 3;
    const float* src = W + (size_t)(g * Hv + j) * 300;
    for (int k = threadIdx.x; k < 300; k += blockDim.x) {
        float x = src[k];
        __nv_bfloat16 h = __float2bfloat16(x);
        hi[(size_t)n * KP + k] = h;
        lo[(size_t)n * KP + k] = __float2bfloat16(x - __bfloat162float(h));
    }
    if (threadIdx.x == 0) bp[n] = b[g * Hv + j];
}

// ---------------------------------------------------------------------------
// VG GEMM: VG = emb @ W_ih^T + b_ih + rz(b_hh). Superchunk 4-plane pipeline,
// TWO cp.async stages (proven config). Block 128x96, warp tile 64x24.
// ---------------------------------------------------------------------------
#define V_A_HI(s) ((s) * 17920 + 0)
#define V_A_LO(s) ((s) * 17920 + 5120)
#define V_B_HI(s) ((s) * 17920 + 10240)
#define V_B_LO(s) ((s) * 17920 + 14080)
#define GH_STRIDE 100
#define SMEM_VG (2 * 17920 * 2)

__global__ void __launch_bounds__(256)
vg_gemm(const __nv_bfloat16* __restrict__ Ahi, const __nv_bfloat16* __restrict__ Alo,
        const __nv_bfloat16* __restrict__ Bhi, const __nv_bfloat16* __restrict__ Blo,
        const float* __restrict__ bias1, const float* __restrict__ bias2,
        float* __restrict__ VGout)
{
    extern __shared__ __align__(16) char smem[];
    float* ghs = (float*)smem;
    const uint32_t sbase = smem_u32(smem);

    int tid = threadIdx.x;
    int lane = tid & 31, wid = tid >> 5;
    int wm = wid >> 2, wn = wid & 3;
    int m0 = blockIdx.y * 128;
    int n0 = blockIdx.x * 96;

    int a_row = lane & 15, a_k = (lane >> 4) << 3;
    int b_row = lane & 7,  b_k = ((lane >> 3) & 1) << 3;

    auto load_chunk = [&](int cc, int s) {
        int kb = cc * 32;
        int r1 = tid >> 2, co = (tid & 3) * 8;
        int r2 = 64 + r1;
        cp16(sbase + (uint32_t)(V_A_HI(s) + r1 * 40 + co) * 2, Ahi + (size_t)(m0 + r1) * KP + kb + co);
        cp16(sbase + (uint32_t)(V_A_HI(s) + r2 * 40 + co) * 2, Ahi + (size_t)(m0 + r2) * KP + kb + co);
        cp16(sbase + (uint32_t)(V_A_LO(s) + r1 * 40 + co) * 2, Alo + (size_t)(m0 + r1) * KP + kb + co);
        cp16(sbase + (uint32_t)(V_A_LO(s) + r2 * 40 + co) * 2, Alo + (size_t)(m0 + r2) * KP + kb + co);
        cp16(sbase + (uint32_t)(V_B_HI(s) + r1 * 40 + co) * 2, Bhi + (size_t)(n0 + r1) * KP + kb + co);
        cp16(sbase + (uint32_t)(V_B_LO(s) + r1 * 40 + co) * 2, Blo + (size_t)(n0 + r1) * KP + kb + co);
        if (tid < 128) {
            int r3 = 64 + r1;
            cp16(sbase + (uint32_t)(V_B_HI(s) + r3 * 40 + co) * 2, Bhi + (size_t)(n0 + r3) * KP + kb + co);
            cp16(sbase + (uint32_t)(V_B_LO(s) + r3 * 40 + co) * 2, Blo + (size_t)(n0 + r3) * KP + kb + co);
        }
        CP_COMMIT();
    };

    float acc[4][3][4];
#pragma unroll
    for (int mi = 0; mi < 4; mi++)
#pragma unroll
        for (int ni = 0; ni < 3; ni++)
#pragma unroll
            for (int q = 0; q < 4; q++) acc[mi][ni][q] = 0.f;

    load_chunk(0, 0);
    load_chunk(1, 1);

    for (int c = 0; c < 10; c++) {
        if (c < 9) { CP_WAIT1(); } else { CP_WAIT0(); }
        __syncthreads();
        int s = c & 1;
        uint32_t ah = sbase + (uint32_t)V_A_HI(s) * 2;
        uint32_t al = sbase + (uint32_t)V_A_LO(s) * 2;
        uint32_t bh = sbase + (uint32_t)V_B_HI(s) * 2;
        uint32_t bl = sbase + (uint32_t)V_B_LO(s) * 2;
#pragma unroll
        for (int kk = 0; kk < 2; kk++) {
            uint32_t fah[4][4], fal[4][4], fbh[3][2], fbl[3][2];
#pragma unroll
            for (int mi = 0; mi < 4; mi++) {
                uint32_t ro = (uint32_t)((wm * 64 + mi * 16 + a_row) * 40 + kk * 16 + a_k) * 2;
                ldsm_x4(fah[mi], ah + ro);
                ldsm_x4(fal[mi], al + ro);
            }
#pragma unroll
            for (int ni = 0; ni < 3; ni++) {
                uint32_t ro = (uint32_t)((wn * 24 + ni * 8 + b_row) * 40 + kk * 16 + b_k) * 2;
                ldsm_x2(fbh[ni], bh + ro);
                ldsm_x2(fbl[ni], bl + ro);
            }
#pragma unroll
            for (int mi = 0; mi < 4; mi++)
#pragma unroll
                for (int ni = 0; ni < 3; ni++) {
                    mma_bf16(acc[mi][ni], fah[mi], fbh[ni]);
                    mma_bf16(acc[mi][ni], fal[mi], fbh[ni]);
                    mma_bf16(acc[mi][ni], fah[mi], fbl[ni]);
                }
        }
        __syncthreads();
        if (c + 2 < 10) load_chunk(c + 2, s);
    }

#pragma unroll
    for (int mi = 0; mi < 4; mi++) {
        int mr = wm * 64 + mi * 16 + (lane >> 2);
#pragma unroll
        for (int ni = 0; ni < 3; ni++) {
            int nn = wn * 24 + ni * 8 + (lane & 3) * 2;
            ghs[mr * GH_STRIDE + nn]           = acc[mi][ni][0];
            ghs[mr * GH_STRIDE + nn + 1]       = acc[mi][ni][1];
            ghs[(mr + 8) * GH_STRIDE + nn]     = acc[mi][ni][2];
            ghs[(mr + 8) * GH_STRIDE + nn + 1] = acc[mi][ni][3];
        }
    }
    __syncthreads();

    for (int i = tid; i < 128 * 96; i += 256) {
        int m = i / 96, n = i - m * 96;
        int gn = n0 + n;
        if (gn < G3) {
            float b2 = (gn % 3 != 2) ? bias2[gn] : 0.f;   // fold b_hh for r,z only
            VGout[(size_t)(m0 + m) * G3 + gn] = ghs[m * GH_STRIDE + n] + bias1[gn] + b2;
        }
    }
}

// ---------------------------------------------------------------------------
// GRU steps, persistent: 320 blocks (10n x 32m), tile 64x96, 8 warps,
// warp tile 32x24, TWO cp.async stages (proven R8 layout, 75904 B smem).
// Fine-grained flags: producer (bm, bn) of step s enables consumer chunk
// c=bn of step s+1 — the wait sits right before each chunk load.
// smem: stages [0,51200), gx [51200,75776), bhn [75776,75904).
// ---------------------------------------------------------------------------
#define S_A_HI(s) ((s) * 12800 + 0)
#define S_A_LO(s) ((s) * 12800 + 2560)
#define S_B_HI(s) ((s) * 12800 + 5120)
#define S_B_LO(s) ((s) * 12800 + 8960)
#define GXS_B 51200
#define BHN_B 75776
#define SMEM_STEP 75904

__global__ void __launch_bounds__(256, 3)
gru_persist(const __nv_bfloat16* __restrict__ Hhi_all, const __nv_bfloat16* __restrict__ Hlo_all,
            const __nv_bfloat16* __restrict__ Bhi, const __nv_bfloat16* __restrict__ Blo,
            const int* __restrict__ seq, const float* __restrict__ VGin,
            const float* __restrict__ bph,
            int s_begin, int s_end, int use_flags)
{
    extern __shared__ __align__(16) char smem[];
    float* cs  = (float*)smem;                    // epilogue C, aliases stages
    float* gxs = (float*)(smem + GXS_B);
    float* bhn = (float*)(smem + BHN_B);
    const uint32_t sbase = smem_u32(smem);

    int tid = threadIdx.x;
    int lane = tid & 31, wid = tid >> 5;
    int wm = wid >> 2, wn = wid & 3;
    int bn = blockIdx.x;                          // 0..9
    int bm = blockIdx.y;                          // 0..31
    int m0 = bm * 64;
    int n0 = bn * 96;
    int j0 = bn * 32;

    if (tid < 32 && (n0 + 3 * tid + 2) < G3) bhn[tid] = bph[n0 + 3 * tid + 2];

    int a_row = lane & 15, a_k = (lane >> 4) << 3;
    int b_row = lane & 7,  b_k = ((lane >> 3) & 1) << 3;
    const size_t slice = (size_t)Bv * KP;

    for (int s = s_begin; s < s_end; s++) {
        const __nv_bfloat16* Hp_hi = Hhi_all + (size_t)s * slice;
        const __nv_bfloat16* Hp_lo = Hlo_all + (size_t)s * slice;
        __nv_bfloat16* Ho_hi = (__nv_bfloat16*)(Hhi_all + (size_t)(s + 1) * slice);
        __nv_bfloat16* Ho_lo = (__nv_bfloat16*)(Hlo_all + (size_t)(s + 1) * slice);
        bool needw = use_flags && (s > 0);

        // ---- gx gather for this step (flag-independent; issue first) ----
#pragma unroll
        for (int c = 0; c < 6; c++) {
            int idx = tid + c * 256;           // 0..1535
            int row = idx / 24, off = (idx % 24) * 4;
            int t = seq[(m0 + row) * Lv + s];
            cp16(sbase + GXS_B + (uint32_t)(row * 96 + off) * 4,
                 VGin + (size_t)t * G3 + n0 + off);
        }
        CP_COMMIT();

        auto wait_flag = [&](int c) {
            if (needw) {
                if (tid == 0) {
                    while (ld_acq(&d_flagc[s - 1][bm][c]) == 0u) __nanosleep(64);
                }
                __syncthreads();
            }
        };

        auto load_chunk = [&](int cc, int st) {
            int kb = cc * 32;
            int r1 = tid >> 2, co = (tid & 3) * 8;
            cp16(sbase + (uint32_t)(S_A_HI(st) + r1 * 40 + co) * 2, Hp_hi + (size_t)(m0 + r1) * KP + kb + co);
            cp16(sbase + (uint32_t)(S_A_LO(st) + r1 * 40 + co) * 2, Hp_lo + (size_t)(m0 + r1) * KP + kb + co);
            cp16(sbase + (uint32_t)(S_B_HI(st) + r1 * 40 + co) * 2, Bhi + (size_t)(n0 + r1) * KP + kb + co);
            cp16(sbase + (uint32_t)(S_B_LO(st) + r1 * 40 + co) * 2, Blo + (size_t)(n0 + r1) * KP + kb + co);
            if (tid < 128) {
                int r2 = 64 + r1;
                cp16(sbase + (uint32_t)(S_B_HI(st) + r2 * 40 + co) * 2, Bhi + (size_t)(n0 + r2) * KP + kb + co);
                cp16(sbase + (uint32_t)(S_B_LO(st) + r2 * 40 + co) * 2, Blo + (size_t)(n0 + r2) * KP + kb + co);
            }
            CP_COMMIT();
        };

        float acc[2][3][4];
#pragma unroll
        for (int mi = 0; mi < 2; mi++)
#pragma unroll
            for (int ni = 0; ni < 3; ni++)
#pragma unroll
                for (int q = 0; q < 4; q++) acc[mi][ni][q] = 0.f;

        wait_flag(0);
        load_chunk(0, 0);
        wait_flag(1);
        load_chunk(1, 1);

        for (int c = 0; c < 10; c++) {
            if (c < 9) { CP_WAIT1(); } else { CP_WAIT0(); }
            __syncthreads();
            int st = c & 1;
            uint32_t ah = sbase + (uint32_t)S_A_HI(st) * 2;
            uint32_t al = sbase + (uint32_t)S_A_LO(st) * 2;
            uint32_t bh = sbase + (uint32_t)S_B_HI(st) * 2;
            uint32_t bl = sbase + (uint32_t)S_B_LO(st) * 2;
#pragma unroll
            for (int kk = 0; kk < 2; kk++) {
                uint32_t fah[2][4], fal[2][4], fbh[3][2], fbl[3][2];
#pragma unroll
                for (int mi = 0; mi < 2; mi++) {
                    uint32_t ro = (uint32_t)((wm * 32 + mi * 16 + a_row) * 40 + kk * 16 + a_k) * 2;
                    ldsm_x4(fah[mi], ah + ro);
                    ldsm_x4(fal[mi], al + ro);
                }
#pragma unroll
                for (int ni = 0; ni < 3; ni++) {
                    uint32_t ro = (uint32_t)((wn * 24 + ni * 8 + b_row) * 40 + kk * 16 + b_k) * 2;
                    ldsm_x2(fbh[ni], bh + ro);
                    ldsm_x2(fbl[ni], bl + ro);
                }
#pragma unroll
                for (int mi = 0; mi < 2; mi++)
#pragma unroll
                    for (int ni = 0; ni < 3; ni++) {
                        mma_bf16(acc[mi][ni], fah[mi], fbh[ni]);
                        mma_bf16(acc[mi][ni], fal[mi], fbh[ni]);
                        mma_bf16(acc[mi][ni], fah[mi], fbl[ni]);
                    }
            }
            __syncthreads();
            if (c + 2 < 10) {
                wait_flag(c + 2);
                load_chunk(c + 2, st);
            }
        }

        // ---- dump C to smem (stage region; all compute synced) ----
#pragma unroll
        for (int mi = 0; mi < 2; mi++) {
            int mr = wm * 32 + mi * 16 + (lane >> 2);
#pragma unroll
            for (int ni = 0; ni < 3; ni++) {
                int nn = wn * 24 + ni * 8 + (lane & 3) * 2;
                cs[mr * GH_STRIDE + nn]           = acc[mi][ni][0];
                cs[mr * GH_STRIDE + nn + 1]       = acc[mi][ni][1];
                cs[(mr + 8) * GH_STRIDE + nn]     = acc[mi][ni][2];
                cs[(mr + 8) * GH_STRIDE + nn + 1] = acc[mi][ni][3];
            }
        }
        __syncthreads();

        // ---- gate epilogue ----
        for (int i = tid; i < 64 * 32; i += 256) {
            int ml = i >> 5, p = i & 31;
            int j = j0 + p;
            if (j < Hv) {
                int m = m0 + ml;
                float gh_r = cs[ml * GH_STRIDE + 3 * p + 0];
                float gh_z = cs[ml * GH_STRIDE + 3 * p + 1];
                float gh_n = cs[ml * GH_STRIDE + 3 * p + 2] + bhn[p];  // b_hh_n inside r*(.)
                float gx_r = gxs[ml * 96 + 3 * p + 0];
                float gx_z = gxs[ml * 96 + 3 * p + 1];
                float gx_n = gxs[ml * 96 + 3 * p + 2];
                float r = 1.f / (1.f + expf(-(gx_r + gh_r)));
                float z = 1.f / (1.f + expf(-(gx_z + gh_z)));
                float ng = tanhf(gx_n + r * gh_n);
                size_t hidx = (size_t)m * KP + j;
                float hp = __bfloat162float(Hp_hi[hidx]) + __bfloat162float(Hp_lo[hidx]);
                float h = (1.f - z) * ng + z * hp;
                __nv_bfloat16 hh = __float2bfloat16(h);
                Ho_hi[hidx] = hh;
                Ho_lo[hidx] = __float2bfloat16(h - __bfloat162float(hh));
            }
        }

        if (use_flags) {
            __threadfence();
            __syncthreads();
            if (tid == 0) red_rel_add1(&d_flagc[s][bm][bn]);
        } else {
            __syncthreads();
        }
    }

    // ---- reset phase (persistent mode only): make flags replay-safe ----
    if (use_flags) {
        if (tid == 0) red_rel_add1(&d_done[bm]);
        if (bn == 0) {
            if (tid == 0) {
                while (ld_acq(&d_done[bm]) < (unsigned)NTILE) __nanosleep(64);
            }
            __syncthreads();
            for (int i = tid; i < Lv * 16; i += 256) {
                int s = i >> 4, c = i & 15;
                d_flagc[s][bm][c] = 0u;
            }
            if (tid == 0) d_done[bm] = 0u;
            __threadfence();
        }
    }
}

// ---------------------------------------------------------------------------
// Post: collapsed co-attention + softmax + pooling + logits. Vectorized h load.
// ---------------------------------------------------------------------------
__device__ __forceinline__ float blockReduceSum(float v, volatile float* red)
{
    __syncthreads();
#pragma unroll
    for (int o = 16; o > 0; o >>= 1) v += __shfl_xor_sync(0xffffffffu, v, o);
    int w = threadIdx.x >> 5, ln = threadIdx.x & 31;
    if (ln == 0) red[w] = v;
    __syncthreads();
    if (threadIdx.x < 32) {
        float x = (threadIdx.x < 8) ? red[threadIdx.x] : 0.f;
#pragma unroll
        for (int o = 4; o > 0; o >>= 1) x += __shfl_xor_sync(0xffffffffu, x, o);
        if (threadIdx.x == 0) red[0] = x;
    }
    __syncthreads();
    return red[0];
}
__device__ __forceinline__ float blockReduceMax(float v, volatile float* red)
{
    __syncthreads();
#pragma unroll
    for (int o = 16; o > 0; o >>= 1) v = fmaxf(v, __shfl_xor_sync(0xffffffffu, v, o));
    int w = threadIdx.x >> 5, ln = threadIdx.x & 31;
    if (ln == 0) red[w] = v;
    __syncthreads();
    if (threadIdx.x < 32) {
        float x = (threadIdx.x < 8) ? red[threadIdx.x] : -3.4e38f;
#pragma unroll
        for (int o = 4; o > 0; o >>= 1) x = fmaxf(x, __shfl_xor_sync(0xffffffffu, x, o));
        if (threadIdx.x == 0) red[0] = x;
    }
    __syncthreads();
    return red[0];
}

__global__ void post_kernel(const __nv_bfloat16* __restrict__ Hhi,
                            const __nv_bfloat16* __restrict__ Hlo,
                            const float* __restrict__ wCo_w, const float* __restrict__ wCo_b,
                            const float* __restrict__ Wmy_w, const float* __restrict__ Wmy_b,
                            const float* __restrict__ logits_w, const float* __restrict__ logits_b,
                            float* __restrict__ out)
{
    extern __shared__ float fs[];
    float* h_s    = fs;
    float* wa     = h_s + Lv * Hv;
    float* wb_    = wa + Hv;
    float* wc     = wb_ + Hv;
    float* wmy    = wc + Hv;
    float* aa     = wmy + 80;
    float* bb     = aa + 80;
    float* qq     = bb + 80;
    float* pp     = qq + 80;
    float* smarr  = pp + 80;
    float* attn   = smarr + 80;
    float* u      = attn + 80;
    float* pooled = u + Hv;
    __shared__ float red[32];

    int b = blockIdx.x;
    int tid = threadIdx.x;
    int w = tid >> 5, ln = tid & 31;

    // vectorized load: 4 bf16 (8B) per array per iteration
    for (int t = tid; t < Lv * (Hv / 4); t += 256) {
        int i = t / (Hv / 4), d4 = (t - i * (Hv / 4)) * 4;
        size_t idx = (size_t)(i + 1) * Bv * KP + (size_t)b * KP + d4;
        uint2 vh = *(const uint2*)(Hhi + idx);
        uint2 vl = *(const uint2*)(Hlo + idx);
        const __nv_bfloat162* ph = (const __nv_bfloat162*)&vh;
        const __nv_bfloat162* pl = (const __nv_bfloat162*)&vl;
        float2 h0 = __bfloat1622float2(ph[0]);
        float2 l0 = __bfloat1622float2(pl[0]);
        float2 h1 = __bfloat1622float2(ph[1]);
        float2 l1 = __bfloat1622float2(pl[1]);
        float* dst = h_s + i * Hv + d4;
        dst[0] = h0.x + l0.x;
        dst[1] = h0.y + l0.y;
        dst[2] = h1.x + l1.x;
        dst[3] = h1.y + l1.y;
    }
    for (int t = tid; t < Hv; t += 256) {
        wa[t]  = wCo_w[t];
        wb_[t] = wCo_w[Hv + t];
        wc[t]  = wCo_w[2 * Hv + t];
    }
    if (tid < Lv) wmy[tid] = Wmy_w[tid];
    __syncthreads();

    for (int i = w; i < Lv; i += 8) {
        float sa = 0.f, sb2 = 0.f, sq = 0.f;
        for (int d = ln; d < Hv; d += 32) {
            float hv = h_s[i * Hv + d];
            sa += hv * wa[d];
            sb2 += hv * wb_[d];
            sq += hv * hv * wc[d];
        }
#pragma unroll
        for (int o = 16; o > 0; o >>= 1) {
            sa += __shfl_xor_sync(0xffffffffu, sa, o);
            sb2 += __shfl_xor_sync(0xffffffffu, sb2, o);
            sq += __shfl_xor_sync(0xffffffffu, sq, o);
        }
        if (ln == 0) { aa[i] = sa; bb[i] = sb2; qq[i] = sq; }
    }
    __syncthreads();

    for (int d = tid; d < Hv; d += 256) {
        float s = 0.f;
#pragma unroll 5
        for (int i = 0; i < Lv; i++) s += wmy[i] * h_s[i * Hv + d];
        u[d] = s;
    }

    float swv = (tid < Lv) ? wmy[tid] : 0.f;
    float Sw = blockReduceSum(swv, red);
    float tv = (tid < Lv) ? wmy[tid] * bb[tid] : 0.f;
    float T = blockReduceSum(tv, red);
    __syncthreads();

    for (int i = w; i < Lv; i += 8) {
        float sp = 0.f;
        for (int d = ln; d < Hv; d += 32) sp += h_s[i * Hv + d] * wc[d] * u[d];
#pragma unroll
        for (int o = 16; o > 0; o >>= 1) sp += __shfl_xor_sync(0xffffffffu, sp, o);
        if (ln == 0) pp[i] = sp;
    }
    __syncthreads();

    float beta = wCo_b[0];
    if (tid < Lv) {
        smarr[tid] = (aa[tid] + beta) * Sw + T + pp[tid]
                   - wmy[tid] * (aa[tid] + bb[tid] + beta + qq[tid]) + Wmy_b[0];
    }
    __syncthreads();

    float mv = (tid < Lv) ? smarr[tid] : -3.4e38f;
    float mx = blockReduceMax(mv, red);
    float ev = (tid < Lv) ? expf(smarr[tid] - mx) : 0.f;
    if (tid < Lv) attn[tid] = ev;
    float se = blockReduceSum(ev, red);
    if (tid < Lv) attn[tid] = attn[tid] / se;
    __syncthreads();

    for (int d = tid; d < Hv; d += 256) {
        float s = 0.f;
#pragma unroll 5
        for (int i = 0; i < Lv; i++) s += attn[i] * h_s[i * Hv + d];
        pooled[d] = s;
    }
    __syncthreads();

    if (w < OUTv) {
        float s = 0.f;
        for (int d = ln; d < Hv; d += 32) s += pooled[d] * logits_w[w * Hv + d];
#pragma unroll
        for (int o = 16; o > 0; o >>= 1) s += __shfl_xor_sync(0xffffffffu, s, o);
        if (ln == 0) out[(size_t)b * OUTv + w] = s + logits_b[w];
    }
}

// ---------------------------------------------------------------------------
extern "C" void kernel_launch(void* const* d_in, const int* in_sizes, int n_in,
                              void* d_out, int out_size)
{
    const int*   seq      = (const int*)  d_in[0];
    const float* emb      = (const float*)d_in[1];
    const float* W_ih     = (const float*)d_in[2];
    const float* W_hh     = (const float*)d_in[3];
    const float* b_ih     = (const float*)d_in[4];
    const float* b_hh     = (const float*)d_in[5];
    const float* wCo_w    = (const float*)d_in[6];
    const float* wCo_b    = (const float*)d_in[7];
    const float* Wmy_w    = (const float*)d_in[8];
    const float* Wmy_b    = (const float*)d_in[9];
    const float* logits_w = (const float*)d_in[10];
    const float* logits_b = (const float*)d_in[11];
    float* out = (float*)d_out;

    __nv_bfloat16 *ehi, *elo, *wih_hi, *wih_lo, *whh_hi, *whh_lo, *Hhi, *Hlo;
    float *bpih, *bphh, *VG;
    cudaGetSymbolAddress((void**)&ehi,    d_emb_hi);
    cudaGetSymbolAddress((void**)&elo,    d_emb_lo);
    cudaGetSymbolAddress((void**)&wih_hi, d_Wih_hi);
    cudaGetSymbolAddress((void**)&wih_lo, d_Wih_lo);
    cudaGetSymbolAddress((void**)&whh_hi, d_Whh_hi);
    cudaGetSymbolAddress((void**)&whh_lo, d_Whh_lo);
    cudaGetSymbolAddress((void**)&bpih,   d_bp_ih);
    cudaGetSymbolAddress((void**)&bphh,   d_bp_hh);
    cudaGetSymbolAddress((void**)&VG,     d_VG);
    cudaGetSymbolAddress((void**)&Hhi,    d_Hhi);
    cudaGetSymbolAddress((void**)&Hlo,    d_Hlo);

    cudaFuncSetAttribute(vg_gemm, cudaFuncAttributeMaxDynamicSharedMemorySize, SMEM_VG);
    cudaFuncSetAttribute(gru_persist, cudaFuncAttributeMaxDynamicSharedMemorySize, SMEM_STEP);
    const int POST_SMEM = (Lv * Hv + 3 * Hv + 7 * 80 + 2 * Hv) * (int)sizeof(float);
    cudaFuncSetAttribute(post_kernel, cudaFuncAttributeMaxDynamicSharedMemorySize, POST_SMEM);

    // Persistent only if all 320 blocks provably co-resident.
    int occ = 0, sms = 0;
    cudaOccupancyMaxActiveBlocksPerMultiprocessor(&occ, gru_persist, 256, SMEM_STEP);
    cudaDeviceGetAttribute(&sms, cudaDevAttrMultiProcessorCount, 0);
    bool persistent = ((long)occ * sms >= NTILE * MTILE);

    // 0) conversions
    {
        long n = (long)VOCAB * Ev;
        conv_emb<<<(unsigned)((n + 255) / 256), 256>>>(emb, ehi, elo);
    }
    conv_w<<<G3, 128>>>(W_ih, b_ih, wih_hi, wih_lo, bpih);
    conv_w<<<G3, 128>>>(W_hh, b_hh, whh_hi, whh_lo, bphh);

    // 1) VG = emb @ W_ih^T + b_ih + rz(b_hh) over full vocab
    {
        dim3 grid(10, VROWS / 128);
        vg_gemm<<<grid, 256, SMEM_VG>>>(ehi, elo, wih_hi, wih_lo, bpih, bphh, VG);
    }

    // 2) GRU recurrence
    dim3 grid(NTILE, MTILE);
    if (persistent) {
        gru_persist<<<grid, 256, SMEM_STEP>>>(Hhi, Hlo, whh_hi, whh_lo,
                                              seq, VG, bphh, 0, Lv, 1);
    } else {
        for (int l = 0; l < Lv; l++)
            gru_persist<<<grid, 256, SMEM_STEP>>>(Hhi, Hlo, whh_hi, whh_lo,
                                                  seq, VG, bphh, l, l + 1, 0);
    }

    // 3) collapsed co-attention + softmax + pooling + logits
    post_kernel<<<Bv, 256, POST_SMEM>>>(Hhi, Hlo, wCo_w, wCo_b, Wmy_w, Wmy_b,
                                        logits_w, logits_b, out);
}

// round 12
// speedup vs baseline: 1.4980x; 1.0358x over previous
#include <cuda_runtime.h>
#include <cuda_bf16.h>
#include <math.h>
#include <stdint.h>

#define Bv   2048
#define Lv   75
#define Ev   300
#define Hv   300
#define G3   900
#define OUTv 5
#define KP   320                 // K padded to 10 x 32
#define VROWS 50048              // vocab rows padded to 391*128
#define NROWS 960                // gate rows padded to 10*96
#define VOCAB 50000
#define NTILE 10                 // n-blocks per step
#define MTILE 32                 // m-blocks per step

// ---------------- scratch (device globals; zero-initialized) ---------------
__device__ __nv_bfloat16 d_emb_hi[(size_t)VROWS * KP];
__device__ __nv_bfloat16 d_emb_lo[(size_t)VROWS * KP];
__device__ __nv_bfloat16 d_Wih_hi[NROWS * KP];
__device__ __nv_bfloat16 d_Wih_lo[NROWS * KP];
__device__ __nv_bfloat16 d_Whh_hi[NROWS * KP];
__device__ __nv_bfloat16 d_Whh_lo[NROWS * KP];
__device__ float d_bp_ih[G3];
__device__ float d_bp_hh[G3];
__device__ float d_VG[(size_t)VROWS * G3];                   // vocab gates (b_ih + rz(b_hh) folded)
__device__ __nv_bfloat16 d_Hhi[(size_t)(Lv + 1) * Bv * KP];  // slice 0 = zeros
__device__ __nv_bfloat16 d_Hlo[(size_t)(Lv + 1) * Bv * KP];
__device__ unsigned int d_flag[Lv][MTILE];                   // producers of slice s+1
__device__ unsigned int d_done[MTILE];

// ---------------------------- helpers ---------------------------------------
__device__ __forceinline__ uint32_t smem_u32(const void* p) {
    uint32_t a;
    asm("{ .reg .u64 t; cvta.to.shared.u64 t, %1; cvt.u32.u64 %0, t; }" : "=r"(a) : "l"(p));
    return a;
}
__device__ __forceinline__ void ldsm_x4(uint32_t* r, uint32_t addr) {
    asm volatile("ldmatrix.sync.aligned.m8n8.x4.shared.b16 {%0,%1,%2,%3}, [%4];"
                 : "=r"(r[0]), "=r"(r[1]), "=r"(r[2]), "=r"(r[3]) : "r"(addr));
}
__device__ __forceinline__ void ldsm_x2(uint32_t* r, uint32_t addr) {
    asm volatile("ldmatrix.sync.aligned.m8n8.x2.shared.b16 {%0,%1}, [%2];"
                 : "=r"(r[0]), "=r"(r[1]) : "r"(addr));
}
__device__ __forceinline__ void mma_bf16(float* c, const uint32_t* a, const uint32_t* b) {
    asm volatile(
        "mma.sync.aligned.m16n8k16.row.col.f32.bf16.bf16.f32 "
        "{%0,%1,%2,%3}, {%4,%5,%6,%7}, {%8,%9}, {%0,%1,%2,%3};"
        : "+f"(c[0]), "+f"(c[1]), "+f"(c[2]), "+f"(c[3])
        : "r"(a[0]), "r"(a[1]), "r"(a[2]), "r"(a[3]), "r"(b[0]), "r"(b[1]));
}
__device__ __forceinline__ void cp16(uint32_t dst, const void* src) {
    asm volatile("cp.async.cg.shared.global [%0], [%1], 16;" :: "r"(dst), "l"(src));
}
#define CP_COMMIT() asm volatile("cp.async.commit_group;" ::: "memory")
#define CP_WAIT0()  asm volatile("cp.async.wait_group 0;" ::: "memory")
#define CP_WAIT1()  asm volatile("cp.async.wait_group 1;" ::: "memory")

__device__ __forceinline__ unsigned int ld_acq(const unsigned int* p) {
    unsigned int v;
    asm volatile("ld.global.acquire.gpu.u32 %0, [%1];" : "=r"(v) : "l"(p) : "memory");
    return v;
}
__device__ __forceinline__ void red_rel_add1(unsigned int* p) {
    asm volatile("red.release.gpu.global.add.u32 [%0], 1;" :: "l"(p) : "memory");
}

// ---------------------------- conversion kernels ---------------------------
__global__ void conv_emb(const float* __restrict__ emb,
                         __nv_bfloat16* __restrict__ hi, __nv_bfloat16* __restrict__ lo)
{
    long i = (long)blockIdx.x * blockDim.x + threadIdx.x;
    if (i >= (long)VOCAB * Ev) return;
    int row = (int)(i / Ev), col = (int)(i - (long)row * Ev);
    float x = emb[i];
    __nv_bfloat16 h = __float2bfloat16(x);
    hi[(size_t)row * KP + col] = h;
    lo[(size_t)row * KP + col] = __float2bfloat16(x - __bfloat162float(h));
}

__global__ void conv_w(const float* __restrict__ W, const float* __restrict__ b,
                       __nv_bfloat16* __restrict__ hi, __nv_bfloat16* __restrict__ lo,
                       float* __restrict__ bp)
{
    int n = blockIdx.x;            // 0..899, target row = 3j+g
    int j = n / 3, g = n % 3;
    const float* src = W + (size_t)(g * Hv + j) * 300;
    for (int k = threadIdx.x; k < 300; k += blockDim.x) {
        float x = src[k];
        __nv_bfloat16 h = __float2bfloat16(x);
        hi[(size_t)n * KP + k] = h;
        lo[(size_t)n * KP + k] = __float2bfloat16(x - __bfloat162float(h));
    }
    if (threadIdx.x == 0) bp[n] = b[g * Hv + j];
}

// ---------------------------------------------------------------------------
// VG GEMM: VG = emb @ W_ih^T + b_ih + rz(b_hh). Superchunk 4-plane pipeline,
// TWO cp.async stages. Block 128x96, warp tile 64x24. MMA loops are
// split-term-OUTERMOST so each acc register is reused only every 12 MMAs.
// ---------------------------------------------------------------------------
#define V_A_HI(s) ((s) * 17920 + 0)
#define V_A_LO(s) ((s) * 17920 + 5120)
#define V_B_HI(s) ((s) * 17920 + 10240)
#define V_B_LO(s) ((s) * 17920 + 14080)
#define GH_STRIDE 100
#define SMEM_VG (2 * 17920 * 2)

__global__ void __launch_bounds__(256)
vg_gemm(const __nv_bfloat16* __restrict__ Ahi, const __nv_bfloat16* __restrict__ Alo,
        const __nv_bfloat16* __restrict__ Bhi, const __nv_bfloat16* __restrict__ Blo,
        const float* __restrict__ bias1, const float* __restrict__ bias2,
        float* __restrict__ VGout)
{
    extern __shared__ __align__(16) char smem[];
    float* ghs = (float*)smem;
    const uint32_t sbase = smem_u32(smem);

    int tid = threadIdx.x;
    int lane = tid & 31, wid = tid >> 5;
    int wm = wid >> 2, wn = wid & 3;
    int m0 = blockIdx.y * 128;
    int n0 = blockIdx.x * 96;

    int a_row = lane & 15, a_k = (lane >> 4) << 3;
    int b_row = lane & 7,  b_k = ((lane >> 3) & 1) << 3;

    auto load_chunk = [&](int cc, int s) {
        int kb = cc * 32;
        int r1 = tid >> 2, co = (tid & 3) * 8;
        int r2 = 64 + r1;
        cp16(sbase + (uint32_t)(V_A_HI(s) + r1 * 40 + co) * 2, Ahi + (size_t)(m0 + r1) * KP + kb + co);
        cp16(sbase + (uint32_t)(V_A_HI(s) + r2 * 40 + co) * 2, Ahi + (size_t)(m0 + r2) * KP + kb + co);
        cp16(sbase + (uint32_t)(V_A_LO(s) + r1 * 40 + co) * 2, Alo + (size_t)(m0 + r1) * KP + kb + co);
        cp16(sbase + (uint32_t)(V_A_LO(s) + r2 * 40 + co) * 2, Alo + (size_t)(m0 + r2) * KP + kb + co);
        cp16(sbase + (uint32_t)(V_B_HI(s) + r1 * 40 + co) * 2, Bhi + (size_t)(n0 + r1) * KP + kb + co);
        cp16(sbase + (uint32_t)(V_B_LO(s) + r1 * 40 + co) * 2, Blo + (size_t)(n0 + r1) * KP + kb + co);
        if (tid < 128) {
            int r3 = 64 + r1;
            cp16(sbase + (uint32_t)(V_B_HI(s) + r3 * 40 + co) * 2, Bhi + (size_t)(n0 + r3) * KP + kb + co);
            cp16(sbase + (uint32_t)(V_B_LO(s) + r3 * 40 + co) * 2, Blo + (size_t)(n0 + r3) * KP + kb + co);
        }
        CP_COMMIT();
    };

    float acc[4][3][4];
#pragma unroll
    for (int mi = 0; mi < 4; mi++)
#pragma unroll
        for (int ni = 0; ni < 3; ni++)
#pragma unroll
            for (int q = 0; q < 4; q++) acc[mi][ni][q] = 0.f;

    load_chunk(0, 0);
    load_chunk(1, 1);

    for (int c = 0; c < 10; c++) {
        if (c < 9) { CP_WAIT1(); } else { CP_WAIT0(); }
        __syncthreads();
        int s = c & 1;
        uint32_t ah = sbase + (uint32_t)V_A_HI(s) * 2;
        uint32_t al = sbase + (uint32_t)V_A_LO(s) * 2;
        uint32_t bh = sbase + (uint32_t)V_B_HI(s) * 2;
        uint32_t bl = sbase + (uint32_t)V_B_LO(s) * 2;
#pragma unroll
        for (int kk = 0; kk < 2; kk++) {
            uint32_t fah[4][4], fal[4][4], fbh[3][2], fbl[3][2];
#pragma unroll
            for (int mi = 0; mi < 4; mi++) {
                uint32_t ro = (uint32_t)((wm * 64 + mi * 16 + a_row) * 40 + kk * 16 + a_k) * 2;
                ldsm_x4(fah[mi], ah + ro);
                ldsm_x4(fal[mi], al + ro);
            }
#pragma unroll
            for (int ni = 0; ni < 3; ni++) {
                uint32_t ro = (uint32_t)((wn * 24 + ni * 8 + b_row) * 40 + kk * 16 + b_k) * 2;
                ldsm_x2(fbh[ni], bh + ro);
                ldsm_x2(fbl[ni], bl + ro);
            }
            // split-term outermost: acc reuse distance = 12 MMAs
#pragma unroll
            for (int mi = 0; mi < 4; mi++)
#pragma unroll
                for (int ni = 0; ni < 3; ni++)
                    mma_bf16(acc[mi][ni], fah[mi], fbh[ni]);
#pragma unroll
            for (int mi = 0; mi < 4; mi++)
#pragma unroll
                for (int ni = 0; ni < 3; ni++)
                    mma_bf16(acc[mi][ni], fal[mi], fbh[ni]);
#pragma unroll
            for (int mi = 0; mi < 4; mi++)
#pragma unroll
                for (int ni = 0; ni < 3; ni++)
                    mma_bf16(acc[mi][ni], fah[mi], fbl[ni]);
        }
        __syncthreads();
        if (c + 2 < 10) load_chunk(c + 2, s);
    }

#pragma unroll
    for (int mi = 0; mi < 4; mi++) {
        int mr = wm * 64 + mi * 16 + (lane >> 2);
#pragma unroll
        for (int ni = 0; ni < 3; ni++) {
            int nn = wn * 24 + ni * 8 + (lane & 3) * 2;
            ghs[mr * GH_STRIDE + nn]           = acc[mi][ni][0];
            ghs[mr * GH_STRIDE + nn + 1]       = acc[mi][ni][1];
            ghs[(mr + 8) * GH_STRIDE + nn]     = acc[mi][ni][2];
            ghs[(mr + 8) * GH_STRIDE + nn + 1] = acc[mi][ni][3];
        }
    }
    __syncthreads();

    for (int i = tid; i < 128 * 96; i += 256) {
        int m = i / 96, n = i - m * 96;
        int gn = n0 + n;
        if (gn < G3) {
            float b2 = (gn % 3 != 2) ? bias2[gn] : 0.f;   // fold b_hh for r,z only
            VGout[(size_t)(m0 + m) * G3 + gn] = ghs[m * GH_STRIDE + n] + bias1[gn] + b2;
        }
    }
}

// ---------------------------------------------------------------------------
// GRU steps, persistent: 320 blocks (10n x 32m), tile 64x96, 8 warps,
// warp tile 32x24, TWO cp.async stages. Coarse per-m flags (proven R8).
// MMA loops split-term-outermost (acc reuse distance 6).
// smem: stages [0,51200), gx [51200,75776), bhn [75776,75904).
// ---------------------------------------------------------------------------
#define S_A_HI(s) ((s) * 12800 + 0)
#define S_A_LO(s) ((s) * 12800 + 2560)
#define S_B_HI(s) ((s) * 12800 + 5120)
#define S_B_LO(s) ((s) * 12800 + 8960)
#define GXS_B 51200
#define BHN_B 75776
#define SMEM_STEP 75904

__global__ void __launch_bounds__(256, 3)
gru_persist(const __nv_bfloat16* __restrict__ Hhi_all, const __nv_bfloat16* __restrict__ Hlo_all,
            const __nv_bfloat16* __restrict__ Bhi, const __nv_bfloat16* __restrict__ Blo,
            const int* __restrict__ seq, const float* __restrict__ VGin,
            const float* __restrict__ bph,
            int s_begin, int s_end, int use_flags)
{
    extern __shared__ __align__(16) char smem[];
    float* cs  = (float*)smem;                    // epilogue C, aliases stages
    float* gxs = (float*)(smem + GXS_B);
    float* bhn = (float*)(smem + BHN_B);
    const uint32_t sbase = smem_u32(smem);

    int tid = threadIdx.x;
    int lane = tid & 31, wid = tid >> 5;
    int wm = wid >> 2, wn = wid & 3;
    int bn = blockIdx.x;                          // 0..9
    int bm = blockIdx.y;                          // 0..31
    int m0 = bm * 64;
    int n0 = bn * 96;
    int j0 = bn * 32;

    if (tid < 32 && (n0 + 3 * tid + 2) < G3) bhn[tid] = bph[n0 + 3 * tid + 2];

    int a_row = lane & 15, a_k = (lane >> 4) << 3;
    int b_row = lane & 7,  b_k = ((lane >> 3) & 1) << 3;
    const size_t slice = (size_t)Bv * KP;

    for (int s = s_begin; s < s_end; s++) {
        const __nv_bfloat16* Hp_hi = Hhi_all + (size_t)s * slice;
        const __nv_bfloat16* Hp_lo = Hlo_all + (size_t)s * slice;
        __nv_bfloat16* Ho_hi = (__nv_bfloat16*)(Hhi_all + (size_t)(s + 1) * slice);
        __nv_bfloat16* Ho_lo = (__nv_bfloat16*)(Hlo_all + (size_t)(s + 1) * slice);

        // ---- gx gather for this step (flag-independent; issue first) ----
#pragma unroll
        for (int c = 0; c < 6; c++) {
            int idx = tid + c * 256;           // 0..1535
            int row = idx / 24, off = (idx % 24) * 4;
            int t = seq[(m0 + row) * Lv + s];
            cp16(sbase + GXS_B + (uint32_t)(row * 96 + off) * 4,
                 VGin + (size_t)t * G3 + n0 + off);
        }
        CP_COMMIT();

        // ---- wait for the 10 producers of slice s (rows m-range) ----
        if (use_flags && s > 0) {
            if (tid == 0) {
                while (ld_acq(&d_flag[s - 1][bm]) < (unsigned)NTILE) __nanosleep(64);
            }
        }
        __syncthreads();

        auto load_chunk = [&](int cc, int st) {
            int kb = cc * 32;
            int r1 = tid >> 2, co = (tid & 3) * 8;
            cp16(sbase + (uint32_t)(S_A_HI(st) + r1 * 40 + co) * 2, Hp_hi + (size_t)(m0 + r1) * KP + kb + co);
            cp16(sbase + (uint32_t)(S_A_LO(st) + r1 * 40 + co) * 2, Hp_lo + (size_t)(m0 + r1) * KP + kb + co);
            cp16(sbase + (uint32_t)(S_B_HI(st) + r1 * 40 + co) * 2, Bhi + (size_t)(n0 + r1) * KP + kb + co);
            cp16(sbase + (uint32_t)(S_B_LO(st) + r1 * 40 + co) * 2, Blo + (size_t)(n0 + r1) * KP + kb + co);
            if (tid < 128) {
                int r2 = 64 + r1;
                cp16(sbase + (uint32_t)(S_B_HI(st) + r2 * 40 + co) * 2, Bhi + (size_t)(n0 + r2) * KP + kb + co);
                cp16(sbase + (uint32_t)(S_B_LO(st) + r2 * 40 + co) * 2, Blo + (size_t)(n0 + r2) * KP + kb + co);
            }
            CP_COMMIT();
        };

        float acc[2][3][4];
#pragma unroll
        for (int mi = 0; mi < 2; mi++)
#pragma unroll
            for (int ni = 0; ni < 3; ni++)
#pragma unroll
                for (int q = 0; q < 4; q++) acc[mi][ni][q] = 0.f;

        load_chunk(0, 0);
        load_chunk(1, 1);

        for (int c = 0; c < 10; c++) {
            if (c < 9) { CP_WAIT1(); } else { CP_WAIT0(); }
            __syncthreads();
            int st = c & 1;
            uint32_t ah = sbase + (uint32_t)S_A_HI(st) * 2;
            uint32_t al = sbase + (uint32_t)S_A_LO(st) * 2;
            uint32_t bh = sbase + (uint32_t)S_B_HI(st) * 2;
            uint32_t bl = sbase + (uint32_t)S_B_LO(st) * 2;
#pragma unroll
            for (int kk = 0; kk < 2; kk++) {
                uint32_t fah[2][4], fal[2][4], fbh[3][2], fbl[3][2];
#pragma unroll
                for (int mi = 0; mi < 2; mi++) {
                    uint32_t ro = (uint32_t)((wm * 32 + mi * 16 + a_row) * 40 + kk * 16 + a_k) * 2;
                    ldsm_x4(fah[mi], ah + ro);
                    ldsm_x4(fal[mi], al + ro);
                }
#pragma unroll
                for (int ni = 0; ni < 3; ni++) {
                    uint32_t ro = (uint32_t)((wn * 24 + ni * 8 + b_row) * 40 + kk * 16 + b_k) * 2;
                    ldsm_x2(fbh[ni], bh + ro);
                    ldsm_x2(fbl[ni], bl + ro);
                }
                // split-term outermost: acc reuse distance = 6 MMAs
#pragma unroll
                for (int mi = 0; mi < 2; mi++)
#pragma unroll
                    for (int ni = 0; ni < 3; ni++)
                        mma_bf16(acc[mi][ni], fah[mi], fbh[ni]);
#pragma unroll
                for (int mi = 0; mi < 2; mi++)
#pragma unroll
                    for (int ni = 0; ni < 3; ni++)
                        mma_bf16(acc[mi][ni], fal[mi], fbh[ni]);
#pragma unroll
                for (int mi = 0; mi < 2; mi++)
#pragma unroll
                    for (int ni = 0; ni < 3; ni++)
                        mma_bf16(acc[mi][ni], fah[mi], fbl[ni]);
            }
            __syncthreads();
            if (c + 2 < 10) load_chunk(c + 2, st);
        }

        // ---- dump C to smem (stage region; all compute synced) ----
#pragma unroll
        for (int mi = 0; mi < 2; mi++) {
            int mr = wm * 32 + mi * 16 + (lane >> 2);
#pragma unroll
            for (int ni = 0; ni < 3; ni++) {
                int nn = wn * 24 + ni * 8 + (lane & 3) * 2;
                cs[mr * GH_STRIDE + nn]           = acc[mi][ni][0];
                cs[mr * GH_STRIDE + nn + 1]       = acc[mi][ni][1];
                cs[(mr + 8) * GH_STRIDE + nn]     = acc[mi][ni][2];
                cs[(mr + 8) * GH_STRIDE + nn + 1] = acc[mi][ni][3];
            }
        }
        __syncthreads();

        // ---- gate epilogue ----
        for (int i = tid; i < 64 * 32; i += 256) {
            int ml = i >> 5, p = i & 31;
            int j = j0 + p;
            if (j < Hv) {
                int m = m0 + ml;
                float gh_r = cs[ml * GH_STRIDE + 3 * p + 0];
                float gh_z = cs[ml * GH_STRIDE + 3 * p + 1];
                float gh_n = cs[ml * GH_STRIDE + 3 * p + 2] + bhn[p];  // b_hh_n inside r*(.)
                float gx_r = gxs[ml * 96 + 3 * p + 0];
                float gx_z = gxs[ml * 96 + 3 * p + 1];
                float gx_n = gxs[ml * 96 + 3 * p + 2];
                float r = 1.f / (1.f + expf(-(gx_r + gh_r)));
                float z = 1.f / (1.f + expf(-(gx_z + gh_z)));
                float ng = tanhf(gx_n + r * gh_n);
                size_t hidx = (size_t)m * KP + j;
                float hp = __bfloat162float(Hp_hi[hidx]) + __bfloat162float(Hp_lo[hidx]);
                float h = (1.f - z) * ng + z * hp;
                __nv_bfloat16 hh = __float2bfloat16(h);
                Ho_hi[hidx] = hh;
                Ho_lo[hidx] = __float2bfloat16(h - __bfloat162float(hh));
            }
        }

        if (use_flags) {
            __threadfence();
            __syncthreads();
            if (tid == 0) red_rel_add1(&d_flag[s][bm]);
        } else {
            __syncthreads();
        }
    }

    // ---- reset phase (persistent mode only): make counters replay-safe ----
    if (use_flags) {
        if (tid == 0) red_rel_add1(&d_done[bm]);
        if (bn == 0) {
            if (tid == 0) {
                while (ld_acq(&d_done[bm]) < (unsigned)NTILE) __nanosleep(64);
            }
            __syncthreads();
            for (int s = tid; s < Lv; s += 256) d_flag[s][bm] = 0;
            if (tid == 0) d_done[bm] = 0;
            __threadfence();
        }
    }
}

// ---------------------------------------------------------------------------
// Post: collapsed co-attention + softmax + pooling + logits. Vectorized h load.
// ---------------------------------------------------------------------------
__device__ __forceinline__ float blockReduceSum(float v, volatile float* red)
{
    __syncthreads();
#pragma unroll
    for (int o = 16; o > 0; o >>= 1) v += __shfl_xor_sync(0xffffffffu, v, o);
    int w = threadIdx.x >> 5, ln = threadIdx.x & 31;
    if (ln == 0) red[w] = v;
    __syncthreads();
    if (threadIdx.x < 32) {
        float x = (threadIdx.x < 8) ? red[threadIdx.x] : 0.f;
#pragma unroll
        for (int o = 4; o > 0; o >>= 1) x += __shfl_xor_sync(0xffffffffu, x, o);
        if (threadIdx.x == 0) red[0] = x;
    }
    __syncthreads();
    return red[0];
}
__device__ __forceinline__ float blockReduceMax(float v, volatile float* red)
{
    __syncthreads();
#pragma unroll
    for (int o = 16; o > 0; o >>= 1) v = fmaxf(v, __shfl_xor_sync(0xffffffffu, v, o));
    int w = threadIdx.x >> 5, ln = threadIdx.x & 31;
    if (ln == 0) red[w] = v;
    __syncthreads();
    if (threadIdx.x < 32) {
        float x = (threadIdx.x < 8) ? red[threadIdx.x] : -3.4e38f;
#pragma unroll
        for (int o = 4; o > 0; o >>= 1) x = fmaxf(x, __shfl_xor_sync(0xffffffffu, x, o));
        if (threadIdx.x == 0) red[0] = x;
    }
    __syncthreads();
    return red[0];
}

__global__ void post_kernel(const __nv_bfloat16* __restrict__ Hhi,
                            const __nv_bfloat16* __restrict__ Hlo,
                            const float* __restrict__ wCo_w, const float* __restrict__ wCo_b,
                            const float* __restrict__ Wmy_w, const float* __restrict__ Wmy_b,
                            const float* __restrict__ logits_w, const float* __restrict__ logits_b,
                            float* __restrict__ out)
{
    extern __shared__ float fs[];
    float* h_s    = fs;
    float* wa     = h_s + Lv * Hv;
    float* wb_    = wa + Hv;
    float* wc     = wb_ + Hv;
    float* wmy    = wc + Hv;
    float* aa     = wmy + 80;
    float* bb     = aa + 80;
    float* qq     = bb + 80;
    float* pp     = qq + 80;
    float* smarr  = pp + 80;
    float* attn   = smarr + 80;
    float* u      = attn + 80;
    float* pooled = u + Hv;
    __shared__ float red[32];

    int b = blockIdx.x;
    int tid = threadIdx.x;
    int w = tid >> 5, ln = tid & 31;

    for (int t = tid; t < Lv * (Hv / 4); t += 256) {
        int i = t / (Hv / 4), d4 = (t - i * (Hv / 4)) * 4;
        size_t idx = (size_t)(i + 1) * Bv * KP + (size_t)b * KP + d4;
        uint2 vh = *(const uint2*)(Hhi + idx);
        uint2 vl = *(const uint2*)(Hlo + idx);
        const __nv_bfloat162* ph = (const __nv_bfloat162*)&vh;
        const __nv_bfloat162* pl = (const __nv_bfloat162*)&vl;
        float2 h0 = __bfloat1622float2(ph[0]);
        float2 l0 = __bfloat1622float2(pl[0]);
        float2 h1 = __bfloat1622float2(ph[1]);
        float2 l1 = __bfloat1622float2(pl[1]);
        float* dst = h_s + i * Hv + d4;
        dst[0] = h0.x + l0.x;
        dst[1] = h0.y + l0.y;
        dst[2] = h1.x + l1.x;
        dst[3] = h1.y + l1.y;
    }
    for (int t = tid; t < Hv; t += 256) {
        wa[t]  = wCo_w[t];
        wb_[t] = wCo_w[Hv + t];
        wc[t]  = wCo_w[2 * Hv + t];
    }
    if (tid < Lv) wmy[tid] = Wmy_w[tid];
    __syncthreads();

    for (int i = w; i < Lv; i += 8) {
        float sa = 0.f, sb2 = 0.f, sq = 0.f;
        for (int d = ln; d < Hv; d += 32) {
            float hv = h_s[i * Hv + d];
            sa += hv * wa[d];
            sb2 += hv * wb_[d];
            sq += hv * hv * wc[d];
        }
#pragma unroll
        for (int o = 16; o > 0; o >>= 1) {
            sa += __shfl_xor_sync(0xffffffffu, sa, o);
            sb2 += __shfl_xor_sync(0xffffffffu, sb2, o);
            sq += __shfl_xor_sync(0xffffffffu, sq, o);
        }
        if (ln == 0) { aa[i] = sa; bb[i] = sb2; qq[i] = sq; }
    }
    __syncthreads();

    for (int d = tid; d < Hv; d += 256) {
        float s = 0.f;
#pragma unroll 5
        for (int i = 0; i < Lv; i++) s += wmy[i] * h_s[i * Hv + d];
        u[d] = s;
    }

    float swv = (tid < Lv) ? wmy[tid] : 0.f;
    float Sw = blockReduceSum(swv, red);
    float tv = (tid < Lv) ? wmy[tid] * bb[tid] : 0.f;
    float T = blockReduceSum(tv, red);
    __syncthreads();

    for (int i = w; i < Lv; i += 8) {
        float sp = 0.f;
        for (int d = ln; d < Hv; d += 32) sp += h_s[i * Hv + d] * wc[d] * u[d];
#pragma unroll
        for (int o = 16; o > 0; o >>= 1) sp += __shfl_xor_sync(0xffffffffu, sp, o);
        if (ln == 0) pp[i] = sp;
    }
    __syncthreads();

    float beta = wCo_b[0];
    if (tid < Lv) {
        smarr[tid] = (aa[tid] + beta) * Sw + T + pp[tid]
                   - wmy[tid] * (aa[tid] + bb[tid] + beta + qq[tid]) + Wmy_b[0];
    }
    __syncthreads();

    float mv = (tid < Lv) ? smarr[tid] : -3.4e38f;
    float mx = blockReduceMax(mv, red);
    float ev = (tid < Lv) ? expf(smarr[tid] - mx) : 0.f;
    if (tid < Lv) attn[tid] = ev;
    float se = blockReduceSum(ev, red);
    if (tid < Lv) attn[tid] = attn[tid] / se;
    __syncthreads();

    for (int d = tid; d < Hv; d += 256) {
        float s = 0.f;
#pragma unroll 5
        for (int i = 0; i < Lv; i++) s += attn[i] * h_s[i * Hv + d];
        pooled[d] = s;
    }
    __syncthreads();

    if (w < OUTv) {
        float s = 0.f;
        for (int d = ln; d < Hv; d += 32) s += pooled[d] * logits_w[w * Hv + d];
#pragma unroll
        for (int o = 16; o > 0; o >>= 1) s += __shfl_xor_sync(0xffffffffu, s, o);
        if (ln == 0) out[(size_t)b * OUTv + w] = s + logits_b[w];
    }
}

// ---------------------------------------------------------------------------
extern "C" void kernel_launch(void* const* d_in, const int* in_sizes, int n_in,
                              void* d_out, int out_size)
{
    const int*   seq      = (const int*)  d_in[0];
    const float* emb      = (const float*)d_in[1];
    const float* W_ih     = (const float*)d_in[2];
    const float* W_hh     = (const float*)d_in[3];
    const float* b_ih     = (const float*)d_in[4];
    const float* b_hh     = (const float*)d_in[5];
    const float* wCo_w    = (const float*)d_in[6];
    const float* wCo_b    = (const float*)d_in[7];
    const float* Wmy_w    = (const float*)d_in[8];
    const float* Wmy_b    = (const float*)d_in[9];
    const float* logits_w = (const float*)d_in[10];
    const float* logits_b = (const float*)d_in[11];
    float* out = (float*)d_out;

    __nv_bfloat16 *ehi, *elo, *wih_hi, *wih_lo, *whh_hi, *whh_lo, *Hhi, *Hlo;
    float *bpih, *bphh, *VG;
    cudaGetSymbolAddress((void**)&ehi,    d_emb_hi);
    cudaGetSymbolAddress((void**)&elo,    d_emb_lo);
    cudaGetSymbolAddress((void**)&wih_hi, d_Wih_hi);
    cudaGetSymbolAddress((void**)&wih_lo, d_Wih_lo);
    cudaGetSymbolAddress((void**)&whh_hi, d_Whh_hi);
    cudaGetSymbolAddress((void**)&whh_lo, d_Whh_lo);
    cudaGetSymbolAddress((void**)&bpih,   d_bp_ih);
    cudaGetSymbolAddress((void**)&bphh,   d_bp_hh);
    cudaGetSymbolAddress((void**)&VG,     d_VG);
    cudaGetSymbolAddress((void**)&Hhi,    d_Hhi);
    cudaGetSymbolAddress((void**)&Hlo,    d_Hlo);

    cudaFuncSetAttribute(vg_gemm, cudaFuncAttributeMaxDynamicSharedMemorySize, SMEM_VG);
    cudaFuncSetAttribute(gru_persist, cudaFuncAttributeMaxDynamicSharedMemorySize, SMEM_STEP);
    const int POST_SMEM = (Lv * Hv + 3 * Hv + 7 * 80 + 2 * Hv) * (int)sizeof(float);
    cudaFuncSetAttribute(post_kernel, cudaFuncAttributeMaxDynamicSharedMemorySize, POST_SMEM);

    // Persistent only if all 320 blocks provably co-resident.
    int occ = 0, sms = 0;
    cudaOccupancyMaxActiveBlocksPerMultiprocessor(&occ, gru_persist, 256, SMEM_STEP);
    cudaDeviceGetAttribute(&sms, cudaDevAttrMultiProcessorCount, 0);
    bool persistent = ((long)occ * sms >= NTILE * MTILE);

    // 0) conversions
    {
        long n = (long)VOCAB * Ev;
        conv_emb<<<(unsigned)((n + 255) / 256), 256>>>(emb, ehi, elo);
    }
    conv_w<<<G3, 128>>>(W_ih, b_ih, wih_hi, wih_lo, bpih);
    conv_w<<<G3, 128>>>(W_hh, b_hh, whh_hi, whh_lo, bphh);

    // 1) VG = emb @ W_ih^T + b_ih + rz(b_hh) over full vocab
    {
        dim3 grid(10, VROWS / 128);
        vg_gemm<<<grid, 256, SMEM_VG>>>(ehi, elo, wih_hi, wih_lo, bpih, bphh, VG);
    }

    // 2) GRU recurrence
    dim3 grid(NTILE, MTILE);
    if (persistent) {
        gru_persist<<<grid, 256, SMEM_STEP>>>(Hhi, Hlo, whh_hi, whh_lo,
                                              seq, VG, bphh, 0, Lv, 1);
    } else {
        for (int l = 0; l < Lv; l++)
            gru_persist<<<grid, 256, SMEM_STEP>>>(Hhi, Hlo, whh_hi, whh_lo,
                                                  seq, VG, bphh, l, l + 1, 0);
    }

    // 3) collapsed co-attention + softmax + pooling + logits
    post_kernel<<<Bv, 256, POST_SMEM>>>(Hhi, Hlo, wCo_w, wCo_b, Wmy_w, Wmy_b,
                                        logits_w, logits_b, out);
}

// round 13
// speedup vs baseline: 1.6324x; 1.0897x over previous
#include <cuda_runtime.h>
#include <cuda_bf16.h>
#include <math.h>
#include <stdint.h>

#define Bv   2048
#define Lv   75
#define Ev   300
#define Hv   300
#define G3   900
#define OUTv 5
#define KP   320                 // K padded to 10 x 32
#define VROWS 50048              // vocab rows padded to 391*128
#define NROWS 960                // gate rows padded to 10*96
#define VOCAB 50000
#define NTILE 10                 // n-blocks per step
#define MTILE 32                 // m-blocks per step

// ---------------- scratch (device globals; zero-initialized) ---------------
__device__ __nv_bfloat16 d_emb_hi[(size_t)VROWS * KP];
__device__ __nv_bfloat16 d_emb_lo[(size_t)VROWS * KP];
__device__ __nv_bfloat16 d_Wih_hi[NROWS * KP];
__device__ __nv_bfloat16 d_Wih_lo[NROWS * KP];
__device__ __nv_bfloat16 d_Whh_hi[NROWS * KP];
__device__ __nv_bfloat16 d_Whh_lo[NROWS * KP];
__device__ float d_bp_ih[G3];
__device__ float d_bp_hh[G3];
__device__ float d_VG[(size_t)VROWS * G3];                   // vocab gates (b_ih + rz(b_hh) folded)
__device__ __nv_bfloat16 d_Hhi[(size_t)(Lv + 1) * Bv * KP];  // slice 0 = zeros
__device__ __nv_bfloat16 d_Hlo[(size_t)(Lv + 1) * Bv * KP];
__device__ unsigned int d_flag[Lv][MTILE];                   // producers of slice s+1
__device__ unsigned int d_done[MTILE];

// ---------------------------- helpers ---------------------------------------
__device__ __forceinline__ uint32_t smem_u32(const void* p) {
    uint32_t a;
    asm("{ .reg .u64 t; cvta.to.shared.u64 t, %1; cvt.u32.u64 %0, t; }" : "=r"(a) : "l"(p));
    return a;
}
__device__ __forceinline__ void ldsm_x4(uint32_t* r, uint32_t addr) {
    asm volatile("ldmatrix.sync.aligned.m8n8.x4.shared.b16 {%0,%1,%2,%3}, [%4];"
                 : "=r"(r[0]), "=r"(r[1]), "=r"(r[2]), "=r"(r[3]) : "r"(addr));
}
__device__ __forceinline__ void ldsm_x2(uint32_t* r, uint32_t addr) {
    asm volatile("ldmatrix.sync.aligned.m8n8.x2.shared.b16 {%0,%1}, [%2];"
                 : "=r"(r[0]), "=r"(r[1]) : "r"(addr));
}
__device__ __forceinline__ void mma_bf16(float* c, const uint32_t* a, const uint32_t* b) {
    asm volatile(
        "mma.sync.aligned.m16n8k16.row.col.f32.bf16.bf16.f32 "
        "{%0,%1,%2,%3}, {%4,%5,%6,%7}, {%8,%9}, {%0,%1,%2,%3};"
        : "+f"(c[0]), "+f"(c[1]), "+f"(c[2]), "+f"(c[3])
        : "r"(a[0]), "r"(a[1]), "r"(a[2]), "r"(a[3]), "r"(b[0]), "r"(b[1]));
}
__device__ __forceinline__ void cp16(uint32_t dst, const void* src) {
    asm volatile("cp.async.cg.shared.global [%0], [%1], 16;" :: "r"(dst), "l"(src));
}
#define CP_COMMIT() asm volatile("cp.async.commit_group;" ::: "memory")
#define CP_WAIT0()  asm volatile("cp.async.wait_group 0;" ::: "memory")

__device__ __forceinline__ unsigned int ld_acq(const unsigned int* p) {
    unsigned int v;
    asm volatile("ld.global.acquire.gpu.u32 %0, [%1];" : "=r"(v) : "l"(p) : "memory");
    return v;
}
__device__ __forceinline__ void red_rel_add1(unsigned int* p) {
    asm volatile("red.release.gpu.global.add.u32 [%0], 1;" :: "l"(p) : "memory");
}
// fast clamped sigmoid/tanh (MUFU-based; error ~1e-6, budget 1e-3)
__device__ __forceinline__ float fsig(float x) {
    x = fminf(fmaxf(x, -30.f), 30.f);
    return __fdividef(1.f, 1.f + __expf(-x));
}
__device__ __forceinline__ float ftanh(float x) {
    x = fminf(fmaxf(x, -15.f), 15.f);
    float e = __expf(2.f * x);
    return __fdividef(e - 1.f, e + 1.f);
}

// ---------------------------- conversion kernels ---------------------------
__global__ void conv_emb(const float* __restrict__ emb,
                         __nv_bfloat16* __restrict__ hi, __nv_bfloat16* __restrict__ lo)
{
    long i = (long)blockIdx.x * blockDim.x + threadIdx.x;
    if (i >= (long)VOCAB * Ev) return;
    int row = (int)(i / Ev), col = (int)(i - (long)row * Ev);
    float x = emb[i];
    __nv_bfloat16 h = __float2bfloat16(x);
    hi[(size_t)row * KP + col] = h;
    lo[(size_t)row * KP + col] = __float2bfloat16(x - __bfloat162float(h));
}

__global__ void conv_w(const float* __restrict__ W, const float* __restrict__ b,
                       __nv_bfloat16* __restrict__ hi, __nv_bfloat16* __restrict__ lo,
                       float* __restrict__ bp)
{
    int n = blockIdx.x;            // 0..899, target row = 3j+g
    int j = n / 3, g = n % 3;
    const float* src = W + (size_t)(g * Hv + j) * 300;
    for (int k = threadIdx.x; k < 300; k += blockDim.x) {
        float x = src[k];
        __nv_bfloat16 h = __float2bfloat16(x);
        hi[(size_t)n * KP + k] = h;
        lo[(size_t)n * KP + k] = __float2bfloat16(x - __bfloat162float(h));
    }
    if (threadIdx.x == 0) bp[n] = b[g * Hv + j];
}

// ---------------------------------------------------------------------------
// VG GEMM: VG = emb @ W_ih^T + b_ih + rz(b_hh). Superchunk 4-plane pipeline,
// 2 stages, ONE sync per chunk. Block 128x96, warp tile 64x24.
// ---------------------------------------------------------------------------
#define V_A_HI(s) ((s) * 17920 + 0)
#define V_A_LO(s) ((s) * 17920 + 5120)
#define V_B_HI(s) ((s) * 17920 + 10240)
#define V_B_LO(s) ((s) * 17920 + 14080)
#define GH_STRIDE 100
#define SMEM_VG (2 * 17920 * 2)

__global__ void __launch_bounds__(256)
vg_gemm(const __nv_bfloat16* __restrict__ Ahi, const __nv_bfloat16* __restrict__ Alo,
        const __nv_bfloat16* __restrict__ Bhi, const __nv_bfloat16* __restrict__ Blo,
        const float* __restrict__ bias1, const float* __restrict__ bias2,
        float* __restrict__ VGout)
{
    extern __shared__ __align__(16) char smem[];
    float* ghs = (float*)smem;
    const uint32_t sbase = smem_u32(smem);

    int tid = threadIdx.x;
    int lane = tid & 31, wid = tid >> 5;
    int wm = wid >> 2, wn = wid & 3;
    int m0 = blockIdx.y * 128;
    int n0 = blockIdx.x * 96;

    int a_row = lane & 15, a_k = (lane >> 4) << 3;
    int b_row = lane & 7,  b_k = ((lane >> 3) & 1) << 3;

    auto load_chunk = [&](int cc, int s) {
        int kb = cc * 32;
        int r1 = tid >> 2, co = (tid & 3) * 8;
        int r2 = 64 + r1;
        cp16(sbase + (uint32_t)(V_A_HI(s) + r1 * 40 + co) * 2, Ahi + (size_t)(m0 + r1) * KP + kb + co);
        cp16(sbase + (uint32_t)(V_A_HI(s) + r2 * 40 + co) * 2, Ahi + (size_t)(m0 + r2) * KP + kb + co);
        cp16(sbase + (uint32_t)(V_A_LO(s) + r1 * 40 + co) * 2, Alo + (size_t)(m0 + r1) * KP + kb + co);
        cp16(sbase + (uint32_t)(V_A_LO(s) + r2 * 40 + co) * 2, Alo + (size_t)(m0 + r2) * KP + kb + co);
        cp16(sbase + (uint32_t)(V_B_HI(s) + r1 * 40 + co) * 2, Bhi + (size_t)(n0 + r1) * KP + kb + co);
        cp16(sbase + (uint32_t)(V_B_LO(s) + r1 * 40 + co) * 2, Blo + (size_t)(n0 + r1) * KP + kb + co);
        if (tid < 128) {
            int r3 = 64 + r1;
            cp16(sbase + (uint32_t)(V_B_HI(s) + r3 * 40 + co) * 2, Bhi + (size_t)(n0 + r3) * KP + kb + co);
            cp16(sbase + (uint32_t)(V_B_LO(s) + r3 * 40 + co) * 2, Blo + (size_t)(n0 + r3) * KP + kb + co);
        }
        CP_COMMIT();
    };

    float acc[4][3][4];
#pragma unroll
    for (int mi = 0; mi < 4; mi++)
#pragma unroll
        for (int ni = 0; ni < 3; ni++)
#pragma unroll
            for (int q = 0; q < 4; q++) acc[mi][ni][q] = 0.f;

    load_chunk(0, 0);

    for (int c = 0; c < 10; c++) {
        CP_WAIT0();
        __syncthreads();
        if (c < 9) load_chunk(c + 1, (c + 1) & 1);
        int s = c & 1;
        uint32_t ah = sbase + (uint32_t)V_A_HI(s) * 2;
        uint32_t al = sbase + (uint32_t)V_A_LO(s) * 2;
        uint32_t bh = sbase + (uint32_t)V_B_HI(s) * 2;
        uint32_t bl = sbase + (uint32_t)V_B_LO(s) * 2;
#pragma unroll
        for (int kk = 0; kk < 2; kk++) {
            uint32_t fah[4][4], fal[4][4], fbh[3][2], fbl[3][2];
#pragma unroll
            for (int mi = 0; mi < 4; mi++) {
                uint32_t ro = (uint32_t)((wm * 64 + mi * 16 + a_row) * 40 + kk * 16 + a_k) * 2;
                ldsm_x4(fah[mi], ah + ro);
                ldsm_x4(fal[mi], al + ro);
            }
#pragma unroll
            for (int ni = 0; ni < 3; ni++) {
                uint32_t ro = (uint32_t)((wn * 24 + ni * 8 + b_row) * 40 + kk * 16 + b_k) * 2;
                ldsm_x2(fbh[ni], bh + ro);
                ldsm_x2(fbl[ni], bl + ro);
            }
#pragma unroll
            for (int mi = 0; mi < 4; mi++)
#pragma unroll
                for (int ni = 0; ni < 3; ni++)
                    mma_bf16(acc[mi][ni], fah[mi], fbh[ni]);
#pragma unroll
            for (int mi = 0; mi < 4; mi++)
#pragma unroll
                for (int ni = 0; ni < 3; ni++)
                    mma_bf16(acc[mi][ni], fal[mi], fbh[ni]);
#pragma unroll
            for (int mi = 0; mi < 4; mi++)
#pragma unroll
                for (int ni = 0; ni < 3; ni++)
                    mma_bf16(acc[mi][ni], fah[mi], fbl[ni]);
        }
    }
    __syncthreads();   // ghs (51200 B) overlaps stage 1 — must drain compute

#pragma unroll
    for (int mi = 0; mi < 4; mi++) {
        int mr = wm * 64 + mi * 16 + (lane >> 2);
#pragma unroll
        for (int ni = 0; ni < 3; ni++) {
            int nn = wn * 24 + ni * 8 + (lane & 3) * 2;
            ghs[mr * GH_STRIDE + nn]           = acc[mi][ni][0];
            ghs[mr * GH_STRIDE + nn + 1]       = acc[mi][ni][1];
            ghs[(mr + 8) * GH_STRIDE + nn]     = acc[mi][ni][2];
            ghs[(mr + 8) * GH_STRIDE + nn + 1] = acc[mi][ni][3];
        }
    }
    __syncthreads();

    for (int i = tid; i < 128 * 96; i += 256) {
        int m = i / 96, n = i - m * 96;
        int gn = n0 + n;
        if (gn < G3) {
            float b2 = (gn % 3 != 2) ? bias2[gn] : 0.f;   // fold b_hh for r,z only
            VGout[(size_t)(m0 + m) * G3 + gn] = ghs[m * GH_STRIDE + n] + bias1[gn] + b2;
        }
    }
}

// ---------------------------------------------------------------------------
// GRU steps, persistent: 320 blocks (10n x 32m), tile 64x96, 8 warps,
// warp tile 32x24, 2 stages, ONE sync per chunk. Coarse per-m flags.
// smem: stages [0,51200), gx [51200,75776), bhn [75776,75904).
// C-dump (cs, 25600 B) aliases stage 0 exactly; chunk 9 reads stage 1, so
// no pre-dump sync is needed.
// ---------------------------------------------------------------------------
#define S_A_HI(s) ((s) * 12800 + 0)
#define S_A_LO(s) ((s) * 12800 + 2560)
#define S_B_HI(s) ((s) * 12800 + 5120)
#define S_B_LO(s) ((s) * 12800 + 8960)
#define GXS_B 51200
#define BHN_B 75776
#define SMEM_STEP 75904

__global__ void __launch_bounds__(256, 3)
gru_persist(const __nv_bfloat16* __restrict__ Hhi_all, const __nv_bfloat16* __restrict__ Hlo_all,
            const __nv_bfloat16* __restrict__ Bhi, const __nv_bfloat16* __restrict__ Blo,
            const int* __restrict__ seq, const float* __restrict__ VGin,
            const float* __restrict__ bph,
            int s_begin, int s_end, int use_flags)
{
    extern __shared__ __align__(16) char smem[];
    float* cs  = (float*)smem;                    // epilogue C, aliases stage 0
    float* gxs = (float*)(smem + GXS_B);
    float* bhn = (float*)(smem + BHN_B);
    const uint32_t sbase = smem_u32(smem);

    int tid = threadIdx.x;
    int lane = tid & 31, wid = tid >> 5;
    int wm = wid >> 2, wn = wid & 3;
    int bn = blockIdx.x;                          // 0..9
    int bm = blockIdx.y;                          // 0..31
    int m0 = bm * 64;
    int n0 = bn * 96;
    int j0 = bn * 32;

    if (tid < 32 && (n0 + 3 * tid + 2) < G3) bhn[tid] = bph[n0 + 3 * tid + 2];

    int a_row = lane & 15, a_k = (lane >> 4) << 3;
    int b_row = lane & 7,  b_k = ((lane >> 3) & 1) << 3;
    const size_t slice = (size_t)Bv * KP;

    for (int s = s_begin; s < s_end; s++) {
        const __nv_bfloat16* Hp_hi = Hhi_all + (size_t)s * slice;
        const __nv_bfloat16* Hp_lo = Hlo_all + (size_t)s * slice;
        __nv_bfloat16* Ho_hi = (__nv_bfloat16*)(Hhi_all + (size_t)(s + 1) * slice);
        __nv_bfloat16* Ho_lo = (__nv_bfloat16*)(Hlo_all + (size_t)(s + 1) * slice);

        // ---- gx gather for this step (flag-independent; issue first) ----
#pragma unroll
        for (int c = 0; c < 6; c++) {
            int idx = tid + c * 256;           // 0..1535
            int row = idx / 24, off = (idx % 24) * 4;
            int t = seq[(m0 + row) * Lv + s];
            cp16(sbase + GXS_B + (uint32_t)(row * 96 + off) * 4,
                 VGin + (size_t)t * G3 + n0 + off);
        }
        CP_COMMIT();

        // ---- wait for the 10 producers of slice s (rows m-range) ----
        if (use_flags && s > 0) {
            if (tid == 0) {
                while (ld_acq(&d_flag[s - 1][bm]) < (unsigned)NTILE) __nanosleep(64);
            }
        }
        __syncthreads();

        auto load_chunk = [&](int cc, int st) {
            int kb = cc * 32;
            int r1 = tid >> 2, co = (tid & 3) * 8;
            cp16(sbase + (uint32_t)(S_A_HI(st) + r1 * 40 + co) * 2, Hp_hi + (size_t)(m0 + r1) * KP + kb + co);
            cp16(sbase + (uint32_t)(S_A_LO(st) + r1 * 40 + co) * 2, Hp_lo + (size_t)(m0 + r1) * KP + kb + co);
            cp16(sbase + (uint32_t)(S_B_HI(st) + r1 * 40 + co) * 2, Bhi + (size_t)(n0 + r1) * KP + kb + co);
            cp16(sbase + (uint32_t)(S_B_LO(st) + r1 * 40 + co) * 2, Blo + (size_t)(n0 + r1) * KP + kb + co);
            if (tid < 128) {
                int r2 = 64 + r1;
                cp16(sbase + (uint32_t)(S_B_HI(st) + r2 * 40 + co) * 2, Bhi + (size_t)(n0 + r2) * KP + kb + co);
                cp16(sbase + (uint32_t)(S_B_LO(st) + r2 * 40 + co) * 2, Blo + (size_t)(n0 + r2) * KP + kb + co);
            }
            CP_COMMIT();
        };

        float acc[2][3][4];
#pragma unroll
        for (int mi = 0; mi < 2; mi++)
#pragma unroll
            for (int ni = 0; ni < 3; ni++)
#pragma unroll
                for (int q = 0; q < 4; q++) acc[mi][ni][q] = 0.f;

        load_chunk(0, 0);

        for (int c = 0; c < 10; c++) {
            CP_WAIT0();
            __syncthreads();
            if (c < 9) load_chunk(c + 1, (c + 1) & 1);
            int st = c & 1;
            uint32_t ah = sbase + (uint32_t)S_A_HI(st) * 2;
            uint32_t al = sbase + (uint32_t)S_A_LO(st) * 2;
            uint32_t bh = sbase + (uint32_t)S_B_HI(st) * 2;
            uint32_t bl = sbase + (uint32_t)S_B_LO(st) * 2;
#pragma unroll
            for (int kk = 0; kk < 2; kk++) {
                uint32_t fah[2][4], fal[2][4], fbh[3][2], fbl[3][2];
#pragma unroll
                for (int mi = 0; mi < 2; mi++) {
                    uint32_t ro = (uint32_t)((wm * 32 + mi * 16 + a_row) * 40 + kk * 16 + a_k) * 2;
                    ldsm_x4(fah[mi], ah + ro);
                    ldsm_x4(fal[mi], al + ro);
                }
#pragma unroll
                for (int ni = 0; ni < 3; ni++) {
                    uint32_t ro = (uint32_t)((wn * 24 + ni * 8 + b_row) * 40 + kk * 16 + b_k) * 2;
                    ldsm_x2(fbh[ni], bh + ro);
                    ldsm_x2(fbl[ni], bl + ro);
                }
#pragma unroll
                for (int mi = 0; mi < 2; mi++)
#pragma unroll
                    for (int ni = 0; ni < 3; ni++)
                        mma_bf16(acc[mi][ni], fah[mi], fbh[ni]);
#pragma unroll
                for (int mi = 0; mi < 2; mi++)
#pragma unroll
                    for (int ni = 0; ni < 3; ni++)
                        mma_bf16(acc[mi][ni], fal[mi], fbh[ni]);
#pragma unroll
                for (int mi = 0; mi < 2; mi++)
#pragma unroll
                    for (int ni = 0; ni < 3; ni++)
                        mma_bf16(acc[mi][ni], fah[mi], fbl[ni]);
            }
        }

        // ---- dump C to smem stage 0 (chunk 9 used stage 1 -> no pre-sync) ----
#pragma unroll
        for (int mi = 0; mi < 2; mi++) {
            int mr = wm * 32 + mi * 16 + (lane >> 2);
#pragma unroll
            for (int ni = 0; ni < 3; ni++) {
                int nn = wn * 24 + ni * 8 + (lane & 3) * 2;
                cs[mr * GH_STRIDE + nn]           = acc[mi][ni][0];
                cs[mr * GH_STRIDE + nn + 1]       = acc[mi][ni][1];
                cs[(mr + 8) * GH_STRIDE + nn]     = acc[mi][ni][2];
                cs[(mr + 8) * GH_STRIDE + nn + 1] = acc[mi][ni][3];
            }
        }
        __syncthreads();

        // ---- gate epilogue ----
        for (int i = tid; i < 64 * 32; i += 256) {
            int ml = i >> 5, p = i & 31;
            int j = j0 + p;
            if (j < Hv) {
                int m = m0 + ml;
                float gh_r = cs[ml * GH_STRIDE + 3 * p + 0];
                float gh_z = cs[ml * GH_STRIDE + 3 * p + 1];
                float gh_n = cs[ml * GH_STRIDE + 3 * p + 2] + bhn[p];  // b_hh_n inside r*(.)
                float gx_r = gxs[ml * 96 + 3 * p + 0];
                float gx_z = gxs[ml * 96 + 3 * p + 1];
                float gx_n = gxs[ml * 96 + 3 * p + 2];
                float r = fsig(gx_r + gh_r);
                float z = fsig(gx_z + gh_z);
                float ng = ftanh(gx_n + r * gh_n);
                size_t hidx = (size_t)m * KP + j;
                float hp = __bfloat162float(Hp_hi[hidx]) + __bfloat162float(Hp_lo[hidx]);
                float h = (1.f - z) * ng + z * hp;
                __nv_bfloat16 hh = __float2bfloat16(h);
                Ho_hi[hidx] = hh;
                Ho_lo[hidx] = __float2bfloat16(h - __bfloat162float(hh));
            }
        }

        if (use_flags) {
            __threadfence();
            __syncthreads();
            if (tid == 0) red_rel_add1(&d_flag[s][bm]);
        } else {
            __syncthreads();
        }
    }

    // ---- reset phase (persistent mode only): make counters replay-safe ----
    if (use_flags) {
        if (tid == 0) red_rel_add1(&d_done[bm]);
        if (bn == 0) {
            if (tid == 0) {
                while (ld_acq(&d_done[bm]) < (unsigned)NTILE) __nanosleep(64);
            }
            __syncthreads();
            for (int s = tid; s < Lv; s += 256) d_flag[s][bm] = 0;
            if (tid == 0) d_done[bm] = 0;
            __threadfence();
        }
    }
}

// ---------------------------------------------------------------------------
// Post: collapsed co-attention + softmax + pooling + logits. Vectorized h load.
// ---------------------------------------------------------------------------
__device__ __forceinline__ float blockReduceSum(float v, volatile float* red)
{
    __syncthreads();
#pragma unroll
    for (int o = 16; o > 0; o >>= 1) v += __shfl_xor_sync(0xffffffffu, v, o);
    int w = threadIdx.x >> 5, ln = threadIdx.x & 31;
    if (ln == 0) red[w] = v;
    __syncthreads();
    if (threadIdx.x < 32) {
        float x = (threadIdx.x < 8) ? red[threadIdx.x] : 0.f;
#pragma unroll
        for (int o = 4; o > 0; o >>= 1) x += __shfl_xor_sync(0xffffffffu, x, o);
        if (threadIdx.x == 0) red[0] = x;
    }
    __syncthreads();
    return red[0];
}
__device__ __forceinline__ float blockReduceMax(float v, volatile float* red)
{
    __syncthreads();
#pragma unroll
    for (int o = 16; o > 0; o >>= 1) v = fmaxf(v, __shfl_xor_sync(0xffffffffu, v, o));
    int w = threadIdx.x >> 5, ln = threadIdx.x & 31;
    if (ln == 0) red[w] = v;
    __syncthreads();
    if (threadIdx.x < 32) {
        float x = (threadIdx.x < 8) ? red[threadIdx.x] : -3.4e38f;
#pragma unroll
        for (int o = 4; o > 0; o >>= 1) x = fmaxf(x, __shfl_xor_sync(0xffffffffu, x, o));
        if (threadIdx.x == 0) red[0] = x;
    }
    __syncthreads();
    return red[0];
}

__global__ void post_kernel(const __nv_bfloat16* __restrict__ Hhi,
                            const __nv_bfloat16* __restrict__ Hlo,
                            const float* __restrict__ wCo_w, const float* __restrict__ wCo_b,
                            const float* __restrict__ Wmy_w, const float* __restrict__ Wmy_b,
                            const float* __restrict__ logits_w, const float* __restrict__ logits_b,
                            float* __restrict__ out)
{
    extern __shared__ float fs[];
    float* h_s    = fs;
    float* wa     = h_s + Lv * Hv;
    float* wb_    = wa + Hv;
    float* wc     = wb_ + Hv;
    float* wmy    = wc + Hv;
    float* aa     = wmy + 80;
    float* bb     = aa + 80;
    float* qq     = bb + 80;
    float* pp     = qq + 80;
    float* smarr  = pp + 80;
    float* attn   = smarr + 80;
    float* u      = attn + 80;
    float* pooled = u + Hv;
    __shared__ float red[32];

    int b = blockIdx.x;
    int tid = threadIdx.x;
    int w = tid >> 5, ln = tid & 31;

    for (int t = tid; t < Lv * (Hv / 4); t += 256) {
        int i = t / (Hv / 4), d4 = (t - i * (Hv / 4)) * 4;
        size_t idx = (size_t)(i + 1) * Bv * KP + (size_t)b * KP + d4;
        uint2 vh = *(const uint2*)(Hhi + idx);
        uint2 vl = *(const uint2*)(Hlo + idx);
        const __nv_bfloat162* ph = (const __nv_bfloat162*)&vh;
        const __nv_bfloat162* pl = (const __nv_bfloat162*)&vl;
        float2 h0 = __bfloat1622float2(ph[0]);
        float2 l0 = __bfloat1622float2(pl[0]);
        float2 h1 = __bfloat1622float2(ph[1]);
        float2 l1 = __bfloat1622float2(pl[1]);
        float* dst = h_s + i * Hv + d4;
        dst[0] = h0.x + l0.x;
        dst[1] = h0.y + l0.y;
        dst[2] = h1.x + l1.x;
        dst[3] = h1.y + l1.y;
    }
    for (int t = tid; t < Hv; t += 256) {
        wa[t]  = wCo_w[t];
        wb_[t] = wCo_w[Hv + t];
        wc[t]  = wCo_w[2 * Hv + t];
    }
    if (tid < Lv) wmy[tid] = Wmy_w[tid];
    __syncthreads();

    for (int i = w; i < Lv; i += 8) {
        float sa = 0.f, sb2 = 0.f, sq = 0.f;
        for (int d = ln; d < Hv; d += 32) {
            float hv = h_s[i * Hv + d];
            sa += hv * wa[d];
            sb2 += hv * wb_[d];
            sq += hv * hv * wc[d];
        }
#pragma unroll
        for (int o = 16; o > 0; o >>= 1) {
            sa += __shfl_xor_sync(0xffffffffu, sa, o);
            sb2 += __shfl_xor_sync(0xffffffffu, sb2, o);
            sq += __shfl_xor_sync(0xffffffffu, sq, o);
        }
        if (ln == 0) { aa[i] = sa; bb[i] = sb2; qq[i] = sq; }
    }
    __syncthreads();

    for (int d = tid; d < Hv; d += 256) {
        float s = 0.f;
#pragma unroll 5
        for (int i = 0; i < Lv; i++) s += wmy[i] * h_s[i * Hv + d];
        u[d] = s;
    }

    float swv = (tid < Lv) ? wmy[tid] : 0.f;
    float Sw = blockReduceSum(swv, red);
    float tv = (tid < Lv) ? wmy[tid] * bb[tid] : 0.f;
    float T = blockReduceSum(tv, red);
    __syncthreads();

    for (int i = w; i < Lv; i += 8) {
        float sp = 0.f;
        for (int d = ln; d < Hv; d += 32) sp += h_s[i * Hv + d] * wc[d] * u[d];
#pragma unroll
        for (int o = 16; o > 0; o >>= 1) sp += __shfl_xor_sync(0xffffffffu, sp, o);
        if (ln == 0) pp[i] = sp;
    }
    __syncthreads();

    float beta = wCo_b[0];
    if (tid < Lv) {
        smarr[tid] = (aa[tid] + beta) * Sw + T + pp[tid]
                   - wmy[tid] * (aa[tid] + bb[tid] + beta + qq[tid]) + Wmy_b[0];
    }
    __syncthreads();

    float mv = (tid < Lv) ? smarr[tid] : -3.4e38f;
    float mx = blockReduceMax(mv, red);
    float ev = (tid < Lv) ? expf(smarr[tid] - mx) : 0.f;
    if (tid < Lv) attn[tid] = ev;
    float se = blockReduceSum(ev, red);
    if (tid < Lv) attn[tid] = attn[tid] / se;
    __syncthreads();

    for (int d = tid; d < Hv; d += 256) {
        float s = 0.f;
#pragma unroll 5
        for (int i = 0; i < Lv; i++) s += attn[i] * h_s[i * Hv + d];
        pooled[d] = s;
    }
    __syncthreads();

    if (w < OUTv) {
        float s = 0.f;
        for (int d = ln; d < Hv; d += 32) s += pooled[d] * logits_w[w * Hv + d];
#pragma unroll
        for (int o = 16; o > 0; o >>= 1) s += __shfl_xor_sync(0xffffffffu, s, o);
        if (ln == 0) out[(size_t)b * OUTv + w] = s + logits_b[w];
    }
}

// ---------------------------------------------------------------------------
extern "C" void kernel_launch(void* const* d_in, const int* in_sizes, int n_in,
                              void* d_out, int out_size)
{
    const int*   seq      = (const int*)  d_in[0];
    const float* emb      = (const float*)d_in[1];
    const float* W_ih     = (const float*)d_in[2];
    const float* W_hh     = (const float*)d_in[3];
    const float* b_ih     = (const float*)d_in[4];
    const float* b_hh     = (const float*)d_in[5];
    const float* wCo_w    = (const float*)d_in[6];
    const float* wCo_b    = (const float*)d_in[7];
    const float* Wmy_w    = (const float*)d_in[8];
    const float* Wmy_b    = (const float*)d_in[9];
    const float* logits_w = (const float*)d_in[10];
    const float* logits_b = (const float*)d_in[11];
    float* out = (float*)d_out;

    __nv_bfloat16 *ehi, *elo, *wih_hi, *wih_lo, *whh_hi, *whh_lo, *Hhi, *Hlo;
    float *bpih, *bphh, *VG;
    cudaGetSymbolAddress((void**)&ehi,    d_emb_hi);
    cudaGetSymbolAddress((void**)&elo,    d_emb_lo);
    cudaGetSymbolAddress((void**)&wih_hi, d_Wih_hi);
    cudaGetSymbolAddress((void**)&wih_lo, d_Wih_lo);
    cudaGetSymbolAddress((void**)&whh_hi, d_Whh_hi);
    cudaGetSymbolAddress((void**)&whh_lo, d_Whh_lo);
    cudaGetSymbolAddress((void**)&bpih,   d_bp_ih);
    cudaGetSymbolAddress((void**)&bphh,   d_bp_hh);
    cudaGetSymbolAddress((void**)&VG,     d_VG);
    cudaGetSymbolAddress((void**)&Hhi,    d_Hhi);
    cudaGetSymbolAddress((void**)&Hlo,    d_Hlo);

    cudaFuncSetAttribute(vg_gemm, cudaFuncAttributeMaxDynamicSharedMemorySize, SMEM_VG);
    cudaFuncSetAttribute(gru_persist, cudaFuncAttributeMaxDynamicSharedMemorySize, SMEM_STEP);
    const int POST_SMEM = (Lv * Hv + 3 * Hv + 7 * 80 + 2 * Hv) * (int)sizeof(float);
    cudaFuncSetAttribute(post_kernel, cudaFuncAttributeMaxDynamicSharedMemorySize, POST_SMEM);

    // Persistent only if all 320 blocks provably co-resident.
    int occ = 0, sms = 0;
    cudaOccupancyMaxActiveBlocksPerMultiprocessor(&occ, gru_persist, 256, SMEM_STEP);
    cudaDeviceGetAttribute(&sms, cudaDevAttrMultiProcessorCount, 0);
    bool persistent = ((long)occ * sms >= NTILE * MTILE);

    // 0) conversions
    {
        long n = (long)VOCAB * Ev;
        conv_emb<<<(unsigned)((n + 255) / 256), 256>>>(emb, ehi, elo);
    }
    conv_w<<<G3, 128>>>(W_ih, b_ih, wih_hi, wih_lo, bpih);
    conv_w<<<G3, 128>>>(W_hh, b_hh, whh_hi, whh_lo, bphh);

    // 1) VG = emb @ W_ih^T + b_ih + rz(b_hh) over full vocab
    {
        dim3 grid(10, VROWS / 128);
        vg_gemm<<<grid, 256, SMEM_VG>>>(ehi, elo, wih_hi, wih_lo, bpih, bphh, VG);
    }

    // 2) GRU recurrence
    dim3 grid(NTILE, MTILE);
    if (persistent) {
        gru_persist<<<grid, 256, SMEM_STEP>>>(Hhi, Hlo, whh_hi, whh_lo,
                                              seq, VG, bphh, 0, Lv, 1);
    } else {
        for (int l = 0; l < Lv; l++)
            gru_persist<<<grid, 256, SMEM_STEP>>>(Hhi, Hlo, whh_hi, whh_lo,
                                                  seq, VG, bphh, l, l + 1, 0);
    }

    // 3) collapsed co-attention + softmax + pooling + logits
    post_kernel<<<Bv, 256, POST_SMEM>>>(Hhi, Hlo, wCo_w, wCo_b, Wmy_w, Wmy_b,
                                        logits_w, logits_b, out);
}

// round 14
// speedup vs baseline: 1.6611x; 1.0176x over previous
#include <cuda_runtime.h>
#include <cuda_bf16.h>
#include <cuda_fp16.h>
#include <math.h>
#include <stdint.h>

#define Bv   2048
#define Lv   75
#define Ev   300
#define Hv   300
#define G3   900
#define G3P  912                 // VG row stride in halves (16B-aligned: 912*2=1824)
#define OUTv 5
#define KP   320                 // K padded to 10 x 32
#define VROWS 50048              // vocab rows padded to 391*128
#define NROWS 960                // gate rows padded to 10*96
#define VOCAB 50000
#define NTILE 10                 // n-blocks per step
#define MTILE 32                 // m-blocks per step

// ---------------- scratch (device globals; zero-initialized) ---------------
__device__ __nv_bfloat16 d_emb_hi[(size_t)VROWS * KP];
__device__ __nv_bfloat16 d_emb_lo[(size_t)VROWS * KP];
__device__ __nv_bfloat16 d_Wih_hi[NROWS * KP];
__device__ __nv_bfloat16 d_Wih_lo[NROWS * KP];
__device__ __nv_bfloat16 d_Whh_hi[NROWS * KP];
__device__ __nv_bfloat16 d_Whh_lo[NROWS * KP];
__device__ float d_bp_ih[G3];
__device__ float d_bp_hh[G3];
__device__ __half d_VG[(size_t)VROWS * G3P];                 // vocab gates, fp16, padded stride
__device__ __nv_bfloat16 d_Hhi[(size_t)(Lv + 1) * Bv * KP];  // slice 0 = zeros
__device__ __nv_bfloat16 d_Hlo[(size_t)(Lv + 1) * Bv * KP];
__device__ unsigned int d_flag[Lv][MTILE];                   // producers of slice s+1
__device__ unsigned int d_done[MTILE];

// ---------------------------- helpers ---------------------------------------
__device__ __forceinline__ uint32_t smem_u32(const void* p) {
    uint32_t a;
    asm("{ .reg .u64 t; cvta.to.shared.u64 t, %1; cvt.u32.u64 %0, t; }" : "=r"(a) : "l"(p));
    return a;
}
__device__ __forceinline__ void ldsm_x4(uint32_t* r, uint32_t addr) {
    asm volatile("ldmatrix.sync.aligned.m8n8.x4.shared.b16 {%0,%1,%2,%3}, [%4];"
                 : "=r"(r[0]), "=r"(r[1]), "=r"(r[2]), "=r"(r[3]) : "r"(addr));
}
__device__ __forceinline__ void ldsm_x2(uint32_t* r, uint32_t addr) {
    asm volatile("ldmatrix.sync.aligned.m8n8.x2.shared.b16 {%0,%1}, [%2];"
                 : "=r"(r[0]), "=r"(r[1]) : "r"(addr));
}
__device__ __forceinline__ void mma_bf16(float* c, const uint32_t* a, const uint32_t* b) {
    asm volatile(
        "mma.sync.aligned.m16n8k16.row.col.f32.bf16.bf16.f32 "
        "{%0,%1,%2,%3}, {%4,%5,%6,%7}, {%8,%9}, {%0,%1,%2,%3};"
        : "+f"(c[0]), "+f"(c[1]), "+f"(c[2]), "+f"(c[3])
        : "r"(a[0]), "r"(a[1]), "r"(a[2]), "r"(a[3]), "r"(b[0]), "r"(b[1]));
}
__device__ __forceinline__ void cp16(uint32_t dst, const void* src) {
    asm volatile("cp.async.cg.shared.global [%0], [%1], 16;" :: "r"(dst), "l"(src));
}
#define CP_COMMIT() asm volatile("cp.async.commit_group;" ::: "memory")
#define CP_WAIT0()  asm volatile("cp.async.wait_group 0;" ::: "memory")

__device__ __forceinline__ unsigned int ld_acq(const unsigned int* p) {
    unsigned int v;
    asm volatile("ld.global.acquire.gpu.u32 %0, [%1];" : "=r"(v) : "l"(p) : "memory");
    return v;
}
__device__ __forceinline__ void red_rel_add1(unsigned int* p) {
    asm volatile("red.release.gpu.global.add.u32 [%0], 1;" :: "l"(p) : "memory");
}
// fast clamped sigmoid/tanh (MUFU-based)
__device__ __forceinline__ float fsig(float x) {
    x = fminf(fmaxf(x, -30.f), 30.f);
    return __fdividef(1.f, 1.f + __expf(-x));
}
__device__ __forceinline__ float ftanh(float x) {
    x = fminf(fmaxf(x, -15.f), 15.f);
    float e = __expf(2.f * x);
    return __fdividef(e - 1.f, e + 1.f);
}

// ---------------------------- conversion kernels ---------------------------
__global__ void conv_emb(const float* __restrict__ emb,
                         __nv_bfloat16* __restrict__ hi, __nv_bfloat16* __restrict__ lo)
{
    long i = (long)blockIdx.x * blockDim.x + threadIdx.x;
    if (i >= (long)VOCAB * Ev) return;
    int row = (int)(i / Ev), col = (int)(i - (long)row * Ev);
    float x = emb[i];
    __nv_bfloat16 h = __float2bfloat16(x);
    hi[(size_t)row * KP + col] = h;
    lo[(size_t)row * KP + col] = __float2bfloat16(x - __bfloat162float(h));
}

__global__ void conv_w(const float* __restrict__ W, const float* __restrict__ b,
                       __nv_bfloat16* __restrict__ hi, __nv_bfloat16* __restrict__ lo,
                       float* __restrict__ bp)
{
    int n = blockIdx.x;            // 0..899, target row = 3j+g
    int j = n / 3, g = n % 3;
    const float* src = W + (size_t)(g * Hv + j) * 300;
    for (int k = threadIdx.x; k < 300; k += blockDim.x) {
        float x = src[k];
        __nv_bfloat16 h = __float2bfloat16(x);
        hi[(size_t)n * KP + k] = h;
        lo[(size_t)n * KP + k] = __float2bfloat16(x - __bfloat162float(h));
    }
    if (threadIdx.x == 0) bp[n] = b[g * Hv + j];
}

// ---------------------------------------------------------------------------
// VG GEMM: VG(fp16) = emb @ W_ih^T + b_ih + rz(b_hh). Superchunk 4-plane
// pipeline, 2 stages, one sync per chunk. Block 128x96, warp tile 64x24.
// ---------------------------------------------------------------------------
#define V_A_HI(s) ((s) * 17920 + 0)
#define V_A_LO(s) ((s) * 17920 + 5120)
#define V_B_HI(s) ((s) * 17920 + 10240)
#define V_B_LO(s) ((s) * 17920 + 14080)
#define GH_STRIDE 100
#define SMEM_VG (2 * 17920 * 2)

__global__ void __launch_bounds__(256)
vg_gemm(const __nv_bfloat16* __restrict__ Ahi, const __nv_bfloat16* __restrict__ Alo,
        const __nv_bfloat16* __restrict__ Bhi, const __nv_bfloat16* __restrict__ Blo,
        const float* __restrict__ bias1, const float* __restrict__ bias2,
        __half* __restrict__ VGout)
{
    extern __shared__ __align__(16) char smem[];
    float* ghs = (float*)smem;
    const uint32_t sbase = smem_u32(smem);

    int tid = threadIdx.x;
    int lane = tid & 31, wid = tid >> 5;
    int wm = wid >> 2, wn = wid & 3;
    int m0 = blockIdx.y * 128;
    int n0 = blockIdx.x * 96;

    int a_row = lane & 15, a_k = (lane >> 4) << 3;
    int b_row = lane & 7,  b_k = ((lane >> 3) & 1) << 3;

    auto load_chunk = [&](int cc, int s) {
        int kb = cc * 32;
        int r1 = tid >> 2, co = (tid & 3) * 8;
        int r2 = 64 + r1;
        cp16(sbase + (uint32_t)(V_A_HI(s) + r1 * 40 + co) * 2, Ahi + (size_t)(m0 + r1) * KP + kb + co);
        cp16(sbase + (uint32_t)(V_A_HI(s) + r2 * 40 + co) * 2, Ahi + (size_t)(m0 + r2) * KP + kb + co);
        cp16(sbase + (uint32_t)(V_A_LO(s) + r1 * 40 + co) * 2, Alo + (size_t)(m0 + r1) * KP + kb + co);
        cp16(sbase + (uint32_t)(V_A_LO(s) + r2 * 40 + co) * 2, Alo + (size_t)(m0 + r2) * KP + kb + co);
        cp16(sbase + (uint32_t)(V_B_HI(s) + r1 * 40 + co) * 2, Bhi + (size_t)(n0 + r1) * KP + kb + co);
        cp16(sbase + (uint32_t)(V_B_LO(s) + r1 * 40 + co) * 2, Blo + (size_t)(n0 + r1) * KP + kb + co);
        if (tid < 128) {
            int r3 = 64 + r1;
            cp16(sbase + (uint32_t)(V_B_HI(s) + r3 * 40 + co) * 2, Bhi + (size_t)(n0 + r3) * KP + kb + co);
            cp16(sbase + (uint32_t)(V_B_LO(s) + r3 * 40 + co) * 2, Blo + (size_t)(n0 + r3) * KP + kb + co);
        }
        CP_COMMIT();
    };

    float acc[4][3][4];
#pragma unroll
    for (int mi = 0; mi < 4; mi++)
#pragma unroll
        for (int ni = 0; ni < 3; ni++)
#pragma unroll
            for (int q = 0; q < 4; q++) acc[mi][ni][q] = 0.f;

    load_chunk(0, 0);

    for (int c = 0; c < 10; c++) {
        CP_WAIT0();
        __syncthreads();
        if (c < 9) load_chunk(c + 1, (c + 1) & 1);
        int s = c & 1;
        uint32_t ah = sbase + (uint32_t)V_A_HI(s) * 2;
        uint32_t al = sbase + (uint32_t)V_A_LO(s) * 2;
        uint32_t bh = sbase + (uint32_t)V_B_HI(s) * 2;
        uint32_t bl = sbase + (uint32_t)V_B_LO(s) * 2;
#pragma unroll
        for (int kk = 0; kk < 2; kk++) {
            uint32_t fah[4][4], fal[4][4], fbh[3][2], fbl[3][2];
#pragma unroll
            for (int mi = 0; mi < 4; mi++) {
                uint32_t ro = (uint32_t)((wm * 64 + mi * 16 + a_row) * 40 + kk * 16 + a_k) * 2;
                ldsm_x4(fah[mi], ah + ro);
                ldsm_x4(fal[mi], al + ro);
            }
#pragma unroll
            for (int ni = 0; ni < 3; ni++) {
                uint32_t ro = (uint32_t)((wn * 24 + ni * 8 + b_row) * 40 + kk * 16 + b_k) * 2;
                ldsm_x2(fbh[ni], bh + ro);
                ldsm_x2(fbl[ni], bl + ro);
            }
#pragma unroll
            for (int mi = 0; mi < 4; mi++)
#pragma unroll
                for (int ni = 0; ni < 3; ni++)
                    mma_bf16(acc[mi][ni], fah[mi], fbh[ni]);
#pragma unroll
            for (int mi = 0; mi < 4; mi++)
#pragma unroll
                for (int ni = 0; ni < 3; ni++)
                    mma_bf16(acc[mi][ni], fal[mi], fbh[ni]);
#pragma unroll
            for (int mi = 0; mi < 4; mi++)
#pragma unroll
                for (int ni = 0; ni < 3; ni++)
                    mma_bf16(acc[mi][ni], fah[mi], fbl[ni]);
        }
    }
    __syncthreads();   // ghs overlaps stage 1 — drain compute

#pragma unroll
    for (int mi = 0; mi < 4; mi++) {
        int mr = wm * 64 + mi * 16 + (lane >> 2);
#pragma unroll
        for (int ni = 0; ni < 3; ni++) {
            int nn = wn * 24 + ni * 8 + (lane & 3) * 2;
            ghs[mr * GH_STRIDE + nn]           = acc[mi][ni][0];
            ghs[mr * GH_STRIDE + nn + 1]       = acc[mi][ni][1];
            ghs[(mr + 8) * GH_STRIDE + nn]     = acc[mi][ni][2];
            ghs[(mr + 8) * GH_STRIDE + nn + 1] = acc[mi][ni][3];
        }
    }
    __syncthreads();

    for (int i = tid; i < 128 * 96; i += 256) {
        int m = i / 96, n = i - m * 96;
        int gn = n0 + n;
        if (gn < G3) {
            float b2 = (gn % 3 != 2) ? bias2[gn] : 0.f;   // fold b_hh for r,z only
            VGout[(size_t)(m0 + m) * G3P + gn] =
                __float2half(ghs[m * GH_STRIDE + n] + bias1[gn] + b2);
        }
    }
}

// ---------------------------------------------------------------------------
// GRU steps, persistent: 320 blocks (10n x 32m), tile 64x96, 8 warps,
// warp tile 32x24, 2 stages, one sync per chunk. Coarse per-m flags.
// gx gathered from fp16 VG (padded stride) into smem as halves.
// smem: stages [0,51200), gx fp16 [51200,63488), bhn [63488,63616).
// ---------------------------------------------------------------------------
#define S_A_HI(s) ((s) * 12800 + 0)
#define S_A_LO(s) ((s) * 12800 + 2560)
#define S_B_HI(s) ((s) * 12800 + 5120)
#define S_B_LO(s) ((s) * 12800 + 8960)
#define GXS_B 51200
#define BHN_B 63488
#define SMEM_STEP 63616

__global__ void __launch_bounds__(256, 3)
gru_persist(const __nv_bfloat16* __restrict__ Hhi_all, const __nv_bfloat16* __restrict__ Hlo_all,
            const __nv_bfloat16* __restrict__ Bhi, const __nv_bfloat16* __restrict__ Blo,
            const int* __restrict__ seq, const __half* __restrict__ VGin,
            const float* __restrict__ bph,
            int s_begin, int s_end, int use_flags)
{
    extern __shared__ __align__(16) char smem[];
    float* cs  = (float*)smem;                    // epilogue C, aliases stage 0
    __half* gxs = (__half*)(smem + GXS_B);
    float* bhn = (float*)(smem + BHN_B);
    const uint32_t sbase = smem_u32(smem);

    int tid = threadIdx.x;
    int lane = tid & 31, wid = tid >> 5;
    int wm = wid >> 2, wn = wid & 3;
    int bn = blockIdx.x;                          // 0..9
    int bm = blockIdx.y;                          // 0..31
    int m0 = bm * 64;
    int n0 = bn * 96;
    int j0 = bn * 32;

    if (tid < 32 && (n0 + 3 * tid + 2) < G3) bhn[tid] = bph[n0 + 3 * tid + 2];

    int a_row = lane & 15, a_k = (lane >> 4) << 3;
    int b_row = lane & 7,  b_k = ((lane >> 3) & 1) << 3;
    const size_t slice = (size_t)Bv * KP;

    for (int s = s_begin; s < s_end; s++) {
        const __nv_bfloat16* Hp_hi = Hhi_all + (size_t)s * slice;
        const __nv_bfloat16* Hp_lo = Hlo_all + (size_t)s * slice;
        __nv_bfloat16* Ho_hi = (__nv_bfloat16*)(Hhi_all + (size_t)(s + 1) * slice);
        __nv_bfloat16* Ho_lo = (__nv_bfloat16*)(Hlo_all + (size_t)(s + 1) * slice);

        // ---- gx gather (fp16, 16B copies; stride G3P keeps alignment) ----
#pragma unroll
        for (int c = 0; c < 3; c++) {
            int idx = tid + c * 256;           // 0..767
            int row = idx / 12, off = (idx % 12) * 8;   // halves
            int t = seq[(m0 + row) * Lv + s];
            cp16(sbase + GXS_B + (uint32_t)(row * 96 + off) * 2,
                 VGin + (size_t)t * G3P + n0 + off);
        }
        CP_COMMIT();

        // ---- wait for the 10 producers of slice s ----
        if (use_flags && s > 0) {
            if (tid == 0) {
                while (ld_acq(&d_flag[s - 1][bm]) < (unsigned)NTILE) __nanosleep(64);
            }
        }
        __syncthreads();

        auto load_chunk = [&](int cc, int st) {
            int kb = cc * 32;
            int r1 = tid >> 2, co = (tid & 3) * 8;
            cp16(sbase + (uint32_t)(S_A_HI(st) + r1 * 40 + co) * 2, Hp_hi + (size_t)(m0 + r1) * KP + kb + co);
            cp16(sbase + (uint32_t)(S_A_LO(st) + r1 * 40 + co) * 2, Hp_lo + (size_t)(m0 + r1) * KP + kb + co);
            cp16(sbase + (uint32_t)(S_B_HI(st) + r1 * 40 + co) * 2, Bhi + (size_t)(n0 + r1) * KP + kb + co);
            cp16(sbase + (uint32_t)(S_B_LO(st) + r1 * 40 + co) * 2, Blo + (size_t)(n0 + r1) * KP + kb + co);
            if (tid < 128) {
                int r2 = 64 + r1;
                cp16(sbase + (uint32_t)(S_B_HI(st) + r2 * 40 + co) * 2, Bhi + (size_t)(n0 + r2) * KP + kb + co);
                cp16(sbase + (uint32_t)(S_B_LO(st) + r2 * 40 + co) * 2, Blo + (size_t)(n0 + r2) * KP + kb + co);
            }
            CP_COMMIT();
        };

        float acc[2][3][4];
#pragma unroll
        for (int mi = 0; mi < 2; mi++)
#pragma unroll
            for (int ni = 0; ni < 3; ni++)
#pragma unroll
                for (int q = 0; q < 4; q++) acc[mi][ni][q] = 0.f;

        load_chunk(0, 0);

        for (int c = 0; c < 10; c++) {
            CP_WAIT0();
            __syncthreads();
            if (c < 9) load_chunk(c + 1, (c + 1) & 1);
            int st = c & 1;
            uint32_t ah = sbase + (uint32_t)S_A_HI(st) * 2;
            uint32_t al = sbase + (uint32_t)S_A_LO(st) * 2;
            uint32_t bh = sbase + (uint32_t)S_B_HI(st) * 2;
            uint32_t bl = sbase + (uint32_t)S_B_LO(st) * 2;
#pragma unroll
            for (int kk = 0; kk < 2; kk++) {
                uint32_t fah[2][4], fal[2][4], fbh[3][2], fbl[3][2];
#pragma unroll
                for (int mi = 0; mi < 2; mi++) {
                    uint32_t ro = (uint32_t)((wm * 32 + mi * 16 + a_row) * 40 + kk * 16 + a_k) * 2;
                    ldsm_x4(fah[mi], ah + ro);
                    ldsm_x4(fal[mi], al + ro);
                }
#pragma unroll
                for (int ni = 0; ni < 3; ni++) {
                    uint32_t ro = (uint32_t)((wn * 24 + ni * 8 + b_row) * 40 + kk * 16 + b_k) * 2;
                    ldsm_x2(fbh[ni], bh + ro);
                    ldsm_x2(fbl[ni], bl + ro);
                }
#pragma unroll
                for (int mi = 0; mi < 2; mi++)
#pragma unroll
                    for (int ni = 0; ni < 3; ni++)
                        mma_bf16(acc[mi][ni], fah[mi], fbh[ni]);
#pragma unroll
                for (int mi = 0; mi < 2; mi++)
#pragma unroll
                    for (int ni = 0; ni < 3; ni++)
                        mma_bf16(acc[mi][ni], fal[mi], fbh[ni]);
#pragma unroll
                for (int mi = 0; mi < 2; mi++)
#pragma unroll
                    for (int ni = 0; ni < 3; ni++)
                        mma_bf16(acc[mi][ni], fah[mi], fbl[ni]);
            }
        }

        // ---- dump C to smem stage 0 (chunk 9 used stage 1 -> no pre-sync) ----
#pragma unroll
        for (int mi = 0; mi < 2; mi++) {
            int mr = wm * 32 + mi * 16 + (lane >> 2);
#pragma unroll
            for (int ni = 0; ni < 3; ni++) {
                int nn = wn * 24 + ni * 8 + (lane & 3) * 2;
                cs[mr * GH_STRIDE + nn]           = acc[mi][ni][0];
                cs[mr * GH_STRIDE + nn + 1]       = acc[mi][ni][1];
                cs[(mr + 8) * GH_STRIDE + nn]     = acc[mi][ni][2];
                cs[(mr + 8) * GH_STRIDE + nn + 1] = acc[mi][ni][3];
            }
        }
        __syncthreads();

        // ---- gate epilogue ----
        for (int i = tid; i < 64 * 32; i += 256) {
            int ml = i >> 5, p = i & 31;
            int j = j0 + p;
            if (j < Hv) {
                int m = m0 + ml;
                float gh_r = cs[ml * GH_STRIDE + 3 * p + 0];
                float gh_z = cs[ml * GH_STRIDE + 3 * p + 1];
                float gh_n = cs[ml * GH_STRIDE + 3 * p + 2] + bhn[p];  // b_hh_n inside r*(.)
                float gx_r = __half2float(gxs[ml * 96 + 3 * p + 0]);
                float gx_z = __half2float(gxs[ml * 96 + 3 * p + 1]);
                float gx_n = __half2float(gxs[ml * 96 + 3 * p + 2]);
                float r = fsig(gx_r + gh_r);
                float z = fsig(gx_z + gh_z);
                float ng = ftanh(gx_n + r * gh_n);
                size_t hidx = (size_t)m * KP + j;
                float hp = __bfloat162float(Hp_hi[hidx]) + __bfloat162float(Hp_lo[hidx]);
                float h = (1.f - z) * ng + z * hp;
                __nv_bfloat16 hh = __float2bfloat16(h);
                Ho_hi[hidx] = hh;
                Ho_lo[hidx] = __float2bfloat16(h - __bfloat162float(hh));
            }
        }

        if (use_flags) {
            __threadfence();
            __syncthreads();
            if (tid == 0) red_rel_add1(&d_flag[s][bm]);
        } else {
            __syncthreads();
        }
    }

    // ---- reset phase (persistent mode only): make counters replay-safe ----
    if (use_flags) {
        if (tid == 0) red_rel_add1(&d_done[bm]);
        if (bn == 0) {
            if (tid == 0) {
                while (ld_acq(&d_done[bm]) < (unsigned)NTILE) __nanosleep(64);
            }
            __syncthreads();
            for (int s = tid; s < Lv; s += 256) d_flag[s][bm] = 0;
            if (tid == 0) d_done[bm] = 0;
            __threadfence();
        }
    }
}

// ---------------------------------------------------------------------------
// Post: collapsed co-attention + softmax + pooling + logits. Vectorized h load.
// ---------------------------------------------------------------------------
__device__ __forceinline__ float blockReduceSum(float v, volatile float* red)
{
    __syncthreads();
#pragma unroll
    for (int o = 16; o > 0; o >>= 1) v += __shfl_xor_sync(0xffffffffu, v, o);
    int w = threadIdx.x >> 5, ln = threadIdx.x & 31;
    if (ln == 0) red[w] = v;
    __syncthreads();
    if (threadIdx.x < 32) {
        float x = (threadIdx.x < 8) ? red[threadIdx.x] : 0.f;
#pragma unroll
        for (int o = 4; o > 0; o >>= 1) x += __shfl_xor_sync(0xffffffffu, x, o);
        if (threadIdx.x == 0) red[0] = x;
    }
    __syncthreads();
    return red[0];
}
__device__ __forceinline__ float blockReduceMax(float v, volatile float* red)
{
    __syncthreads();
#pragma unroll
    for (int o = 16; o > 0; o >>= 1) v = fmaxf(v, __shfl_xor_sync(0xffffffffu, v, o));
    int w = threadIdx.x >> 5, ln = threadIdx.x & 31;
    if (ln == 0) red[w] = v;
    __syncthreads();
    if (threadIdx.x < 32) {
        float x = (threadIdx.x < 8) ? red[threadIdx.x] : -3.4e38f;
#pragma unroll
        for (int o = 4; o > 0; o >>= 1) x = fmaxf(x, __shfl_xor_sync(0xffffffffu, x, o));
        if (threadIdx.x == 0) red[0] = x;
    }
    __syncthreads();
    return red[0];
}

__global__ void post_kernel(const __nv_bfloat16* __restrict__ Hhi,
                            const __nv_bfloat16* __restrict__ Hlo,
                            const float* __restrict__ wCo_w, const float* __restrict__ wCo_b,
                            const float* __restrict__ Wmy_w, const float* __restrict__ Wmy_b,
                            const float* __restrict__ logits_w, const float* __restrict__ logits_b,
                            float* __restrict__ out)
{
    extern __shared__ float fs[];
    float* h_s    = fs;
    float* wa     = h_s + Lv * Hv;
    float* wb_    = wa + Hv;
    float* wc     = wb_ + Hv;
    float* wmy    = wc + Hv;
    float* aa     = wmy + 80;
    float* bb     = aa + 80;
    float* qq     = bb + 80;
    float* pp     = qq + 80;
    float* smarr  = pp + 80;
    float* attn   = smarr + 80;
    float* u      = attn + 80;
    float* pooled = u + Hv;
    __shared__ float red[32];

    int b = blockIdx.x;
    int tid = threadIdx.x;
    int w = tid >> 5, ln = tid & 31;

    for (int t = tid; t < Lv * (Hv / 4); t += 256) {
        int i = t / (Hv / 4), d4 = (t - i * (Hv / 4)) * 4;
        size_t idx = (size_t)(i + 1) * Bv * KP + (size_t)b * KP + d4;
        uint2 vh = *(const uint2*)(Hhi + idx);
        uint2 vl = *(const uint2*)(Hlo + idx);
        const __nv_bfloat162* ph = (const __nv_bfloat162*)&vh;
        const __nv_bfloat162* pl = (const __nv_bfloat162*)&vl;
        float2 h0 = __bfloat1622float2(ph[0]);
        float2 l0 = __bfloat1622float2(pl[0]);
        float2 h1 = __bfloat1622float2(ph[1]);
        float2 l1 = __bfloat1622float2(pl[1]);
        float* dst = h_s + i * Hv + d4;
        dst[0] = h0.x + l0.x;
        dst[1] = h0.y + l0.y;
        dst[2] = h1.x + l1.x;
        dst[3] = h1.y + l1.y;
    }
    for (int t = tid; t < Hv; t += 256) {
        wa[t]  = wCo_w[t];
        wb_[t] = wCo_w[Hv + t];
        wc[t]  = wCo_w[2 * Hv + t];
    }
    if (tid < Lv) wmy[tid] = Wmy_w[tid];
    __syncthreads();

    for (int i = w; i < Lv; i += 8) {
        float sa = 0.f, sb2 = 0.f, sq = 0.f;
        for (int d = ln; d < Hv; d += 32) {
            float hv = h_s[i * Hv + d];
            sa += hv * wa[d];
            sb2 += hv * wb_[d];
            sq += hv * hv * wc[d];
        }
#pragma unroll
        for (int o = 16; o > 0; o >>= 1) {
            sa += __shfl_xor_sync(0xffffffffu, sa, o);
            sb2 += __shfl_xor_sync(0xffffffffu, sb2, o);
            sq += __shfl_xor_sync(0xffffffffu, sq, o);
        }
        if (ln == 0) { aa[i] = sa; bb[i] = sb2; qq[i] = sq; }
    }
    __syncthreads();

    for (int d = tid; d < Hv; d += 256) {
        float s = 0.f;
#pragma unroll 5
        for (int i = 0; i < Lv; i++) s += wmy[i] * h_s[i * Hv + d];
        u[d] = s;
    }

    float swv = (tid < Lv) ? wmy[tid] : 0.f;
    float Sw = blockReduceSum(swv, red);
    float tv = (tid < Lv) ? wmy[tid] * bb[tid] : 0.f;
    float T = blockReduceSum(tv, red);
    __syncthreads();

    for (int i = w; i < Lv; i += 8) {
        float sp = 0.f;
        for (int d = ln; d < Hv; d += 32) sp += h_s[i * Hv + d] * wc[d] * u[d];
#pragma unroll
        for (int o = 16; o > 0; o >>= 1) sp += __shfl_xor_sync(0xffffffffu, sp, o);
        if (ln == 0) pp[i] = sp;
    }
    __syncthreads();

    float beta = wCo_b[0];
    if (tid < Lv) {
        smarr[tid] = (aa[tid] + beta) * Sw + T + pp[tid]
                   - wmy[tid] * (aa[tid] + bb[tid] + beta + qq[tid]) + Wmy_b[0];
    }
    __syncthreads();

    float mv = (tid < Lv) ? smarr[tid] : -3.4e38f;
    float mx = blockReduceMax(mv, red);
    float ev = (tid < Lv) ? expf(smarr[tid] - mx) : 0.f;
    if (tid < Lv) attn[tid] = ev;
    float se = blockReduceSum(ev, red);
    if (tid < Lv) attn[tid] = attn[tid] / se;
    __syncthreads();

    for (int d = tid; d < Hv; d += 256) {
        float s = 0.f;
#pragma unroll 5
        for (int i = 0; i < Lv; i++) s += attn[i] * h_s[i * Hv + d];
        pooled[d] = s;
    }
    __syncthreads();

    if (w < OUTv) {
        float s = 0.f;
        for (int d = ln; d < Hv; d += 32) s += pooled[d] * logits_w[w * Hv + d];
#pragma unroll
        for (int o = 16; o > 0; o >>= 1) s += __shfl_xor_sync(0xffffffffu, s, o);
        if (ln == 0) out[(size_t)b * OUTv + w] = s + logits_b[w];
    }
}

// ---------------------------------------------------------------------------
extern "C" void kernel_launch(void* const* d_in, const int* in_sizes, int n_in,
                              void* d_out, int out_size)
{
    const int*   seq      = (const int*)  d_in[0];
    const float* emb      = (const float*)d_in[1];
    const float* W_ih     = (const float*)d_in[2];
    const float* W_hh     = (const float*)d_in[3];
    const float* b_ih     = (const float*)d_in[4];
    const float* b_hh     = (const float*)d_in[5];
    const float* wCo_w    = (const float*)d_in[6];
    const float* wCo_b    = (const float*)d_in[7];
    const float* Wmy_w    = (const float*)d_in[8];
    const float* Wmy_b    = (const float*)d_in[9];
    const float* logits_w = (const float*)d_in[10];
    const float* logits_b = (const float*)d_in[11];
    float* out = (float*)d_out;

    __nv_bfloat16 *ehi, *elo, *wih_hi, *wih_lo, *whh_hi, *whh_lo, *Hhi, *Hlo;
    float *bpih, *bphh;
    __half* VG;
    cudaGetSymbolAddress((void**)&ehi,    d_emb_hi);
    cudaGetSymbolAddress((void**)&elo,    d_emb_lo);
    cudaGetSymbolAddress((void**)&wih_hi, d_Wih_hi);
    cudaGetSymbolAddress((void**)&wih_lo, d_Wih_lo);
    cudaGetSymbolAddress((void**)&whh_hi, d_Whh_hi);
    cudaGetSymbolAddress((void**)&whh_lo, d_Whh_lo);
    cudaGetSymbolAddress((void**)&bpih,   d_bp_ih);
    cudaGetSymbolAddress((void**)&bphh,   d_bp_hh);
    cudaGetSymbolAddress((void**)&VG,     d_VG);
    cudaGetSymbolAddress((void**)&Hhi,    d_Hhi);
    cudaGetSymbolAddress((void**)&Hlo,    d_Hlo);

    cudaFuncSetAttribute(vg_gemm, cudaFuncAttributeMaxDynamicSharedMemorySize, SMEM_VG);
    cudaFuncSetAttribute(gru_persist, cudaFuncAttributeMaxDynamicSharedMemorySize, SMEM_STEP);
    const int POST_SMEM = (Lv * Hv + 3 * Hv + 7 * 80 + 2 * Hv) * (int)sizeof(float);
    cudaFuncSetAttribute(post_kernel, cudaFuncAttributeMaxDynamicSharedMemorySize, POST_SMEM);

    // Persistent only if all 320 blocks provably co-resident.
    int occ = 0, sms = 0;
    cudaOccupancyMaxActiveBlocksPerMultiprocessor(&occ, gru_persist, 256, SMEM_STEP);
    cudaDeviceGetAttribute(&sms, cudaDevAttrMultiProcessorCount, 0);
    bool persistent = ((long)occ * sms >= NTILE * MTILE);

    // 0) conversions
    {
        long n = (long)VOCAB * Ev;
        conv_emb<<<(unsigned)((n + 255) / 256), 256>>>(emb, ehi, elo);
    }
    conv_w<<<G3, 128>>>(W_ih, b_ih, wih_hi, wih_lo, bpih);
    conv_w<<<G3, 128>>>(W_hh, b_hh, whh_hi, whh_lo, bphh);

    // 1) VG(fp16) = emb @ W_ih^T + b_ih + rz(b_hh) over full vocab
    {
        dim3 grid(10, VROWS / 128);
        vg_gemm<<<grid, 256, SMEM_VG>>>(ehi, elo, wih_hi, wih_lo, bpih, bphh, VG);
    }

    // 2) GRU recurrence
    dim3 grid(NTILE, MTILE);
    if (persistent) {
        gru_persist<<<grid, 256, SMEM_STEP>>>(Hhi, Hlo, whh_hi, whh_lo,
                                              seq, VG, bphh, 0, Lv, 1);
    } else {
        for (int l = 0; l < Lv; l++)
            gru_persist<<<grid, 256, SMEM_STEP>>>(Hhi, Hlo, whh_hi, whh_lo,
                                                  seq, VG, bphh, l, l + 1, 0);
    }

    // 3) collapsed co-attention + softmax + pooling + logits
    post_kernel<<<Bv, 256, POST_SMEM>>>(Hhi, Hlo, wCo_w, wCo_b, Wmy_w, Wmy_b,
                                        logits_w, logits_b, out);
}

// round 15
// speedup vs baseline: 2.0780x; 1.2510x over previous
#include <cuda_runtime.h>
#include <cuda_bf16.h>
#include <cuda_fp16.h>
#include <math.h>
#include <stdint.h>

#define Bv   2048
#define Lv   75
#define Ev   300
#define Hv   300
#define G3   900
#define G3P  912                 // VG row stride in halves (16B-aligned)
#define OUTv 5
#define KP   320                 // K padded to 10 x 32
#define VROWS 50048              // vocab rows padded to 391*128
#define NROWS 960                // gate rows padded to 10*96
#define VOCAB 50000
#define NTILE 10                 // n-blocks per step
#define MTILE 32                 // m-blocks per step

// ---------------- scratch (device globals; zero-initialized) ---------------
__device__ __nv_bfloat16 d_emb_hi[(size_t)VROWS * KP];
__device__ __nv_bfloat16 d_emb_lo[(size_t)VROWS * KP];
__device__ __nv_bfloat16 d_Wih_hi[NROWS * KP];
__device__ __nv_bfloat16 d_Whh_hi[NROWS * KP];
__device__ float d_bp_ih[G3];
__device__ float d_bp_hh[G3];
__device__ __half d_VG[(size_t)VROWS * G3P];                 // vocab gates, fp16
__device__ __nv_bfloat16 d_Hhi[(size_t)(Lv + 1) * Bv * KP];  // slice 0 = zeros
__device__ __nv_bfloat16 d_Hlo[(size_t)(Lv + 1) * Bv * KP];
__device__ unsigned int d_flag[Lv][MTILE];                   // producers of slice s+1
__device__ unsigned int d_done[MTILE];

// ---------------------------- helpers ---------------------------------------
__device__ __forceinline__ uint32_t smem_u32(const void* p) {
    uint32_t a;
    asm("{ .reg .u64 t; cvta.to.shared.u64 t, %1; cvt.u32.u64 %0, t; }" : "=r"(a) : "l"(p));
    return a;
}
__device__ __forceinline__ void ldsm_x4(uint32_t* r, uint32_t addr) {
    asm volatile("ldmatrix.sync.aligned.m8n8.x4.shared.b16 {%0,%1,%2,%3}, [%4];"
                 : "=r"(r[0]), "=r"(r[1]), "=r"(r[2]), "=r"(r[3]) : "r"(addr));
}
__device__ __forceinline__ void ldsm_x2(uint32_t* r, uint32_t addr) {
    asm volatile("ldmatrix.sync.aligned.m8n8.x2.shared.b16 {%0,%1}, [%2];"
                 : "=r"(r[0]), "=r"(r[1]) : "r"(addr));
}
__device__ __forceinline__ void mma_bf16(float* c, const uint32_t* a, const uint32_t* b) {
    asm volatile(
        "mma.sync.aligned.m16n8k16.row.col.f32.bf16.bf16.f32 "
        "{%0,%1,%2,%3}, {%4,%5,%6,%7}, {%8,%9}, {%0,%1,%2,%3};"
        : "+f"(c[0]), "+f"(c[1]), "+f"(c[2]), "+f"(c[3])
        : "r"(a[0]), "r"(a[1]), "r"(a[2]), "r"(a[3]), "r"(b[0]), "r"(b[1]));
}
__device__ __forceinline__ void cp16(uint32_t dst, const void* src) {
    asm volatile("cp.async.cg.shared.global [%0], [%1], 16;" :: "r"(dst), "l"(src));
}
#define CP_COMMIT() asm volatile("cp.async.commit_group;" ::: "memory")
#define CP_WAIT0()  asm volatile("cp.async.wait_group 0;" ::: "memory")

__device__ __forceinline__ unsigned int ld_acq(const unsigned int* p) {
    unsigned int v;
    asm volatile("ld.global.acquire.gpu.u32 %0, [%1];" : "=r"(v) : "l"(p) : "memory");
    return v;
}
__device__ __forceinline__ void red_rel_add1(unsigned int* p) {
    asm volatile("red.release.gpu.global.add.u32 [%0], 1;" :: "l"(p) : "memory");
}
__device__ __forceinline__ float fsig(float x) {
    x = fminf(fmaxf(x, -30.f), 30.f);
    return __fdividef(1.f, 1.f + __expf(-x));
}
__device__ __forceinline__ float ftanh(float x) {
    x = fminf(fmaxf(x, -15.f), 15.f);
    float e = __expf(2.f * x);
    return __fdividef(e - 1.f, e + 1.f);
}

// ---------------------------- conversion kernels ---------------------------
__global__ void conv_emb(const float* __restrict__ emb,
                         __nv_bfloat16* __restrict__ hi, __nv_bfloat16* __restrict__ lo)
{
    long i = (long)blockIdx.x * blockDim.x + threadIdx.x;
    if (i >= (long)VOCAB * Ev) return;
    int row = (int)(i / Ev), col = (int)(i - (long)row * Ev);
    float x = emb[i];
    __nv_bfloat16 h = __float2bfloat16(x);
    hi[(size_t)row * KP + col] = h;
    lo[(size_t)row * KP + col] = __float2bfloat16(x - __bfloat162float(h));
}

// permute rows (g*H+j) -> (3j+g); W stored bf16 hi only (lo term dropped).
__global__ void conv_w(const float* __restrict__ W, const float* __restrict__ b,
                       __nv_bfloat16* __restrict__ hi, float* __restrict__ bp)
{
    int n = blockIdx.x;            // 0..899
    int j = n / 3, g = n % 3;
    const float* src = W + (size_t)(g * Hv + j) * 300;
    for (int k = threadIdx.x; k < 300; k += blockDim.x)
        hi[(size_t)n * KP + k] = __float2bfloat16(src[k]);
    if (threadIdx.x == 0) bp[n] = b[g * Hv + j];
}

// ---------------------------------------------------------------------------
// VG GEMM: VG(fp16) = (emb_hi+emb_lo) @ W_ih_hi^T + biases. 2-term split.
// Block 128x96, warp tile 64x24, 2 stages, one sync per chunk.
// Stage (bf16 units): A_hi 5120, A_lo 5120, B_hi 3840 -> 14080 (28160 B).
// ---------------------------------------------------------------------------
#define V_A_HI(s) ((s) * 14080 + 0)
#define V_A_LO(s) ((s) * 14080 + 5120)
#define V_B_HI(s) ((s) * 14080 + 10240)
#define GH_STRIDE 100
#define SMEM_VG (2 * 14080 * 2)

__global__ void __launch_bounds__(256)
vg_gemm(const __nv_bfloat16* __restrict__ Ahi, const __nv_bfloat16* __restrict__ Alo,
        const __nv_bfloat16* __restrict__ Bhi,
        const float* __restrict__ bias1, const float* __restrict__ bias2,
        __half* __restrict__ VGout)
{
    extern __shared__ __align__(16) char smem[];
    float* ghs = (float*)smem;
    const uint32_t sbase = smem_u32(smem);

    int tid = threadIdx.x;
    int lane = tid & 31, wid = tid >> 5;
    int wm = wid >> 2, wn = wid & 3;
    int m0 = blockIdx.y * 128;
    int n0 = blockIdx.x * 96;

    int a_row = lane & 15, a_k = (lane >> 4) << 3;
    int b_row = lane & 7,  b_k = ((lane >> 3) & 1) << 3;

    auto load_chunk = [&](int cc, int s) {
        int kb = cc * 32;
        int r1 = tid >> 2, co = (tid & 3) * 8;
        int r2 = 64 + r1;
        cp16(sbase + (uint32_t)(V_A_HI(s) + r1 * 40 + co) * 2, Ahi + (size_t)(m0 + r1) * KP + kb + co);
        cp16(sbase + (uint32_t)(V_A_HI(s) + r2 * 40 + co) * 2, Ahi + (size_t)(m0 + r2) * KP + kb + co);
        cp16(sbase + (uint32_t)(V_A_LO(s) + r1 * 40 + co) * 2, Alo + (size_t)(m0 + r1) * KP + kb + co);
        cp16(sbase + (uint32_t)(V_A_LO(s) + r2 * 40 + co) * 2, Alo + (size_t)(m0 + r2) * KP + kb + co);
        cp16(sbase + (uint32_t)(V_B_HI(s) + r1 * 40 + co) * 2, Bhi + (size_t)(n0 + r1) * KP + kb + co);
        if (tid < 128) {
            int r3 = 64 + r1;
            cp16(sbase + (uint32_t)(V_B_HI(s) + r3 * 40 + co) * 2, Bhi + (size_t)(n0 + r3) * KP + kb + co);
        }
        CP_COMMIT();
    };

    float acc[4][3][4];
#pragma unroll
    for (int mi = 0; mi < 4; mi++)
#pragma unroll
        for (int ni = 0; ni < 3; ni++)
#pragma unroll
            for (int q = 0; q < 4; q++) acc[mi][ni][q] = 0.f;

    load_chunk(0, 0);

    for (int c = 0; c < 10; c++) {
        CP_WAIT0();
        __syncthreads();
        if (c < 9) load_chunk(c + 1, (c + 1) & 1);
        int s = c & 1;
        uint32_t ah = sbase + (uint32_t)V_A_HI(s) * 2;
        uint32_t al = sbase + (uint32_t)V_A_LO(s) * 2;
        uint32_t bh = sbase + (uint32_t)V_B_HI(s) * 2;
#pragma unroll
        for (int kk = 0; kk < 2; kk++) {
            uint32_t fah[4][4], fal[4][4], fbh[3][2];
#pragma unroll
            for (int mi = 0; mi < 4; mi++) {
                uint32_t ro = (uint32_t)((wm * 64 + mi * 16 + a_row) * 40 + kk * 16 + a_k) * 2;
                ldsm_x4(fah[mi], ah + ro);
                ldsm_x4(fal[mi], al + ro);
            }
#pragma unroll
            for (int ni = 0; ni < 3; ni++) {
                uint32_t ro = (uint32_t)((wn * 24 + ni * 8 + b_row) * 40 + kk * 16 + b_k) * 2;
                ldsm_x2(fbh[ni], bh + ro);
            }
#pragma unroll
            for (int mi = 0; mi < 4; mi++)
#pragma unroll
                for (int ni = 0; ni < 3; ni++)
                    mma_bf16(acc[mi][ni], fah[mi], fbh[ni]);
#pragma unroll
            for (int mi = 0; mi < 4; mi++)
#pragma unroll
                for (int ni = 0; ni < 3; ni++)
                    mma_bf16(acc[mi][ni], fal[mi], fbh[ni]);
        }
    }
    __syncthreads();   // ghs (51200 B) overlaps both stages — drain compute

#pragma unroll
    for (int mi = 0; mi < 4; mi++) {
        int mr = wm * 64 + mi * 16 + (lane >> 2);
#pragma unroll
        for (int ni = 0; ni < 3; ni++) {
            int nn = wn * 24 + ni * 8 + (lane & 3) * 2;
            ghs[mr * GH_STRIDE + nn]           = acc[mi][ni][0];
            ghs[mr * GH_STRIDE + nn + 1]       = acc[mi][ni][1];
            ghs[(mr + 8) * GH_STRIDE + nn]     = acc[mi][ni][2];
            ghs[(mr + 8) * GH_STRIDE + nn + 1] = acc[mi][ni][3];
        }
    }
    __syncthreads();

    for (int i = tid; i < 128 * 96; i += 256) {
        int m = i / 96, n = i - m * 96;
        int gn = n0 + n;
        if (gn < G3) {
            float b2 = (gn % 3 != 2) ? bias2[gn] : 0.f;   // fold b_hh for r,z only
            VGout[(size_t)(m0 + m) * G3P + gn] =
                __float2half(ghs[m * GH_STRIDE + n] + bias1[gn] + b2);
        }
    }
}

// ---------------------------------------------------------------------------
// GRU steps, persistent: 320 blocks, tile 64x96, 2-term split (hi*W + lo*W).
// Stage (bf16 units): A_hi 2560, A_lo 2560, B_hi 3840 -> 8960 (17920 B).
// smem: stages [0,35840), gx fp16 [35840,48128), bhn [48128,48256).
// C-dump (25600 B) overlaps stage 1 -> sync before dump.
// ---------------------------------------------------------------------------
#define S_A_HI(s) ((s) * 8960 + 0)
#define S_A_LO(s) ((s) * 8960 + 2560)
#define S_B_HI(s) ((s) * 8960 + 5120)
#define GXS_B 35840
#define BHN_B 48128
#define SMEM_STEP 48256

__global__ void __launch_bounds__(256, 3)
gru_persist(const __nv_bfloat16* __restrict__ Hhi_all, const __nv_bfloat16* __restrict__ Hlo_all,
            const __nv_bfloat16* __restrict__ Bhi,
            const int* __restrict__ seq, const __half* __restrict__ VGin,
            const float* __restrict__ bph,
            int s_begin, int s_end, int use_flags)
{
    extern __shared__ __align__(16) char smem[];
    float* cs  = (float*)smem;                    // epilogue C
    __half* gxs = (__half*)(smem + GXS_B);
    float* bhn = (float*)(smem + BHN_B);
    const uint32_t sbase = smem_u32(smem);

    int tid = threadIdx.x;
    int lane = tid & 31, wid = tid >> 5;
    int wm = wid >> 2, wn = wid & 3;
    int bn = blockIdx.x;                          // 0..9
    int bm = blockIdx.y;                          // 0..31
    int m0 = bm * 64;
    int n0 = bn * 96;
    int j0 = bn * 32;

    if (tid < 32 && (n0 + 3 * tid + 2) < G3) bhn[tid] = bph[n0 + 3 * tid + 2];

    int a_row = lane & 15, a_k = (lane >> 4) << 3;
    int b_row = lane & 7,  b_k = ((lane >> 3) & 1) << 3;
    const size_t slice = (size_t)Bv * KP;

    for (int s = s_begin; s < s_end; s++) {
        const __nv_bfloat16* Hp_hi = Hhi_all + (size_t)s * slice;
        const __nv_bfloat16* Hp_lo = Hlo_all + (size_t)s * slice;
        __nv_bfloat16* Ho_hi = (__nv_bfloat16*)(Hhi_all + (size_t)(s + 1) * slice);
        __nv_bfloat16* Ho_lo = (__nv_bfloat16*)(Hlo_all + (size_t)(s + 1) * slice);

        // ---- gx gather (fp16, 16B copies) ----
#pragma unroll
        for (int c = 0; c < 3; c++) {
            int idx = tid + c * 256;           // 0..767
            int row = idx / 12, off = (idx % 12) * 8;
            int t = seq[(m0 + row) * Lv + s];
            cp16(sbase + GXS_B + (uint32_t)(row * 96 + off) * 2,
                 VGin + (size_t)t * G3P + n0 + off);
        }
        CP_COMMIT();

        // ---- wait for the 10 producers of slice s ----
        if (use_flags && s > 0) {
            if (tid == 0) {
                while (ld_acq(&d_flag[s - 1][bm]) < (unsigned)NTILE) __nanosleep(64);
            }
        }
        __syncthreads();

        auto load_chunk = [&](int cc, int st) {
            int kb = cc * 32;
            int r1 = tid >> 2, co = (tid & 3) * 8;
            cp16(sbase + (uint32_t)(S_A_HI(st) + r1 * 40 + co) * 2, Hp_hi + (size_t)(m0 + r1) * KP + kb + co);
            cp16(sbase + (uint32_t)(S_A_LO(st) + r1 * 40 + co) * 2, Hp_lo + (size_t)(m0 + r1) * KP + kb + co);
            cp16(sbase + (uint32_t)(S_B_HI(st) + r1 * 40 + co) * 2, Bhi + (size_t)(n0 + r1) * KP + kb + co);
            if (tid < 128) {
                int r2 = 64 + r1;
                cp16(sbase + (uint32_t)(S_B_HI(st) + r2 * 40 + co) * 2, Bhi + (size_t)(n0 + r2) * KP + kb + co);
            }
            CP_COMMIT();
        };

        float acc[2][3][4];
#pragma unroll
        for (int mi = 0; mi < 2; mi++)
#pragma unroll
            for (int ni = 0; ni < 3; ni++)
#pragma unroll
                for (int q = 0; q < 4; q++) acc[mi][ni][q] = 0.f;

        load_chunk(0, 0);

        for (int c = 0; c < 10; c++) {
            CP_WAIT0();
            __syncthreads();
            if (c < 9) load_chunk(c + 1, (c + 1) & 1);
            int st = c & 1;
            uint32_t ah = sbase + (uint32_t)S_A_HI(st) * 2;
            uint32_t al = sbase + (uint32_t)S_A_LO(st) * 2;
            uint32_t bh = sbase + (uint32_t)S_B_HI(st) * 2;
#pragma unroll
            for (int kk = 0; kk < 2; kk++) {
                uint32_t fah[2][4], fal[2][4], fbh[3][2];
#pragma unroll
                for (int mi = 0; mi < 2; mi++) {
                    uint32_t ro = (uint32_t)((wm * 32 + mi * 16 + a_row) * 40 + kk * 16 + a_k) * 2;
                    ldsm_x4(fah[mi], ah + ro);
                    ldsm_x4(fal[mi], al + ro);
                }
#pragma unroll
                for (int ni = 0; ni < 3; ni++) {
                    uint32_t ro = (uint32_t)((wn * 24 + ni * 8 + b_row) * 40 + kk * 16 + b_k) * 2;
                    ldsm_x2(fbh[ni], bh + ro);
                }
#pragma unroll
                for (int mi = 0; mi < 2; mi++)
#pragma unroll
                    for (int ni = 0; ni < 3; ni++)
                        mma_bf16(acc[mi][ni], fah[mi], fbh[ni]);
#pragma unroll
                for (int mi = 0; mi < 2; mi++)
#pragma unroll
                    for (int ni = 0; ni < 3; ni++)
                        mma_bf16(acc[mi][ni], fal[mi], fbh[ni]);
            }
        }
        __syncthreads();   // cs (25600 B) overlaps stage 1 — drain chunk 9 reads

        // ---- dump C to smem ----
#pragma unroll
        for (int mi = 0; mi < 2; mi++) {
            int mr = wm * 32 + mi * 16 + (lane >> 2);
#pragma unroll
            for (int ni = 0; ni < 3; ni++) {
                int nn = wn * 24 + ni * 8 + (lane & 3) * 2;
                cs[mr * GH_STRIDE + nn]           = acc[mi][ni][0];
                cs[mr * GH_STRIDE + nn + 1]       = acc[mi][ni][1];
                cs[(mr + 8) * GH_STRIDE + nn]     = acc[mi][ni][2];
                cs[(mr + 8) * GH_STRIDE + nn + 1] = acc[mi][ni][3];
            }
        }
        __syncthreads();

        // ---- gate epilogue ----
        for (int i = tid; i < 64 * 32; i += 256) {
            int ml = i >> 5, p = i & 31;
            int j = j0 + p;
            if (j < Hv) {
                int m = m0 + ml;
                float gh_r = cs[ml * GH_STRIDE + 3 * p + 0];
                float gh_z = cs[ml * GH_STRIDE + 3 * p + 1];
                float gh_n = cs[ml * GH_STRIDE + 3 * p + 2] + bhn[p];  // b_hh_n inside r*(.)
                float gx_r = __half2float(gxs[ml * 96 + 3 * p + 0]);
                float gx_z = __half2float(gxs[ml * 96 + 3 * p + 1]);
                float gx_n = __half2float(gxs[ml * 96 + 3 * p + 2]);
                float r = fsig(gx_r + gh_r);
                float z = fsig(gx_z + gh_z);
                float ng = ftanh(gx_n + r * gh_n);
                size_t hidx = (size_t)m * KP + j;
                float hp = __bfloat162float(Hp_hi[hidx]) + __bfloat162float(Hp_lo[hidx]);
                float h = (1.f - z) * ng + z * hp;
                __nv_bfloat16 hh = __float2bfloat16(h);
                Ho_hi[hidx] = hh;
                Ho_lo[hidx] = __float2bfloat16(h - __bfloat162float(hh));
            }
        }

        if (use_flags) {
            __threadfence();
            __syncthreads();
            if (tid == 0) red_rel_add1(&d_flag[s][bm]);
        } else {
            __syncthreads();
        }
    }

    // ---- reset phase (persistent mode only) ----
    if (use_flags) {
        if (tid == 0) red_rel_add1(&d_done[bm]);
        if (bn == 0) {
            if (tid == 0) {
                while (ld_acq(&d_done[bm]) < (unsigned)NTILE) __nanosleep(64);
            }
            __syncthreads();
            for (int s = tid; s < Lv; s += 256) d_flag[s][bm] = 0;
            if (tid == 0) d_done[bm] = 0;
            __threadfence();
        }
    }
}

// ---------------------------------------------------------------------------
// Post: collapsed co-attention + softmax + pooling + logits. Vectorized h load.
// ---------------------------------------------------------------------------
__device__ __forceinline__ float blockReduceSum(float v, volatile float* red)
{
    __syncthreads();
#pragma unroll
    for (int o = 16; o > 0; o >>= 1) v += __shfl_xor_sync(0xffffffffu, v, o);
    int w = threadIdx.x >> 5, ln = threadIdx.x & 31;
    if (ln == 0) red[w] = v;
    __syncthreads();
    if (threadIdx.x < 32) {
        float x = (threadIdx.x < 8) ? red[threadIdx.x] : 0.f;
#pragma unroll
        for (int o = 4; o > 0; o >>= 1) x += __shfl_xor_sync(0xffffffffu, x, o);
        if (threadIdx.x == 0) red[0] = x;
    }
    __syncthreads();
    return red[0];
}
__device__ __forceinline__ float blockReduceMax(float v, volatile float* red)
{
    __syncthreads();
#pragma unroll
    for (int o = 16; o > 0; o >>= 1) v = fmaxf(v, __shfl_xor_sync(0xffffffffu, v, o));
    int w = threadIdx.x >> 5, ln = threadIdx.x & 31;
    if (ln == 0) red[w] = v;
    __syncthreads();
    if (threadIdx.x < 32) {
        float x = (threadIdx.x < 8) ? red[threadIdx.x] : -3.4e38f;
#pragma unroll
        for (int o = 4; o > 0; o >>= 1) x = fmaxf(x, __shfl_xor_sync(0xffffffffu, x, o));
        if (threadIdx.x == 0) red[0] = x;
    }
    __syncthreads();
    return red[0];
}

__global__ void post_kernel(const __nv_bfloat16* __restrict__ Hhi,
                            const __nv_bfloat16* __restrict__ Hlo,
                            const float* __restrict__ wCo_w, const float* __restrict__ wCo_b,
                            const float* __restrict__ Wmy_w, const float* __restrict__ Wmy_b,
                            const float* __restrict__ logits_w, const float* __restrict__ logits_b,
                            float* __restrict__ out)
{
    extern __shared__ float fs[];
    float* h_s    = fs;
    float* wa     = h_s + Lv * Hv;
    float* wb_    = wa + Hv;
    float* wc     = wb_ + Hv;
    float* wmy    = wc + Hv;
    float* aa     = wmy + 80;
    float* bb     = aa + 80;
    float* qq     = bb + 80;
    float* pp     = qq + 80;
    float* smarr  = pp + 80;
    float* attn   = smarr + 80;
    float* u      = attn + 80;
    float* pooled = u + Hv;
    __shared__ float red[32];

    int b = blockIdx.x;
    int tid = threadIdx.x;
    int w = tid >> 5, ln = tid & 31;

    for (int t = tid; t < Lv * (Hv / 4); t += 256) {
        int i = t / (Hv / 4), d4 = (t - i * (Hv / 4)) * 4;
        size_t idx = (size_t)(i + 1) * Bv * KP + (size_t)b * KP + d4;
        uint2 vh = *(const uint2*)(Hhi + idx);
        uint2 vl = *(const uint2*)(Hlo + idx);
        const __nv_bfloat162* ph = (const __nv_bfloat162*)&vh;
        const __nv_bfloat162* pl = (const __nv_bfloat162*)&vl;
        float2 h0 = __bfloat1622float2(ph[0]);
        float2 l0 = __bfloat1622float2(pl[0]);
        float2 h1 = __bfloat1622float2(ph[1]);
        float2 l1 = __bfloat1622float2(pl[1]);
        float* dst = h_s + i * Hv + d4;
        dst[0] = h0.x + l0.x;
        dst[1] = h0.y + l0.y;
        dst[2] = h1.x + l1.x;
        dst[3] = h1.y + l1.y;
    }
    for (int t = tid; t < Hv; t += 256) {
        wa[t]  = wCo_w[t];
        wb_[t] = wCo_w[Hv + t];
        wc[t]  = wCo_w[2 * Hv + t];
    }
    if (tid < Lv) wmy[tid] = Wmy_w[tid];
    __syncthreads();

    for (int i = w; i < Lv; i += 8) {
        float sa = 0.f, sb2 = 0.f, sq = 0.f;
        for (int d = ln; d < Hv; d += 32) {
            float hv = h_s[i * Hv + d];
            sa += hv * wa[d];
            sb2 += hv * wb_[d];
            sq += hv * hv * wc[d];
        }
#pragma unroll
        for (int o = 16; o > 0; o >>= 1) {
            sa += __shfl_xor_sync(0xffffffffu, sa, o);
            sb2 += __shfl_xor_sync(0xffffffffu, sb2, o);
            sq += __shfl_xor_sync(0xffffffffu, sq, o);
        }
        if (ln == 0) { aa[i] = sa; bb[i] = sb2; qq[i] = sq; }
    }
    __syncthreads();

    for (int d = tid; d < Hv; d += 256) {
        float s = 0.f;
#pragma unroll 5
        for (int i = 0; i < Lv; i++) s += wmy[i] * h_s[i * Hv + d];
        u[d] = s;
    }

    float swv = (tid < Lv) ? wmy[tid] : 0.f;
    float Sw = blockReduceSum(swv, red);
    float tv = (tid < Lv) ? wmy[tid] * bb[tid] : 0.f;
    float T = blockReduceSum(tv, red);
    __syncthreads();

    for (int i = w; i < Lv; i += 8) {
        float sp = 0.f;
        for (int d = ln; d < Hv; d += 32) sp += h_s[i * Hv + d] * wc[d] * u[d];
#pragma unroll
        for (int o = 16; o > 0; o >>= 1) sp += __shfl_xor_sync(0xffffffffu, sp, o);
        if (ln == 0) pp[i] = sp;
    }
    __syncthreads();

    float beta = wCo_b[0];
    if (tid < Lv) {
        smarr[tid] = (aa[tid] + beta) * Sw + T + pp[tid]
                   - wmy[tid] * (aa[tid] + bb[tid] + beta + qq[tid]) + Wmy_b[0];
    }
    __syncthreads();

    float mv = (tid < Lv) ? smarr[tid] : -3.4e38f;
    float mx = blockReduceMax(mv, red);
    float ev = (tid < Lv) ? expf(smarr[tid] - mx) : 0.f;
    if (tid < Lv) attn[tid] = ev;
    float se = blockReduceSum(ev, red);
    if (tid < Lv) attn[tid] = attn[tid] / se;
    __syncthreads();

    for (int d = tid; d < Hv; d += 256) {
        float s = 0.f;
#pragma unroll 5
        for (int i = 0; i < Lv; i++) s += attn[i] * h_s[i * Hv + d];
        pooled[d] = s;
    }
    __syncthreads();

    if (w < OUTv) {
        float s = 0.f;
        for (int d = ln; d < Hv; d += 32) s += pooled[d] * logits_w[w * Hv + d];
#pragma unroll
        for (int o = 16; o > 0; o >>= 1) s += __shfl_xor_sync(0xffffffffu, s, o);
        if (ln == 0) out[(size_t)b * OUTv + w] = s + logits_b[w];
    }
}

// ---------------------------------------------------------------------------
extern "C" void kernel_launch(void* const* d_in, const int* in_sizes, int n_in,
                              void* d_out, int out_size)
{
    const int*   seq      = (const int*)  d_in[0];
    const float* emb      = (const float*)d_in[1];
    const float* W_ih     = (const float*)d_in[2];
    const float* W_hh     = (const float*)d_in[3];
    const float* b_ih     = (const float*)d_in[4];
    const float* b_hh     = (const float*)d_in[5];
    const float* wCo_w    = (const float*)d_in[6];
    const float* wCo_b    = (const float*)d_in[7];
    const float* Wmy_w    = (const float*)d_in[8];
    const float* Wmy_b    = (const float*)d_in[9];
    const float* logits_w = (const float*)d_in[10];
    const float* logits_b = (const float*)d_in[11];
    float* out = (float*)d_out;

    __nv_bfloat16 *ehi, *elo, *wih_hi, *whh_hi, *Hhi, *Hlo;
    float *bpih, *bphh;
    __half* VG;
    cudaGetSymbolAddress((void**)&ehi,    d_emb_hi);
    cudaGetSymbolAddress((void**)&elo,    d_emb_lo);
    cudaGetSymbolAddress((void**)&wih_hi, d_Wih_hi);
    cudaGetSymbolAddress((void**)&whh_hi, d_Whh_hi);
    cudaGetSymbolAddress((void**)&bpih,   d_bp_ih);
    cudaGetSymbolAddress((void**)&bphh,   d_bp_hh);
    cudaGetSymbolAddress((void**)&VG,     d_VG);
    cudaGetSymbolAddress((void**)&Hhi,    d_Hhi);
    cudaGetSymbolAddress((void**)&Hlo,    d_Hlo);

    cudaFuncSetAttribute(vg_gemm, cudaFuncAttributeMaxDynamicSharedMemorySize, SMEM_VG);
    cudaFuncSetAttribute(gru_persist, cudaFuncAttributeMaxDynamicSharedMemorySize, SMEM_STEP);
    const int POST_SMEM = (Lv * Hv + 3 * Hv + 7 * 80 + 2 * Hv) * (int)sizeof(float);
    cudaFuncSetAttribute(post_kernel, cudaFuncAttributeMaxDynamicSharedMemorySize, POST_SMEM);

    // Persistent only if all 320 blocks provably co-resident.
    int occ = 0, sms = 0;
    cudaOccupancyMaxActiveBlocksPerMultiprocessor(&occ, gru_persist, 256, SMEM_STEP);
    cudaDeviceGetAttribute(&sms, cudaDevAttrMultiProcessorCount, 0);
    bool persistent = ((long)occ * sms >= NTILE * MTILE);

    // 0) conversions
    {
        long n = (long)VOCAB * Ev;
        conv_emb<<<(unsigned)((n + 255) / 256), 256>>>(emb, ehi, elo);
    }
    conv_w<<<G3, 128>>>(W_ih, b_ih, wih_hi, bpih);
    conv_w<<<G3, 128>>>(W_hh, b_hh, whh_hi, bphh);

    // 1) VG(fp16) = emb @ W_ih^T + b_ih + rz(b_hh) over full vocab
    {
        dim3 grid(10, VROWS / 128);
        vg_gemm<<<grid, 256, SMEM_VG>>>(ehi, elo, wih_hi, bpih, bphh, VG);
    }

    // 2) GRU recurrence
    dim3 grid(NTILE, MTILE);
    if (persistent) {
        gru_persist<<<grid, 256, SMEM_STEP>>>(Hhi, Hlo, whh_hi,
                                              seq, VG, bphh, 0, Lv, 1);
    } else {
        for (int l = 0; l < Lv; l++)
            gru_persist<<<grid, 256, SMEM_STEP>>>(Hhi, Hlo, whh_hi,
                                                  seq, VG, bphh, l, l + 1, 0);
    }

    // 3) collapsed co-attention + softmax + pooling + logits
    post_kernel<<<Bv, 256, POST_SMEM>>>(Hhi, Hlo, wCo_w, wCo_b, Wmy_w, Wmy_b,
                                        logits_w, logits_b, out);
}

// round 16
// speedup vs baseline: 2.0832x; 1.0025x over previous
#include <cuda_runtime.h>
#include <cuda_bf16.h>
#include <cuda_fp16.h>
#include <math.h>
#include <stdint.h>

#define Bv   2048
#define Lv   75
#define Ev   300
#define Hv   300
#define G3   900
#define G3P  912                 // VG row stride in halves (16B-aligned)
#define OUTv 5
#define KP   320                 // K padded to 10 x 32
#define VROWS 50048              // vocab rows padded to 391*128
#define NROWS 960                // gate rows padded to 10*96
#define VOCAB 50000
#define NTILE 10                 // n-blocks per step
#define MTILE 32                 // m-blocks per step

// ---------------- scratch (device globals; zero-initialized) ---------------
__device__ __half d_emb_hi[(size_t)VROWS * KP];
__device__ __half d_emb_lo[(size_t)VROWS * KP];
__device__ __half d_Wih_hi[NROWS * KP];
__device__ __half d_Whh_hi[NROWS * KP];
__device__ float d_bp_ih[G3];
__device__ float d_bp_hh[G3];
__device__ __half d_VG[(size_t)VROWS * G3P];             // vocab gates, fp16
__device__ __half d_Hhi[(size_t)(Lv + 1) * Bv * KP];     // slice 0 = zeros
__device__ __half d_Hlo[(size_t)(Lv + 1) * Bv * KP];
__device__ unsigned int d_flag[Lv][MTILE];               // producers of slice s+1
__device__ unsigned int d_done[MTILE];

// ---------------------------- helpers ---------------------------------------
__device__ __forceinline__ uint32_t smem_u32(const void* p) {
    uint32_t a;
    asm("{ .reg .u64 t; cvta.to.shared.u64 t, %1; cvt.u32.u64 %0, t; }" : "=r"(a) : "l"(p));
    return a;
}
__device__ __forceinline__ void ldsm_x4(uint32_t* r, uint32_t addr) {
    asm volatile("ldmatrix.sync.aligned.m8n8.x4.shared.b16 {%0,%1,%2,%3}, [%4];"
                 : "=r"(r[0]), "=r"(r[1]), "=r"(r[2]), "=r"(r[3]) : "r"(addr));
}
__device__ __forceinline__ void ldsm_x2(uint32_t* r, uint32_t addr) {
    asm volatile("ldmatrix.sync.aligned.m8n8.x2.shared.b16 {%0,%1}, [%2];"
                 : "=r"(r[0]), "=r"(r[1]) : "r"(addr));
}
// fp16 inputs, fp32 accumulate
__device__ __forceinline__ void mma_f16(float* c, const uint32_t* a, const uint32_t* b) {
    asm volatile(
        "mma.sync.aligned.m16n8k16.row.col.f32.f16.f16.f32 "
        "{%0,%1,%2,%3}, {%4,%5,%6,%7}, {%8,%9}, {%0,%1,%2,%3};"
        : "+f"(c[0]), "+f"(c[1]), "+f"(c[2]), "+f"(c[3])
        : "r"(a[0]), "r"(a[1]), "r"(a[2]), "r"(a[3]), "r"(b[0]), "r"(b[1]));
}
__device__ __forceinline__ void cp16(uint32_t dst, const void* src) {
    asm volatile("cp.async.cg.shared.global [%0], [%1], 16;" :: "r"(dst), "l"(src));
}
#define CP_COMMIT() asm volatile("cp.async.commit_group;" ::: "memory")
#define CP_WAIT0()  asm volatile("cp.async.wait_group 0;" ::: "memory")

__device__ __forceinline__ unsigned int ld_acq(const unsigned int* p) {
    unsigned int v;
    asm volatile("ld.global.acquire.gpu.u32 %0, [%1];" : "=r"(v) : "l"(p) : "memory");
    return v;
}
__device__ __forceinline__ void red_rel_add1(unsigned int* p) {
    asm volatile("red.release.gpu.global.add.u32 [%0], 1;" :: "l"(p) : "memory");
}
__device__ __forceinline__ float fsig(float x) {
    x = fminf(fmaxf(x, -30.f), 30.f);
    return __fdividef(1.f, 1.f + __expf(-x));
}
__device__ __forceinline__ float ftanh(float x) {
    x = fminf(fmaxf(x, -15.f), 15.f);
    float e = __expf(2.f * x);
    return __fdividef(e - 1.f, e + 1.f);
}

// ---------------------------- conversion kernels ---------------------------
__global__ void conv_emb(const float* __restrict__ emb,
                         __half* __restrict__ hi, __half* __restrict__ lo)
{
    long i = (long)blockIdx.x * blockDim.x + threadIdx.x;
    if (i >= (long)VOCAB * Ev) return;
    int row = (int)(i / Ev), col = (int)(i - (long)row * Ev);
    float x = emb[i];
    __half h = __float2half(x);
    hi[(size_t)row * KP + col] = h;
    lo[(size_t)row * KP + col] = __float2half(x - __half2float(h));
}

// permute rows (g*H+j) -> (3j+g); W stored fp16 (11-bit mantissa).
__global__ void conv_w(const float* __restrict__ W, const float* __restrict__ b,
                       __half* __restrict__ hi, float* __restrict__ bp)
{
    int n = blockIdx.x;            // 0..899
    int j = n / 3, g = n % 3;
    const float* src = W + (size_t)(g * Hv + j) * 300;
    for (int k = threadIdx.x; k < 300; k += blockDim.x)
        hi[(size_t)n * KP + k] = __float2half(src[k]);
    if (threadIdx.x == 0) bp[n] = b[g * Hv + j];
}

// ---------------------------------------------------------------------------
// VG GEMM: VG(fp16) = (emb_hi+emb_lo) @ W_ih^T + biases. fp16 MMA, 2-term.
// Block 128x96, warp tile 64x24, 2 stages, one sync per chunk.
// ---------------------------------------------------------------------------
#define V_A_HI(s) ((s) * 14080 + 0)
#define V_A_LO(s) ((s) * 14080 + 5120)
#define V_B_HI(s) ((s) * 14080 + 10240)
#define GH_STRIDE 100
#define SMEM_VG (2 * 14080 * 2)

__global__ void __launch_bounds__(256)
vg_gemm(const __half* __restrict__ Ahi, const __half* __restrict__ Alo,
        const __half* __restrict__ Bhi,
        const float* __restrict__ bias1, const float* __restrict__ bias2,
        __half* __restrict__ VGout)
{
    extern __shared__ __align__(16) char smem[];
    float* ghs = (float*)smem;
    const uint32_t sbase = smem_u32(smem);

    int tid = threadIdx.x;
    int lane = tid & 31, wid = tid >> 5;
    int wm = wid >> 2, wn = wid & 3;
    int m0 = blockIdx.y * 128;
    int n0 = blockIdx.x * 96;

    int a_row = lane & 15, a_k = (lane >> 4) << 3;
    int b_row = lane & 7,  b_k = ((lane >> 3) & 1) << 3;

    auto load_chunk = [&](int cc, int s) {
        int kb = cc * 32;
        int r1 = tid >> 2, co = (tid & 3) * 8;
        int r2 = 64 + r1;
        cp16(sbase + (uint32_t)(V_A_HI(s) + r1 * 40 + co) * 2, Ahi + (size_t)(m0 + r1) * KP + kb + co);
        cp16(sbase + (uint32_t)(V_A_HI(s) + r2 * 40 + co) * 2, Ahi + (size_t)(m0 + r2) * KP + kb + co);
        cp16(sbase + (uint32_t)(V_A_LO(s) + r1 * 40 + co) * 2, Alo + (size_t)(m0 + r1) * KP + kb + co);
        cp16(sbase + (uint32_t)(V_A_LO(s) + r2 * 40 + co) * 2, Alo + (size_t)(m0 + r2) * KP + kb + co);
        cp16(sbase + (uint32_t)(V_B_HI(s) + r1 * 40 + co) * 2, Bhi + (size_t)(n0 + r1) * KP + kb + co);
        if (tid < 128) {
            int r3 = 64 + r1;
            cp16(sbase + (uint32_t)(V_B_HI(s) + r3 * 40 + co) * 2, Bhi + (size_t)(n0 + r3) * KP + kb + co);
        }
        CP_COMMIT();
    };

    float acc[4][3][4];
#pragma unroll
    for (int mi = 0; mi < 4; mi++)
#pragma unroll
        for (int ni = 0; ni < 3; ni++)
#pragma unroll
            for (int q = 0; q < 4; q++) acc[mi][ni][q] = 0.f;

    load_chunk(0, 0);

    for (int c = 0; c < 10; c++) {
        CP_WAIT0();
        __syncthreads();
        if (c < 9) load_chunk(c + 1, (c + 1) & 1);
        int s = c & 1;
        uint32_t ah = sbase + (uint32_t)V_A_HI(s) * 2;
        uint32_t al = sbase + (uint32_t)V_A_LO(s) * 2;
        uint32_t bh = sbase + (uint32_t)V_B_HI(s) * 2;
#pragma unroll
        for (int kk = 0; kk < 2; kk++) {
            uint32_t fah[4][4], fal[4][4], fbh[3][2];
#pragma unroll
            for (int mi = 0; mi < 4; mi++) {
                uint32_t ro = (uint32_t)((wm * 64 + mi * 16 + a_row) * 40 + kk * 16 + a_k) * 2;
                ldsm_x4(fah[mi], ah + ro);
                ldsm_x4(fal[mi], al + ro);
            }
#pragma unroll
            for (int ni = 0; ni < 3; ni++) {
                uint32_t ro = (uint32_t)((wn * 24 + ni * 8 + b_row) * 40 + kk * 16 + b_k) * 2;
                ldsm_x2(fbh[ni], bh + ro);
            }
#pragma unroll
            for (int mi = 0; mi < 4; mi++)
#pragma unroll
                for (int ni = 0; ni < 3; ni++)
                    mma_f16(acc[mi][ni], fah[mi], fbh[ni]);
#pragma unroll
            for (int mi = 0; mi < 4; mi++)
#pragma unroll
                for (int ni = 0; ni < 3; ni++)
                    mma_f16(acc[mi][ni], fal[mi], fbh[ni]);
        }
    }
    __syncthreads();   // ghs overlaps stages — drain compute

#pragma unroll
    for (int mi = 0; mi < 4; mi++) {
        int mr = wm * 64 + mi * 16 + (lane >> 2);
#pragma unroll
        for (int ni = 0; ni < 3; ni++) {
            int nn = wn * 24 + ni * 8 + (lane & 3) * 2;
            ghs[mr * GH_STRIDE + nn]           = acc[mi][ni][0];
            ghs[mr * GH_STRIDE + nn + 1]       = acc[mi][ni][1];
            ghs[(mr + 8) * GH_STRIDE + nn]     = acc[mi][ni][2];
            ghs[(mr + 8) * GH_STRIDE + nn + 1] = acc[mi][ni][3];
        }
    }
    __syncthreads();

    for (int i = tid; i < 128 * 96; i += 256) {
        int m = i / 96, n = i - m * 96;
        int gn = n0 + n;
        if (gn < G3) {
            float b2 = (gn % 3 != 2) ? bias2[gn] : 0.f;   // fold b_hh for r,z only
            VGout[(size_t)(m0 + m) * G3P + gn] =
                __float2half(ghs[m * GH_STRIDE + n] + bias1[gn] + b2);
        }
    }
}

// ---------------------------------------------------------------------------
// GRU steps, persistent: 320 blocks, tile 64x96, fp16 MMA, 2-term split.
// smem: stages [0,35840), gx fp16 [35840,48128), bhn [48128,48256).
// ---------------------------------------------------------------------------
#define S_A_HI(s) ((s) * 8960 + 0)
#define S_A_LO(s) ((s) * 8960 + 2560)
#define S_B_HI(s) ((s) * 8960 + 5120)
#define GXS_B 35840
#define BHN_B 48128
#define SMEM_STEP 48256

__global__ void __launch_bounds__(256, 3)
gru_persist(const __half* __restrict__ Hhi_all, const __half* __restrict__ Hlo_all,
            const __half* __restrict__ Bhi,
            const int* __restrict__ seq, const __half* __restrict__ VGin,
            const float* __restrict__ bph,
            int s_begin, int s_end, int use_flags)
{
    extern __shared__ __align__(16) char smem[];
    float* cs  = (float*)smem;                    // epilogue C
    __half* gxs = (__half*)(smem + GXS_B);
    float* bhn = (float*)(smem + BHN_B);
    const uint32_t sbase = smem_u32(smem);

    int tid = threadIdx.x;
    int lane = tid & 31, wid = tid >> 5;
    int wm = wid >> 2, wn = wid & 3;
    int bn = blockIdx.x;                          // 0..9
    int bm = blockIdx.y;                          // 0..31
    int m0 = bm * 64;
    int n0 = bn * 96;
    int j0 = bn * 32;

    if (tid < 32 && (n0 + 3 * tid + 2) < G3) bhn[tid] = bph[n0 + 3 * tid + 2];

    int a_row = lane & 15, a_k = (lane >> 4) << 3;
    int b_row = lane & 7,  b_k = ((lane >> 3) & 1) << 3;
    const size_t slice = (size_t)Bv * KP;

    for (int s = s_begin; s < s_end; s++) {
        const __half* Hp_hi = Hhi_all + (size_t)s * slice;
        const __half* Hp_lo = Hlo_all + (size_t)s * slice;
        __half* Ho_hi = (__half*)(Hhi_all + (size_t)(s + 1) * slice);
        __half* Ho_lo = (__half*)(Hlo_all + (size_t)(s + 1) * slice);

        // ---- gx gather (fp16, 16B copies) ----
#pragma unroll
        for (int c = 0; c < 3; c++) {
            int idx = tid + c * 256;           // 0..767
            int row = idx / 12, off = (idx % 12) * 8;
            int t = seq[(m0 + row) * Lv + s];
            cp16(sbase + GXS_B + (uint32_t)(row * 96 + off) * 2,
                 VGin + (size_t)t * G3P + n0 + off);
        }
        CP_COMMIT();

        // ---- wait for the 10 producers of slice s ----
        if (use_flags && s > 0) {
            if (tid == 0) {
                while (ld_acq(&d_flag[s - 1][bm]) < (unsigned)NTILE) __nanosleep(64);
            }
        }
        __syncthreads();

        auto load_chunk = [&](int cc, int st) {
            int kb = cc * 32;
            int r1 = tid >> 2, co = (tid & 3) * 8;
            cp16(sbase + (uint32_t)(S_A_HI(st) + r1 * 40 + co) * 2, Hp_hi + (size_t)(m0 + r1) * KP + kb + co);
            cp16(sbase + (uint32_t)(S_A_LO(st) + r1 * 40 + co) * 2, Hp_lo + (size_t)(m0 + r1) * KP + kb + co);
            cp16(sbase + (uint32_t)(S_B_HI(st) + r1 * 40 + co) * 2, Bhi + (size_t)(n0 + r1) * KP + kb + co);
            if (tid < 128) {
                int r2 = 64 + r1;
                cp16(sbase + (uint32_t)(S_B_HI(st) + r2 * 40 + co) * 2, Bhi + (size_t)(n0 + r2) * KP + kb + co);
            }
            CP_COMMIT();
        };

        float acc[2][3][4];
#pragma unroll
        for (int mi = 0; mi < 2; mi++)
#pragma unroll
            for (int ni = 0; ni < 3; ni++)
#pragma unroll
                for (int q = 0; q < 4; q++) acc[mi][ni][q] = 0.f;

        load_chunk(0, 0);

        for (int c = 0; c < 10; c++) {
            CP_WAIT0();
            __syncthreads();
            if (c < 9) load_chunk(c + 1, (c + 1) & 1);
            int st = c & 1;
            uint32_t ah = sbase + (uint32_t)S_A_HI(st) * 2;
            uint32_t al = sbase + (uint32_t)S_A_LO(st) * 2;
            uint32_t bh = sbase + (uint32_t)S_B_HI(st) * 2;
#pragma unroll
            for (int kk = 0; kk < 2; kk++) {
                uint32_t fah[2][4], fal[2][4], fbh[3][2];
#pragma unroll
                for (int mi = 0; mi < 2; mi++) {
                    uint32_t ro = (uint32_t)((wm * 32 + mi * 16 + a_row) * 40 + kk * 16 + a_k) * 2;
                    ldsm_x4(fah[mi], ah + ro);
                    ldsm_x4(fal[mi], al + ro);
                }
#pragma unroll
                for (int ni = 0; ni < 3; ni++) {
                    uint32_t ro = (uint32_t)((wn * 24 + ni * 8 + b_row) * 40 + kk * 16 + b_k) * 2;
                    ldsm_x2(fbh[ni], bh + ro);
                }
#pragma unroll
                for (int mi = 0; mi < 2; mi++)
#pragma unroll
                    for (int ni = 0; ni < 3; ni++)
                        mma_f16(acc[mi][ni], fah[mi], fbh[ni]);
#pragma unroll
                for (int mi = 0; mi < 2; mi++)
#pragma unroll
                    for (int ni = 0; ni < 3; ni++)
                        mma_f16(acc[mi][ni], fal[mi], fbh[ni]);
            }
        }
        __syncthreads();   // cs overlaps stage 1 — drain chunk 9 reads

        // ---- dump C to smem ----
#pragma unroll
        for (int mi = 0; mi < 2; mi++) {
            int mr = wm * 32 + mi * 16 + (lane >> 2);
#pragma unroll
            for (int ni = 0; ni < 3; ni++) {
                int nn = wn * 24 + ni * 8 + (lane & 3) * 2;
                cs[mr * GH_STRIDE + nn]           = acc[mi][ni][0];
                cs[mr * GH_STRIDE + nn + 1]       = acc[mi][ni][1];
                cs[(mr + 8) * GH_STRIDE + nn]     = acc[mi][ni][2];
                cs[(mr + 8) * GH_STRIDE + nn + 1] = acc[mi][ni][3];
            }
        }
        __syncthreads();

        // ---- gate epilogue ----
        for (int i = tid; i < 64 * 32; i += 256) {
            int ml = i >> 5, p = i & 31;
            int j = j0 + p;
            if (j < Hv) {
                int m = m0 + ml;
                float gh_r = cs[ml * GH_STRIDE + 3 * p + 0];
                float gh_z = cs[ml * GH_STRIDE + 3 * p + 1];
                float gh_n = cs[ml * GH_STRIDE + 3 * p + 2] + bhn[p];  // b_hh_n inside r*(.)
                float gx_r = __half2float(gxs[ml * 96 + 3 * p + 0]);
                float gx_z = __half2float(gxs[ml * 96 + 3 * p + 1]);
                float gx_n = __half2float(gxs[ml * 96 + 3 * p + 2]);
                float r = fsig(gx_r + gh_r);
                float z = fsig(gx_z + gh_z);
                float ng = ftanh(gx_n + r * gh_n);
                size_t hidx = (size_t)m * KP + j;
                float hp = __half2float(Hp_hi[hidx]) + __half2float(Hp_lo[hidx]);
                float h = (1.f - z) * ng + z * hp;
                __half hh = __float2half(h);
                Ho_hi[hidx] = hh;
                Ho_lo[hidx] = __float2half(h - __half2float(hh));
            }
        }

        if (use_flags) {
            __threadfence();
            __syncthreads();
            if (tid == 0) red_rel_add1(&d_flag[s][bm]);
        } else {
            __syncthreads();
        }
    }

    // ---- reset phase (persistent mode only) ----
    if (use_flags) {
        if (tid == 0) red_rel_add1(&d_done[bm]);
        if (bn == 0) {
            if (tid == 0) {
                while (ld_acq(&d_done[bm]) < (unsigned)NTILE) __nanosleep(64);
            }
            __syncthreads();
            for (int s = tid; s < Lv; s += 256) d_flag[s][bm] = 0;
            if (tid == 0) d_done[bm] = 0;
            __threadfence();
        }
    }
}

// ---------------------------------------------------------------------------
// Post: collapsed co-attention + softmax + pooling + logits. Vectorized h load.
// ---------------------------------------------------------------------------
__device__ __forceinline__ float blockReduceSum(float v, volatile float* red)
{
    __syncthreads();
#pragma unroll
    for (int o = 16; o > 0; o >>= 1) v += __shfl_xor_sync(0xffffffffu, v, o);
    int w = threadIdx.x >> 5, ln = threadIdx.x & 31;
    if (ln == 0) red[w] = v;
    __syncthreads();
    if (threadIdx.x < 32) {
        float x = (threadIdx.x < 8) ? red[threadIdx.x] : 0.f;
#pragma unroll
        for (int o = 4; o > 0; o >>= 1) x += __shfl_xor_sync(0xffffffffu, x, o);
        if (threadIdx.x == 0) red[0] = x;
    }
    __syncthreads();
    return red[0];
}
__device__ __forceinline__ float blockReduceMax(float v, volatile float* red)
{
    __syncthreads();
#pragma unroll
    for (int o = 16; o > 0; o >>= 1) v = fmaxf(v, __shfl_xor_sync(0xffffffffu, v, o));
    int w = threadIdx.x >> 5, ln = threadIdx.x & 31;
    if (ln == 0) red[w] = v;
    __syncthreads();
    if (threadIdx.x < 32) {
        float x = (threadIdx.x < 8) ? red[threadIdx.x] : -3.4e38f;
#pragma unroll
        for (int o = 4; o > 0; o >>= 1) x = fmaxf(x, __shfl_xor_sync(0xffffffffu, x, o));
        if (threadIdx.x == 0) red[0] = x;
    }
    __syncthreads();
    return red[0];
}

__global__ void post_kernel(const __half* __restrict__ Hhi,
                            const __half* __restrict__ Hlo,
                            const float* __restrict__ wCo_w, const float* __restrict__ wCo_b,
                            const float* __restrict__ Wmy_w, const float* __restrict__ Wmy_b,
                            const float* __restrict__ logits_w, const float* __restrict__ logits_b,
                            float* __restrict__ out)
{
    extern __shared__ float fs[];
    float* h_s    = fs;
    float* wa     = h_s + Lv * Hv;
    float* wb_    = wa + Hv;
    float* wc     = wb_ + Hv;
    float* wmy    = wc + Hv;
    float* aa     = wmy + 80;
    float* bb     = aa + 80;
    float* qq     = bb + 80;
    float* pp     = qq + 80;
    float* smarr  = pp + 80;
    float* attn   = smarr + 80;
    float* u      = attn + 80;
    float* pooled = u + Hv;
    __shared__ float red[32];

    int b = blockIdx.x;
    int tid = threadIdx.x;
    int w = tid >> 5, ln = tid & 31;

    for (int t = tid; t < Lv * (Hv / 4); t += 256) {
        int i = t / (Hv / 4), d4 = (t - i * (Hv / 4)) * 4;
        size_t idx = (size_t)(i + 1) * Bv * KP + (size_t)b * KP + d4;
        uint2 vh = *(const uint2*)(Hhi + idx);
        uint2 vl = *(const uint2*)(Hlo + idx);
        const __half2* ph = (const __half2*)&vh;
        const __half2* pl = (const __half2*)&vl;
        float2 h0 = __half22float2(ph[0]);
        float2 l0 = __half22float2(pl[0]);
        float2 h1 = __half22float2(ph[1]);
        float2 l1 = __half22float2(pl[1]);
        float* dst = h_s + i * Hv + d4;
        dst[0] = h0.x + l0.x;
        dst[1] = h0.y + l0.y;
        dst[2] = h1.x + l1.x;
        dst[3] = h1.y + l1.y;
    }
    for (int t = tid; t < Hv; t += 256) {
        wa[t]  = wCo_w[t];
        wb_[t] = wCo_w[Hv + t];
        wc[t]  = wCo_w[2 * Hv + t];
    }
    if (tid < Lv) wmy[tid] = Wmy_w[tid];
    __syncthreads();

    for (int i = w; i < Lv; i += 8) {
        float sa = 0.f, sb2 = 0.f, sq = 0.f;
        for (int d = ln; d < Hv; d += 32) {
            float hv = h_s[i * Hv + d];
            sa += hv * wa[d];
            sb2 += hv * wb_[d];
            sq += hv * hv * wc[d];
        }
#pragma unroll
        for (int o = 16; o > 0; o >>= 1) {
            sa += __shfl_xor_sync(0xffffffffu, sa, o);
            sb2 += __shfl_xor_sync(0xffffffffu, sb2, o);
            sq += __shfl_xor_sync(0xffffffffu, sq, o);
        }
        if (ln == 0) { aa[i] = sa; bb[i] = sb2; qq[i] = sq; }
    }
    __syncthreads();

    for (int d = tid; d < Hv; d += 256) {
        float s = 0.f;
#pragma unroll 5
        for (int i = 0; i < Lv; i++) s += wmy[i] * h_s[i * Hv + d];
        u[d] = s;
    }

    float swv = (tid < Lv) ? wmy[tid] : 0.f;
    float Sw = blockReduceSum(swv, red);
    float tv = (tid < Lv) ? wmy[tid] * bb[tid] : 0.f;
    float T = blockReduceSum(tv, red);
    __syncthreads();

    for (int i = w; i < Lv; i += 8) {
        float sp = 0.f;
        for (int d = ln; d < Hv; d += 32) sp += h_s[i * Hv + d] * wc[d] * u[d];
#pragma unroll
        for (int o = 16; o > 0; o >>= 1) sp += __shfl_xor_sync(0xffffffffu, sp, o);
        if (ln == 0) pp[i] = sp;
    }
    __syncthreads();

    float beta = wCo_b[0];
    if (tid < Lv) {
        smarr[tid] = (aa[tid] + beta) * Sw + T + pp[tid]
                   - wmy[tid] * (aa[tid] + bb[tid] + beta + qq[tid]) + Wmy_b[0];
    }
    __syncthreads();

    float mv = (tid < Lv) ? smarr[tid] : -3.4e38f;
    float mx = blockReduceMax(mv, red);
    float ev = (tid < Lv) ? expf(smarr[tid] - mx) : 0.f;
    if (tid < Lv) attn[tid] = ev;
    float se = blockReduceSum(ev, red);
    if (tid < Lv) attn[tid] = attn[tid] / se;
    __syncthreads();

    for (int d = tid; d < Hv; d += 256) {
        float s = 0.f;
#pragma unroll 5
        for (int i = 0; i < Lv; i++) s += attn[i] * h_s[i * Hv + d];
        pooled[d] = s;
    }
    __syncthreads();

    if (w < OUTv) {
        float s = 0.f;
        for (int d = ln; d < Hv; d += 32) s += pooled[d] * logits_w[w * Hv + d];
#pragma unroll
        for (int o = 16; o > 0; o >>= 1) s += __shfl_xor_sync(0xffffffffu, s, o);
        if (ln == 0) out[(size_t)b * OUTv + w] = s + logits_b[w];
    }
}

// ---------------------------------------------------------------------------
extern "C" void kernel_launch(void* const* d_in, const int* in_sizes, int n_in,
                              void* d_out, int out_size)
{
    const int*   seq      = (const int*)  d_in[0];
    const float* emb      = (const float*)d_in[1];
    const float* W_ih     = (const float*)d_in[2];
    const float* W_hh     = (const float*)d_in[3];
    const float* b_ih     = (const float*)d_in[4];
    const float* b_hh     = (const float*)d_in[5];
    const float* wCo_w    = (const float*)d_in[6];
    const float* wCo_b    = (const float*)d_in[7];
    const float* Wmy_w    = (const float*)d_in[8];
    const float* Wmy_b    = (const float*)d_in[9];
    const float* logits_w = (const float*)d_in[10];
    const float* logits_b = (const float*)d_in[11];
    float* out = (float*)d_out;

    __half *ehi, *elo, *wih_hi, *whh_hi, *Hhi, *Hlo, *VG;
    float *bpih, *bphh;
    cudaGetSymbolAddress((void**)&ehi,    d_emb_hi);
    cudaGetSymbolAddress((void**)&elo,    d_emb_lo);
    cudaGetSymbolAddress((void**)&wih_hi, d_Wih_hi);
    cudaGetSymbolAddress((void**)&whh_hi, d_Whh_hi);
    cudaGetSymbolAddress((void**)&bpih,   d_bp_ih);
    cudaGetSymbolAddress((void**)&bphh,   d_bp_hh);
    cudaGetSymbolAddress((void**)&VG,     d_VG);
    cudaGetSymbolAddress((void**)&Hhi,    d_Hhi);
    cudaGetSymbolAddress((void**)&Hlo,    d_Hlo);

    cudaFuncSetAttribute(vg_gemm, cudaFuncAttributeMaxDynamicSharedMemorySize, SMEM_VG);
    cudaFuncSetAttribute(gru_persist, cudaFuncAttributeMaxDynamicSharedMemorySize, SMEM_STEP);
    const int POST_SMEM = (Lv * Hv + 3 * Hv + 7 * 80 + 2 * Hv) * (int)sizeof(float);
    cudaFuncSetAttribute(post_kernel, cudaFuncAttributeMaxDynamicSharedMemorySize, POST_SMEM);

    // Persistent only if all 320 blocks provably co-resident.
    int occ = 0, sms = 0;
    cudaOccupancyMaxActiveBlocksPerMultiprocessor(&occ, gru_persist, 256, SMEM_STEP);
    cudaDeviceGetAttribute(&sms, cudaDevAttrMultiProcessorCount, 0);
    bool persistent = ((long)occ * sms >= NTILE * MTILE);

    // 0) conversions
    {
        long n = (long)VOCAB * Ev;
        conv_emb<<<(unsigned)((n + 255) / 256), 256>>>(emb, ehi, elo);
    }
    conv_w<<<G3, 128>>>(W_ih, b_ih, wih_hi, bpih);
    conv_w<<<G3, 128>>>(W_hh, b_hh, whh_hi, bphh);

    // 1) VG(fp16) = emb @ W_ih^T + b_ih + rz(b_hh) over full vocab
    {
        dim3 grid(10, VROWS / 128);
        vg_gemm<<<grid, 256, SMEM_VG>>>(ehi, elo, wih_hi, bpih, bphh, VG);
    }

    // 2) GRU recurrence
    dim3 grid(NTILE, MTILE);
    if (persistent) {
        gru_persist<<<grid, 256, SMEM_STEP>>>(Hhi, Hlo, whh_hi,
                                              seq, VG, bphh, 0, Lv, 1);
    } else {
        for (int l = 0; l < Lv; l++)
            gru_persist<<<grid, 256, SMEM_STEP>>>(Hhi, Hlo, whh_hi,
                                                  seq, VG, bphh, l, l + 1, 0);
    }

    // 3) collapsed co-attention + softmax + pooling + logits
    post_kernel<<<Bv, 256, POST_SMEM>>>(Hhi, Hlo, wCo_w, wCo_b, Wmy_w, Wmy_b,
                                        logits_w, logits_b, out);
}

// round 17
// speedup vs baseline: 2.5828x; 1.2398x over previous
#include <cuda_runtime.h>
#include <cuda_bf16.h>
#include <cuda_fp16.h>
#include <math.h>
#include <stdint.h>

#define Bv   2048
#define Lv   75
#define Ev   300
#define Hv   300
#define G3   900
#define G3P  912                 // VG row stride in halves (16B-aligned)
#define OUTv 5
#define KP   320                 // K padded to 10 x 32
#define VROWS 50048              // vocab rows padded to 391*128
#define NROWS 960                // gate rows padded to 10*96
#define VOCAB 50000
#define NTILE 10                 // n-blocks per step
#define MTILE 32                 // m-blocks per step

// ---------------- scratch (device globals; zero-initialized) ---------------
__device__ __half d_emb_hi[(size_t)VROWS * KP];
__device__ __half d_Wih_hi[NROWS * KP];
__device__ __half d_Whh_hi[NROWS * KP];
__device__ float d_bp_ih[G3];
__device__ float d_bp_hh[G3];
__device__ __half d_VG[(size_t)VROWS * G3P];             // vocab gates, fp16
__device__ __half d_Hhi[(size_t)(Lv + 1) * Bv * KP];     // slice 0 = zeros
__device__ __half d_Hlo[(size_t)(Lv + 1) * Bv * KP];     // state residual (epilogue only)
__device__ unsigned int d_flag[Lv][MTILE];               // producers of slice s+1
__device__ unsigned int d_done[MTILE];

// ---------------------------- helpers ---------------------------------------
__device__ __forceinline__ uint32_t smem_u32(const void* p) {
    uint32_t a;
    asm("{ .reg .u64 t; cvta.to.shared.u64 t, %1; cvt.u32.u64 %0, t; }" : "=r"(a) : "l"(p));
    return a;
}
__device__ __forceinline__ void ldsm_x4(uint32_t* r, uint32_t addr) {
    asm volatile("ldmatrix.sync.aligned.m8n8.x4.shared.b16 {%0,%1,%2,%3}, [%4];"
                 : "=r"(r[0]), "=r"(r[1]), "=r"(r[2]), "=r"(r[3]) : "r"(addr));
}
__device__ __forceinline__ void ldsm_x2(uint32_t* r, uint32_t addr) {
    asm volatile("ldmatrix.sync.aligned.m8n8.x2.shared.b16 {%0,%1}, [%2];"
                 : "=r"(r[0]), "=r"(r[1]) : "r"(addr));
}
__device__ __forceinline__ void mma_f16(float* c, const uint32_t* a, const uint32_t* b) {
    asm volatile(
        "mma.sync.aligned.m16n8k16.row.col.f32.f16.f16.f32 "
        "{%0,%1,%2,%3}, {%4,%5,%6,%7}, {%8,%9}, {%0,%1,%2,%3};"
        : "+f"(c[0]), "+f"(c[1]), "+f"(c[2]), "+f"(c[3])
        : "r"(a[0]), "r"(a[1]), "r"(a[2]), "r"(a[3]), "r"(b[0]), "r"(b[1]));
}
__device__ __forceinline__ void cp16(uint32_t dst, const void* src) {
    asm volatile("cp.async.cg.shared.global [%0], [%1], 16;" :: "r"(dst), "l"(src));
}
#define CP_COMMIT() asm volatile("cp.async.commit_group;" ::: "memory")
#define CP_WAIT0()  asm volatile("cp.async.wait_group 0;" ::: "memory")

__device__ __forceinline__ unsigned int ld_acq(const unsigned int* p) {
    unsigned int v;
    asm volatile("ld.global.acquire.gpu.u32 %0, [%1];" : "=r"(v) : "l"(p) : "memory");
    return v;
}
__device__ __forceinline__ void red_rel_add1(unsigned int* p) {
    asm volatile("red.release.gpu.global.add.u32 [%0], 1;" :: "l"(p) : "memory");
}
__device__ __forceinline__ float fsig(float x) {
    x = fminf(fmaxf(x, -30.f), 30.f);
    return __fdividef(1.f, 1.f + __expf(-x));
}
__device__ __forceinline__ float ftanh(float x) {
    x = fminf(fmaxf(x, -15.f), 15.f);
    float e = __expf(2.f * x);
    return __fdividef(e - 1.f, e + 1.f);
}

// ---------------------------- conversion kernels ---------------------------
__global__ void conv_emb(const float* __restrict__ emb, __half* __restrict__ hi)
{
    long i = (long)blockIdx.x * blockDim.x + threadIdx.x;
    if (i >= (long)VOCAB * Ev) return;
    int row = (int)(i / Ev), col = (int)(i - (long)row * Ev);
    hi[(size_t)row * KP + col] = __float2half(emb[i]);
}

// permute rows (g*H+j) -> (3j+g); W stored fp16.
__global__ void conv_w(const float* __restrict__ W, const float* __restrict__ b,
                       __half* __restrict__ hi, float* __restrict__ bp)
{
    int n = blockIdx.x;            // 0..899
    int j = n / 3, g = n % 3;
    const float* src = W + (size_t)(g * Hv + j) * 300;
    for (int k = threadIdx.x; k < 300; k += blockDim.x)
        hi[(size_t)n * KP + k] = __float2half(src[k]);
    if (threadIdx.x == 0) bp[n] = b[g * Hv + j];
}

// ---------------------------------------------------------------------------
// VG GEMM: VG(fp16) = emb_fp16 @ W_ih^T + biases. Single-term fp16 MMA.
// Block 128x96, warp tile 64x24, 2 stages, one sync per chunk.
// Stage (halves): A 5120 + B 3840 = 8960 (17920 B). Epilogue ghs = 51200 B.
// ---------------------------------------------------------------------------
#define V_A_HI(s) ((s) * 8960 + 0)
#define V_B_HI(s) ((s) * 8960 + 5120)
#define GH_STRIDE 100
#define SMEM_VG 51200

__global__ void __launch_bounds__(256)
vg_gemm(const __half* __restrict__ Ahi, const __half* __restrict__ Bhi,
        const float* __restrict__ bias1, const float* __restrict__ bias2,
        __half* __restrict__ VGout)
{
    extern __shared__ __align__(16) char smem[];
    float* ghs = (float*)smem;
    const uint32_t sbase = smem_u32(smem);

    int tid = threadIdx.x;
    int lane = tid & 31, wid = tid >> 5;
    int wm = wid >> 2, wn = wid & 3;
    int m0 = blockIdx.y * 128;
    int n0 = blockIdx.x * 96;

    int a_row = lane & 15, a_k = (lane >> 4) << 3;
    int b_row = lane & 7,  b_k = ((lane >> 3) & 1) << 3;

    auto load_chunk = [&](int cc, int s) {
        int kb = cc * 32;
        int r1 = tid >> 2, co = (tid & 3) * 8;
        int r2 = 64 + r1;
        cp16(sbase + (uint32_t)(V_A_HI(s) + r1 * 40 + co) * 2, Ahi + (size_t)(m0 + r1) * KP + kb + co);
        cp16(sbase + (uint32_t)(V_A_HI(s) + r2 * 40 + co) * 2, Ahi + (size_t)(m0 + r2) * KP + kb + co);
        cp16(sbase + (uint32_t)(V_B_HI(s) + r1 * 40 + co) * 2, Bhi + (size_t)(n0 + r1) * KP + kb + co);
        if (tid < 128) {
            int r3 = 64 + r1;
            cp16(sbase + (uint32_t)(V_B_HI(s) + r3 * 40 + co) * 2, Bhi + (size_t)(n0 + r3) * KP + kb + co);
        }
        CP_COMMIT();
    };

    float acc[4][3][4];
#pragma unroll
    for (int mi = 0; mi < 4; mi++)
#pragma unroll
        for (int ni = 0; ni < 3; ni++)
#pragma unroll
            for (int q = 0; q < 4; q++) acc[mi][ni][q] = 0.f;

    load_chunk(0, 0);

    for (int c = 0; c < 10; c++) {
        CP_WAIT0();
        __syncthreads();
        if (c < 9) load_chunk(c + 1, (c + 1) & 1);
        int s = c & 1;
        uint32_t ah = sbase + (uint32_t)V_A_HI(s) * 2;
        uint32_t bh = sbase + (uint32_t)V_B_HI(s) * 2;
#pragma unroll
        for (int kk = 0; kk < 2; kk++) {
            uint32_t fah[4][4], fbh[3][2];
#pragma unroll
            for (int mi = 0; mi < 4; mi++) {
                uint32_t ro = (uint32_t)((wm * 64 + mi * 16 + a_row) * 40 + kk * 16 + a_k) * 2;
                ldsm_x4(fah[mi], ah + ro);
            }
#pragma unroll
            for (int ni = 0; ni < 3; ni++) {
                uint32_t ro = (uint32_t)((wn * 24 + ni * 8 + b_row) * 40 + kk * 16 + b_k) * 2;
                ldsm_x2(fbh[ni], bh + ro);
            }
#pragma unroll
            for (int mi = 0; mi < 4; mi++)
#pragma unroll
                for (int ni = 0; ni < 3; ni++)
                    mma_f16(acc[mi][ni], fah[mi], fbh[ni]);
        }
    }
    __syncthreads();   // ghs overlaps stages — drain compute

#pragma unroll
    for (int mi = 0; mi < 4; mi++) {
        int mr = wm * 64 + mi * 16 + (lane >> 2);
#pragma unroll
        for (int ni = 0; ni < 3; ni++) {
            int nn = wn * 24 + ni * 8 + (lane & 3) * 2;
            ghs[mr * GH_STRIDE + nn]           = acc[mi][ni][0];
            ghs[mr * GH_STRIDE + nn + 1]       = acc[mi][ni][1];
            ghs[(mr + 8) * GH_STRIDE + nn]     = acc[mi][ni][2];
            ghs[(mr + 8) * GH_STRIDE + nn + 1] = acc[mi][ni][3];
        }
    }
    __syncthreads();

    for (int i = tid; i < 128 * 96; i += 256) {
        int m = i / 96, n = i - m * 96;
        int gn = n0 + n;
        if (gn < G3) {
            float b2 = (gn % 3 != 2) ? bias2[gn] : 0.f;   // fold b_hh for r,z only
            VGout[(size_t)(m0 + m) * G3P + gn] =
                __float2half(ghs[m * GH_STRIDE + n] + bias1[gn] + b2);
        }
    }
}

// ---------------------------------------------------------------------------
// GRU steps, persistent: 320 blocks, tile 64x96, single-term fp16 MMA.
// Stage (halves): A 2560 + B 3840 = 6400 (12800 B). cs (25600 B) = both stages.
// smem: stages [0,25600), gx fp16 [25600,37888), bhn [37888,38016).
// ---------------------------------------------------------------------------
#define S_A_HI(s) ((s) * 6400 + 0)
#define S_B_HI(s) ((s) * 6400 + 2560)
#define GXS_B 25600
#define BHN_B 37888
#define SMEM_STEP 38016

__global__ void __launch_bounds__(256, 3)
gru_persist(const __half* __restrict__ Hhi_all, const __half* __restrict__ Hlo_all,
            const __half* __restrict__ Bhi,
            const int* __restrict__ seq, const __half* __restrict__ VGin,
            const float* __restrict__ bph,
            int s_begin, int s_end, int use_flags)
{
    extern __shared__ __align__(16) char smem[];
    float* cs  = (float*)smem;                    // epilogue C (aliases stages)
    __half* gxs = (__half*)(smem + GXS_B);
    float* bhn = (float*)(smem + BHN_B);
    const uint32_t sbase = smem_u32(smem);

    int tid = threadIdx.x;
    int lane = tid & 31, wid = tid >> 5;
    int wm = wid >> 2, wn = wid & 3;
    int bn = blockIdx.x;                          // 0..9
    int bm = blockIdx.y;                          // 0..31
    int m0 = bm * 64;
    int n0 = bn * 96;
    int j0 = bn * 32;

    if (tid < 32 && (n0 + 3 * tid + 2) < G3) bhn[tid] = bph[n0 + 3 * tid + 2];

    int a_row = lane & 15, a_k = (lane >> 4) << 3;
    int b_row = lane & 7,  b_k = ((lane >> 3) & 1) << 3;
    const size_t slice = (size_t)Bv * KP;

    for (int s = s_begin; s < s_end; s++) {
        const __half* Hp_hi = Hhi_all + (size_t)s * slice;
        const __half* Hp_lo = Hlo_all + (size_t)s * slice;
        __half* Ho_hi = (__half*)(Hhi_all + (size_t)(s + 1) * slice);
        __half* Ho_lo = (__half*)(Hlo_all + (size_t)(s + 1) * slice);

        // ---- gx gather (fp16, 16B copies) ----
#pragma unroll
        for (int c = 0; c < 3; c++) {
            int idx = tid + c * 256;           // 0..767
            int row = idx / 12, off = (idx % 12) * 8;
            int t = seq[(m0 + row) * Lv + s];
            cp16(sbase + GXS_B + (uint32_t)(row * 96 + off) * 2,
                 VGin + (size_t)t * G3P + n0 + off);
        }
        CP_COMMIT();

        // ---- wait for the 10 producers of slice s ----
        if (use_flags && s > 0) {
            if (tid == 0) {
                while (ld_acq(&d_flag[s - 1][bm]) < (unsigned)NTILE) __nanosleep(64);
            }
        }
        __syncthreads();

        auto load_chunk = [&](int cc, int st) {
            int kb = cc * 32;
            int r1 = tid >> 2, co = (tid & 3) * 8;
            cp16(sbase + (uint32_t)(S_A_HI(st) + r1 * 40 + co) * 2, Hp_hi + (size_t)(m0 + r1) * KP + kb + co);
            cp16(sbase + (uint32_t)(S_B_HI(st) + r1 * 40 + co) * 2, Bhi + (size_t)(n0 + r1) * KP + kb + co);
            if (tid < 128) {
                int r2 = 64 + r1;
                cp16(sbase + (uint32_t)(S_B_HI(st) + r2 * 40 + co) * 2, Bhi + (size_t)(n0 + r2) * KP + kb + co);
            }
            CP_COMMIT();
        };

        float acc[2][3][4];
#pragma unroll
        for (int mi = 0; mi < 2; mi++)
#pragma unroll
            for (int ni = 0; ni < 3; ni++)
#pragma unroll
                for (int q = 0; q < 4; q++) acc[mi][ni][q] = 0.f;

        load_chunk(0, 0);

        for (int c = 0; c < 10; c++) {
            CP_WAIT0();
            __syncthreads();
            if (c < 9) load_chunk(c + 1, (c + 1) & 1);
            int st = c & 1;
            uint32_t ah = sbase + (uint32_t)S_A_HI(st) * 2;
            uint32_t bh = sbase + (uint32_t)S_B_HI(st) * 2;
#pragma unroll
            for (int kk = 0; kk < 2; kk++) {
                uint32_t fah[2][4], fbh[3][2];
#pragma unroll
                for (int mi = 0; mi < 2; mi++) {
                    uint32_t ro = (uint32_t)((wm * 32 + mi * 16 + a_row) * 40 + kk * 16 + a_k) * 2;
                    ldsm_x4(fah[mi], ah + ro);
                }
#pragma unroll
                for (int ni = 0; ni < 3; ni++) {
                    uint32_t ro = (uint32_t)((wn * 24 + ni * 8 + b_row) * 40 + kk * 16 + b_k) * 2;
                    ldsm_x2(fbh[ni], bh + ro);
                }
#pragma unroll
                for (int mi = 0; mi < 2; mi++)
#pragma unroll
                    for (int ni = 0; ni < 3; ni++)
                        mma_f16(acc[mi][ni], fah[mi], fbh[ni]);
            }
        }
        __syncthreads();   // cs aliases both stages — drain chunk 9 reads

        // ---- dump C to smem ----
#pragma unroll
        for (int mi = 0; mi < 2; mi++) {
            int mr = wm * 32 + mi * 16 + (lane >> 2);
#pragma unroll
            for (int ni = 0; ni < 3; ni++) {
                int nn = wn * 24 + ni * 8 + (lane & 3) * 2;
                cs[mr * GH_STRIDE + nn]           = acc[mi][ni][0];
                cs[mr * GH_STRIDE + nn + 1]       = acc[mi][ni][1];
                cs[(mr + 8) * GH_STRIDE + nn]     = acc[mi][ni][2];
                cs[(mr + 8) * GH_STRIDE + nn + 1] = acc[mi][ni][3];
            }
        }
        __syncthreads();

        // ---- gate epilogue (full-precision state blend via hi+lo) ----
        for (int i = tid; i < 64 * 32; i += 256) {
            int ml = i >> 5, p = i & 31;
            int j = j0 + p;
            if (j < Hv) {
                int m = m0 + ml;
                float gh_r = cs[ml * GH_STRIDE + 3 * p + 0];
                float gh_z = cs[ml * GH_STRIDE + 3 * p + 1];
                float gh_n = cs[ml * GH_STRIDE + 3 * p + 2] + bhn[p];  // b_hh_n inside r*(.)
                float gx_r = __half2float(gxs[ml * 96 + 3 * p + 0]);
                float gx_z = __half2float(gxs[ml * 96 + 3 * p + 1]);
                float gx_n = __half2float(gxs[ml * 96 + 3 * p + 2]);
                float r = fsig(gx_r + gh_r);
                float z = fsig(gx_z + gh_z);
                float ng = ftanh(gx_n + r * gh_n);
                size_t hidx = (size_t)m * KP + j;
                float hp = __half2float(Hp_hi[hidx]) + __half2float(Hp_lo[hidx]);
                float h = (1.f - z) * ng + z * hp;
                __half hh = __float2half(h);
                Ho_hi[hidx] = hh;
                Ho_lo[hidx] = __float2half(h - __half2float(hh));
            }
        }

        if (use_flags) {
            __threadfence();
            __syncthreads();
            if (tid == 0) red_rel_add1(&d_flag[s][bm]);
        } else {
            __syncthreads();
        }
    }

    // ---- reset phase (persistent mode only) ----
    if (use_flags) {
        if (tid == 0) red_rel_add1(&d_done[bm]);
        if (bn == 0) {
            if (tid == 0) {
                while (ld_acq(&d_done[bm]) < (unsigned)NTILE) __nanosleep(64);
            }
            __syncthreads();
            for (int s = tid; s < Lv; s += 256) d_flag[s][bm] = 0;
            if (tid == 0) d_done[bm] = 0;
            __threadfence();
        }
    }
}

// ---------------------------------------------------------------------------
// Post: collapsed co-attention + softmax + pooling + logits. Vectorized h load.
// ---------------------------------------------------------------------------
__device__ __forceinline__ float blockReduceSum(float v, volatile float* red)
{
    __syncthreads();
#pragma unroll
    for (int o = 16; o > 0; o >>= 1) v += __shfl_xor_sync(0xffffffffu, v, o);
    int w = threadIdx.x >> 5, ln = threadIdx.x & 31;
    if (ln == 0) red[w] = v;
    __syncthreads();
    if (threadIdx.x < 32) {
        float x = (threadIdx.x < 8) ? red[threadIdx.x] : 0.f;
#pragma unroll
        for (int o = 4; o > 0; o >>= 1) x += __shfl_xor_sync(0xffffffffu, x, o);
        if (threadIdx.x == 0) red[0] = x;
    }
    __syncthreads();
    return red[0];
}
__device__ __forceinline__ float blockReduceMax(float v, volatile float* red)
{
    __syncthreads();
#pragma unroll
    for (int o = 16; o > 0; o >>= 1) v = fmaxf(v, __shfl_xor_sync(0xffffffffu, v, o));
    int w = threadIdx.x >> 5, ln = threadIdx.x & 31;
    if (ln == 0) red[w] = v;
    __syncthreads();
    if (threadIdx.x < 32) {
        float x = (threadIdx.x < 8) ? red[threadIdx.x] : -3.4e38f;
#pragma unroll
        for (int o = 4; o > 0; o >>= 1) x = fmaxf(x, __shfl_xor_sync(0xffffffffu, x, o));
        if (threadIdx.x == 0) red[0] = x;
    }
    __syncthreads();
    return red[0];
}

__global__ void post_kernel(const __half* __restrict__ Hhi,
                            const __half* __restrict__ Hlo,
                            const float* __restrict__ wCo_w, const float* __restrict__ wCo_b,
                            const float* __restrict__ Wmy_w, const float* __restrict__ Wmy_b,
                            const float* __restrict__ logits_w, const float* __restrict__ logits_b,
                            float* __restrict__ out)
{
    extern __shared__ float fs[];
    float* h_s    = fs;
    float* wa     = h_s + Lv * Hv;
    float* wb_    = wa + Hv;
    float* wc     = wb_ + Hv;
    float* wmy    = wc + Hv;
    float* aa     = wmy + 80;
    float* bb     = aa + 80;
    float* qq     = bb + 80;
    float* pp     = qq + 80;
    float* smarr  = pp + 80;
    float* attn   = smarr + 80;
    float* u      = attn + 80;
    float* pooled = u + Hv;
    __shared__ float red[32];

    int b = blockIdx.x;
    int tid = threadIdx.x;
    int w = tid >> 5, ln = tid & 31;

    for (int t = tid; t < Lv * (Hv / 4); t += 256) {
        int i = t / (Hv / 4), d4 = (t - i * (Hv / 4)) * 4;
        size_t idx = (size_t)(i + 1) * Bv * KP + (size_t)b * KP + d4;
        uint2 vh = *(const uint2*)(Hhi + idx);
        uint2 vl = *(const uint2*)(Hlo + idx);
        const __half2* ph = (const __half2*)&vh;
        const __half2* pl = (const __half2*)&vl;
        float2 h0 = __half22float2(ph[0]);
        float2 l0 = __half22float2(pl[0]);
        float2 h1 = __half22float2(ph[1]);
        float2 l1 = __half22float2(pl[1]);
        float* dst = h_s + i * Hv + d4;
        dst[0] = h0.x + l0.x;
        dst[1] = h0.y + l0.y;
        dst[2] = h1.x + l1.x;
        dst[3] = h1.y + l1.y;
    }
    for (int t = tid; t < Hv; t += 256) {
        wa[t]  = wCo_w[t];
        wb_[t] = wCo_w[Hv + t];
        wc[t]  = wCo_w[2 * Hv + t];
    }
    if (tid < Lv) wmy[tid] = Wmy_w[tid];
    __syncthreads();

    for (int i = w; i < Lv; i += 8) {
        float sa = 0.f, sb2 = 0.f, sq = 0.f;
        for (int d = ln; d < Hv; d += 32) {
            float hv = h_s[i * Hv + d];
            sa += hv * wa[d];
            sb2 += hv * wb_[d];
            sq += hv * hv * wc[d];
        }
#pragma unroll
        for (int o = 16; o > 0; o >>= 1) {
            sa += __shfl_xor_sync(0xffffffffu, sa, o);
            sb2 += __shfl_xor_sync(0xffffffffu, sb2, o);
            sq += __shfl_xor_sync(0xffffffffu, sq, o);
        }
        if (ln == 0) { aa[i] = sa; bb[i] = sb2; qq[i] = sq; }
    }
    __syncthreads();

    for (int d = tid; d < Hv; d += 256) {
        float s = 0.f;
#pragma unroll 5
        for (int i = 0; i < Lv; i++) s += wmy[i] * h_s[i * Hv + d];
        u[d] = s;
    }

    float swv = (tid < Lv) ? wmy[tid] : 0.f;
    float Sw = blockReduceSum(swv, red);
    float tv = (tid < Lv) ? wmy[tid] * bb[tid] : 0.f;
    float T = blockReduceSum(tv, red);
    __syncthreads();

    for (int i = w; i < Lv; i += 8) {
        float sp = 0.f;
        for (int d = ln; d < Hv; d += 32) sp += h_s[i * Hv + d] * wc[d] * u[d];
#pragma unroll
        for (int o = 16; o > 0; o >>= 1) sp += __shfl_xor_sync(0xffffffffu, sp, o);
        if (ln == 0) pp[i] = sp;
    }
    __syncthreads();

    float beta = wCo_b[0];
    if (tid < Lv) {
        smarr[tid] = (aa[tid] + beta) * Sw + T + pp[tid]
                   - wmy[tid] * (aa[tid] + bb[tid] + beta + qq[tid]) + Wmy_b[0];
    }
    __syncthreads();

    float mv = (tid < Lv) ? smarr[tid] : -3.4e38f;
    float mx = blockReduceMax(mv, red);
    float ev = (tid < Lv) ? expf(smarr[tid] - mx) : 0.f;
    if (tid < Lv) attn[tid] = ev;
    float se = blockReduceSum(ev, red);
    if (tid < Lv) attn[tid] = attn[tid] / se;
    __syncthreads();

    for (int d = tid; d < Hv; d += 256) {
        float s = 0.f;
#pragma unroll 5
        for (int i = 0; i < Lv; i++) s += attn[i] * h_s[i * Hv + d];
        pooled[d] = s;
    }
    __syncthreads();

    if (w < OUTv) {
        float s = 0.f;
        for (int d = ln; d < Hv; d += 32) s += pooled[d] * logits_w[w * Hv + d];
#pragma unroll
        for (int o = 16; o > 0; o >>= 1) s += __shfl_xor_sync(0xffffffffu, s, o);
        if (ln == 0) out[(size_t)b * OUTv + w] = s + logits_b[w];
    }
}

// ---------------------------------------------------------------------------
extern "C" void kernel_launch(void* const* d_in, const int* in_sizes, int n_in,
                              void* d_out, int out_size)
{
    const int*   seq      = (const int*)  d_in[0];
    const float* emb      = (const float*)d_in[1];
    const float* W_ih     = (const float*)d_in[2];
    const float* W_hh     = (const float*)d_in[3];
    const float* b_ih     = (const float*)d_in[4];
    const float* b_hh     = (const float*)d_in[5];
    const float* wCo_w    = (const float*)d_in[6];
    const float* wCo_b    = (const float*)d_in[7];
    const float* Wmy_w    = (const float*)d_in[8];
    const float* Wmy_b    = (const float*)d_in[9];
    const float* logits_w = (const float*)d_in[10];
    const float* logits_b = (const float*)d_in[11];
    float* out = (float*)d_out;

    __half *ehi, *wih_hi, *whh_hi, *Hhi, *Hlo, *VG;
    float *bpih, *bphh;
    cudaGetSymbolAddress((void**)&ehi,    d_emb_hi);
    cudaGetSymbolAddress((void**)&wih_hi, d_Wih_hi);
    cudaGetSymbolAddress((void**)&whh_hi, d_Whh_hi);
    cudaGetSymbolAddress((void**)&bpih,   d_bp_ih);
    cudaGetSymbolAddress((void**)&bphh,   d_bp_hh);
    cudaGetSymbolAddress((void**)&VG,     d_VG);
    cudaGetSymbolAddress((void**)&Hhi,    d_Hhi);
    cudaGetSymbolAddress((void**)&Hlo,    d_Hlo);

    cudaFuncSetAttribute(vg_gemm, cudaFuncAttributeMaxDynamicSharedMemorySize, SMEM_VG);
    cudaFuncSetAttribute(gru_persist, cudaFuncAttributeMaxDynamicSharedMemorySize, SMEM_STEP);
    const int POST_SMEM = (Lv * Hv + 3 * Hv + 7 * 80 + 2 * Hv) * (int)sizeof(float);
    cudaFuncSetAttribute(post_kernel, cudaFuncAttributeMaxDynamicSharedMemorySize, POST_SMEM);

    // Persistent only if all 320 blocks provably co-resident.
    int occ = 0, sms = 0;
    cudaOccupancyMaxActiveBlocksPerMultiprocessor(&occ, gru_persist, 256, SMEM_STEP);
    cudaDeviceGetAttribute(&sms, cudaDevAttrMultiProcessorCount, 0);
    bool persistent = ((long)occ * sms >= NTILE * MTILE);

    // 0) conversions
    {
        long n = (long)VOCAB * Ev;
        conv_emb<<<(unsigned)((n + 255) / 256), 256>>>(emb, ehi);
    }
    conv_w<<<G3, 128>>>(W_ih, b_ih, wih_hi, bpih);
    conv_w<<<G3, 128>>>(W_hh, b_hh, whh_hi, bphh);

    // 1) VG(fp16) = emb @ W_ih^T + b_ih + rz(b_hh) over full vocab
    {
        dim3 grid(10, VROWS / 128);
        vg_gemm<<<grid, 256, SMEM_VG>>>(ehi, wih_hi, bpih, bphh, VG);
    }

    // 2) GRU recurrence
    dim3 grid(NTILE, MTILE);
    if (persistent) {
        gru_persist<<<grid, 256, SMEM_STEP>>>(Hhi, Hlo, whh_hi,
                                              seq, VG, bphh, 0, Lv, 1);
    } else {
        for (int l = 0; l < Lv; l++)
            gru_persist<<<grid, 256, SMEM_STEP>>>(Hhi, Hlo, whh_hi,
                                                  seq, VG, bphh, l, l + 1, 0);
    }

    // 3) collapsed co-attention + softmax + pooling + logits
    post_kernel<<<Bv, 256, POST_SMEM>>>(Hhi, Hlo, wCo_w, wCo_b, Wmy_w, Wmy_b,
                                        logits_w, logits_b, out);
}